// round 12
// baseline (speedup 1.0000x reference)
#include <cuda_runtime.h>
#include <cuda_bf16.h>
#include <cstdint>
#include <math.h>

#define BB   32
#define SEQ  257
#define SEQP 320
#define DIM  1024
#define NH   16
#define HD   64
#define NEXP 8
#define RNK  16
#define GHID 256
#define BSQ  (BB*SEQ)          /* 8224 tokens */
#define QSCALE 0.125f

/* ---------------- scratch (device globals; no allocations) ---------------- */
static __device__ float g_pooled[BB*DIM];
static __device__ float g_gates[BB*2];
static __device__ int   g_idx  [BB*2];
static __device__ __align__(16) __nv_bfloat16 g_xh[(size_t)BSQ*DIM];
static __device__ __align__(16) __nv_bfloat16 g_xl[(size_t)BSQ*DIM];
static __device__ __align__(16) __nv_bfloat16 g_wh[(size_t)4*DIM*DIM];
static __device__ __align__(16) __nv_bfloat16 g_wl[(size_t)4*DIM*DIM];
static __device__ __align__(16) __nv_bfloat16 g_vbh[(size_t)4*BB*32*DIM];
static __device__ __align__(16) __nv_bfloat16 g_vbl[(size_t)4*BB*32*DIM];
static __device__ __align__(16) __nv_bfloat16 g_ubh[(size_t)4*BB*DIM*32];
static __device__ __align__(16) __nv_bfloat16 g_ubl[(size_t)4*BB*DIM*32];
static __device__ __align__(16) __nv_bfloat16 g_xvh[(size_t)4*BB*SEQP*32];
static __device__ __align__(16) __nv_bfloat16 g_xvl[(size_t)4*BB*SEQP*32];
static __device__ __align__(16) __nv_bfloat16 g_aqh[(size_t)BB*NH*SEQP*HD];
static __device__ __align__(16) __nv_bfloat16 g_aql[(size_t)BB*NH*SEQP*HD];
static __device__ __align__(16) __nv_bfloat16 g_akh[(size_t)BB*NH*SEQP*HD];
static __device__ __align__(16) __nv_bfloat16 g_akl[(size_t)BB*NH*SEQP*HD];
static __device__ __align__(16) __nv_bfloat16 g_avh[(size_t)BB*NH*SEQP*HD];
static __device__ __align__(16) __nv_bfloat16 g_avl[(size_t)BB*NH*SEQP*HD];

/* ---------------- small PTX helpers ---------------- */
__device__ __forceinline__ uint32_t smem_u32(const void* p) {
    uint32_t a;
    asm("{ .reg .u64 t; cvta.to.shared.u64 t, %1; cvt.u32.u64 %0, t; }" : "=r"(a) : "l"(p));
    return a;
}
__device__ __forceinline__ void cp16(uint32_t dst, const void* src, int srcBytes) {
    asm volatile("cp.async.cg.shared.global [%0], [%1], 16, %2;"
                 :: "r"(dst), "l"(src), "r"(srcBytes) : "memory");
}
#define CP_COMMIT() asm volatile("cp.async.commit_group;" ::: "memory")
#define CP_WAIT0()  asm volatile("cp.async.wait_group 0;" ::: "memory")
#define CP_WAIT1()  asm volatile("cp.async.wait_group 1;" ::: "memory")
#define CP_WAIT2()  asm volatile("cp.async.wait_group 2;" ::: "memory")

__device__ __forceinline__ void ldsm_x4(uint32_t& r0, uint32_t& r1, uint32_t& r2, uint32_t& r3,
                                        uint32_t addr) {
    asm volatile("ldmatrix.sync.aligned.m8n8.x4.shared.b16 {%0,%1,%2,%3}, [%4];"
                 : "=r"(r0), "=r"(r1), "=r"(r2), "=r"(r3) : "r"(addr));
}
__device__ __forceinline__ void ldsm_x4_t(uint32_t& r0, uint32_t& r1, uint32_t& r2, uint32_t& r3,
                                          uint32_t addr) {
    asm volatile("ldmatrix.sync.aligned.m8n8.x4.trans.shared.b16 {%0,%1,%2,%3}, [%4];"
                 : "=r"(r0), "=r"(r1), "=r"(r2), "=r"(r3) : "r"(addr));
}
__device__ __forceinline__ void mma_bf16(float* c, const uint32_t* a, uint32_t b0, uint32_t b1) {
    asm volatile("mma.sync.aligned.m16n8k16.row.col.f32.bf16.bf16.f32 "
                 "{%0,%1,%2,%3}, {%4,%5,%6,%7}, {%8,%9}, {%0,%1,%2,%3};"
                 : "+f"(c[0]), "+f"(c[1]), "+f"(c[2]), "+f"(c[3])
                 : "r"(a[0]), "r"(a[1]), "r"(a[2]), "r"(a[3]), "r"(b0), "r"(b1));
}
__device__ __forceinline__ uint32_t pack_bf2(float lo, float hi) {
    __nv_bfloat16 l = __float2bfloat16(lo), h = __float2bfloat16(hi);
    return ((uint32_t)__bfloat16_as_ushort(h) << 16) | (uint32_t)__bfloat16_as_ushort(l);
}

/* ---------------- pooling (parallel) + gating MLP ---------------- */
__global__ void pool_kernel(const float* __restrict__ x)
{
    int b = blockIdx.x;
    int d = blockIdx.y*128 + threadIdx.x;
    const float* xp = x + (size_t)b*SEQ*DIM + d;
    float s = 0.f;
    #pragma unroll 4
    for (int t = 0; t < SEQ; t++) s += xp[(size_t)t*DIM];
    g_pooled[b*DIM + d] = s * (1.0f/SEQ);
}

__global__ void gating_mlp_kernel(const float* __restrict__ gw1, const float* __restrict__ gb1,
                                  const float* __restrict__ gw2, const float* __restrict__ gb2)
{
    int b = blockIdx.x;
    __shared__ float h[GHID];
    __shared__ float logits[NEXP];
    int tid = threadIdx.x;
    const float* pooled = g_pooled + b*DIM;
    {
        float a = gb1[tid];
        const float* w = gw1 + (size_t)tid*DIM;
        #pragma unroll 4
        for (int d = 0; d < DIM; d++) a += pooled[d]*w[d];
        h[tid] = fmaxf(a, 0.f);
    }
    __syncthreads();
    if (tid < NEXP) {
        float a = gb2[tid];
        const float* w = gw2 + tid*GHID;
        for (int d = 0; d < GHID; d++) a += h[d]*w[d];
        logits[tid] = a;
    }
    __syncthreads();
    if (tid == 0) {
        int i0 = 0;
        for (int e = 1; e < NEXP; e++) if (logits[e] > logits[i0]) i0 = e;
        int i1 = -1;
        for (int e = 0; e < NEXP; e++) {
            if (e == i0) continue;
            if (i1 < 0 || logits[e] > logits[i1]) i1 = e;
        }
        float v0 = logits[i0], v1 = logits[i1];
        float e0 = expf(v0 - v0), e1 = expf(v1 - v0);
        float inv = 1.f/(e0 + e1);
        g_gates[b*2]   = e0*inv;
        g_gates[b*2+1] = e1*inv;
        g_idx[b*2]   = i0;
        g_idx[b*2+1] = i1;
    }
}

/* ---------------- fp32 -> (bf16 hi, bf16 lo) ---------------- */
__device__ __forceinline__ void split4(float4 v, ushort4& hh, ushort4& ll)
{
    __nv_bfloat16 t;
    t = __float2bfloat16(v.x); hh.x = __bfloat16_as_ushort(t);
    ll.x = __bfloat16_as_ushort(__float2bfloat16(v.x - __bfloat162float(t)));
    t = __float2bfloat16(v.y); hh.y = __bfloat16_as_ushort(t);
    ll.y = __bfloat16_as_ushort(__float2bfloat16(v.y - __bfloat162float(t)));
    t = __float2bfloat16(v.z); hh.z = __bfloat16_as_ushort(t);
    ll.z = __bfloat16_as_ushort(__float2bfloat16(v.z - __bfloat162float(t)));
    t = __float2bfloat16(v.w); hh.w = __bfloat16_as_ushort(t);
    ll.w = __bfloat16_as_ushort(__float2bfloat16(v.w - __bfloat162float(t)));
}

__global__ void convx_kernel(const float* __restrict__ s, int n4)
{
    int i = blockIdx.x*256 + threadIdx.x;
    if (i >= n4) return;
    ushort4 hh, ll;
    split4(((const float4*)s)[i], hh, ll);
    ((ushort4*)g_xh)[i] = hh;
    ((ushort4*)g_xl)[i] = ll;
}

__global__ void convw_kernel(const float* __restrict__ w0, const float* __restrict__ w1,
                             const float* __restrict__ w2, const float* __restrict__ w3)
{
    int p = blockIdx.y;
    const float* s = (p==0)?w0:(p==1)?w1:(p==2)?w2:w3;
    int i = blockIdx.x*256 + threadIdx.x;
    ushort4 hh, ll;
    split4(((const float4*)s)[i], hh, ll);
    size_t o = (size_t)p*(DIM*DIM/4) + i;
    ((ushort4*)g_wh)[o] = hh;
    ((ushort4*)g_wl)[o] = ll;
}

/* ---------------- vconv / uconv ---------------- */
__global__ void vconv_kernel(const float* __restrict__ V0, const float* __restrict__ V1,
                             const float* __restrict__ V2, const float* __restrict__ V3,
                             const float* __restrict__ S0, const float* __restrict__ S1,
                             const float* __restrict__ S2, const float* __restrict__ S3)
{
    int b = blockIdx.x, j = blockIdx.y, p = blockIdx.z;
    const float* Vm = (p==0)?V0:(p==1)?V1:(p==2)?V2:V3;
    const float* Sm = (p==0)?S0:(p==1)?S1:(p==2)?S2:S3;
    int half = j >> 4, r = j & 15;
    int e = g_idx[b*2 + half];
    float sc = g_gates[b*2 + half] * Sm[e*RNK + r];
    float4 v = ((const float4*)(Vm + ((size_t)e*RNK + r)*DIM))[threadIdx.x];
    v.x *= sc; v.y *= sc; v.z *= sc; v.w *= sc;
    ushort4 hh, ll;
    split4(v, hh, ll);
    size_t o = ((size_t)p*BB*32 + (size_t)b*32 + j)*DIM/4 + threadIdx.x;
    ((ushort4*)g_vbh)[o] = hh;
    ((ushort4*)g_vbl)[o] = ll;
}

__global__ void uconv_kernel(const float* __restrict__ U0, const float* __restrict__ U1,
                             const float* __restrict__ U2, const float* __restrict__ U3)
{
    int b = blockIdx.x, p = blockIdx.z;
    const float* U = (p==0)?U0:(p==1)?U1:(p==2)?U2:U3;
    int n = blockIdx.y*256 + threadIdx.x;
    int i0 = g_idx[b*2], i1 = g_idx[b*2+1];
    const float* u0 = U + ((size_t)i0*DIM + n)*RNK;
    const float* u1 = U + ((size_t)i1*DIM + n)*RNK;
    __nv_bfloat16* H = g_ubh + ((size_t)p*BB*DIM + (size_t)b*DIM + n)*32;
    __nv_bfloat16* L = g_ubl + ((size_t)p*BB*DIM + (size_t)b*DIM + n)*32;
    #pragma unroll
    for (int r = 0; r < 16; r++) {
        float v0 = u0[r], v1 = u1[r];
        __nv_bfloat16 h0 = __float2bfloat16(v0);
        H[r]      = h0;
        L[r]      = __float2bfloat16(v0 - __bfloat162float(h0));
        __nv_bfloat16 h1 = __float2bfloat16(v1);
        H[16 + r] = h1;
        L[16 + r] = __float2bfloat16(v1 - __bfloat162float(h1));
    }
}

/* ---------------- fused GEMM, 4-stage pipeline, BK=16 -------------------- */
#define MM_MATB (128*24*2)              /* 6144 */
#define MM_STGB (4*MM_MATB)             /* 24576 */
#define MM_SMEM (4*MM_STGB)             /* 98304 -> 2 CTAs/SM */

__device__ __forceinline__ void mm_load16(uint32_t sb, int buf, int k0,
    const __nv_bfloat16* Ah, const __nv_bfloat16* Al,
    const __nv_bfloat16* Bh, const __nv_bfloat16* Bl,
    int m0, int n0, int tid)
{
    uint32_t base = sb + buf*MM_STGB;
    const __nv_bfloat16* srcs[4] = {Ah, Al, Bh, Bl};
    #pragma unroll
    for (int i = 0; i < 4; i++) {
        int c = tid + 256*i;            /* 0..1023 */
        int mat = c >> 8;
        int cc  = c & 255;
        int row = cc >> 1;
        int col = (cc & 1) * 8;
        const __nv_bfloat16* p = srcs[mat];
        int grow = ((mat < 2) ? m0 : n0) + row;
        int ok = (mat >= 2) || (grow < BSQ);
        const void* src = p + ((size_t)(ok ? grow : 0))*DIM + k0 + col;
        cp16(base + mat*MM_MATB + (uint32_t)(row*24 + col)*2, src, ok ? 16 : 0);
    }
}

__global__ void __launch_bounds__(256, 2) mm_kernel(int base_code,
    const float* __restrict__ bias0, const float* __restrict__ bias1,
    const float* __restrict__ bias2, float* __restrict__ Yext)
{
    extern __shared__ __align__(128) char smem[];
    int code = (base_code < 0) ? (int)blockIdx.z : base_code;
    const __nv_bfloat16* Ah = g_xh;
    const __nv_bfloat16* Al = g_xl;
    const __nv_bfloat16* Bh = g_wh + (size_t)code*DIM*DIM;
    const __nv_bfloat16* Bl = g_wl + (size_t)code*DIM*DIM;
    const float* bias = (code==0)?bias0:(code==1)?bias1:(code==2)?bias2:bias0;

    uint32_t sb = smem_u32(smem);
    int tid = threadIdx.x;
    int lane = tid & 31;
    int wid = tid >> 5;
    int warp_m = wid >> 2;
    int warp_n = wid & 3;
    int n0 = blockIdx.x*128, m0 = blockIdx.y*128;

    float acc[4][4][4];
    #pragma unroll
    for (int i = 0; i < 4; i++)
        #pragma unroll
        for (int j = 0; j < 4; j++)
            #pragma unroll
            for (int q = 0; q < 4; q++) acc[i][j][q] = 0.f;

    uint32_t aRow = (uint32_t)(warp_m*64 + (lane & 15));
    uint32_t aCol = (uint32_t)((lane >> 4) * 8);
    uint32_t bRowBase = (uint32_t)(warp_n*32 + (lane & 7) + ((lane >> 4) << 3));
    uint32_t bCol = (uint32_t)(((lane >> 3) & 1) * 8);

    mm_load16(sb, 0, 0,  Ah, Al, Bh, Bl, m0, n0, tid); CP_COMMIT();
    mm_load16(sb, 1, 16, Ah, Al, Bh, Bl, m0, n0, tid); CP_COMMIT();
    mm_load16(sb, 2, 32, Ah, Al, Bh, Bl, m0, n0, tid); CP_COMMIT();

    const int NK = DIM/16;              /* 64 stages */
    for (int s = 0; s < NK; s++) {
        if (s < NK-2)      CP_WAIT2();
        else if (s == NK-2) CP_WAIT1();
        else               CP_WAIT0();
        __syncthreads();

        uint32_t stg = sb + (uint32_t)(s & 3)*MM_STGB;
        uint32_t ah[4][4], al[4][4], bh[8], bl[8];
        #pragma unroll
        for (int i = 0; i < 4; i++) {
            uint32_t off = ((aRow + i*16)*24 + aCol)*2;
            ldsm_x4(ah[i][0], ah[i][1], ah[i][2], ah[i][3], stg + 0*MM_MATB + off);
            ldsm_x4(al[i][0], al[i][1], al[i][2], al[i][3], stg + 1*MM_MATB + off);
        }
        #pragma unroll
        for (int g = 0; g < 2; g++) {
            uint32_t off = ((bRowBase + g*16)*24 + bCol)*2;
            ldsm_x4(bh[g*4+0], bh[g*4+1], bh[g*4+2], bh[g*4+3], stg + 2*MM_MATB + off);
            ldsm_x4(bl[g*4+0], bl[g*4+1], bl[g*4+2], bl[g*4+3], stg + 3*MM_MATB + off);
        }
        #pragma unroll
        for (int i = 0; i < 4; i++) {
            #pragma unroll
            for (int j = 0; j < 4; j++) {
                mma_bf16(acc[i][j], ah[i], bh[j*2], bh[j*2+1]);
                mma_bf16(acc[i][j], ah[i], bl[j*2], bl[j*2+1]);
                mma_bf16(acc[i][j], al[i], bh[j*2], bh[j*2+1]);
            }
        }

        if (s + 3 < NK) {
            mm_load16(sb, (s+3)&3, (s+3)*16, Ah, Al, Bh, Bl, m0, n0, tid);
            CP_COMMIT();
        }
    }
    __syncthreads();

    /* ---- fused rank-32 MoE correction (BK=16 passes) ---- */
    {
        int mlast = m0 + 127; if (mlast >= BSQ) mlast = BSQ - 1;
        int bb0 = m0 / SEQ, bb1 = mlast / SEQ;
        int pass = 0;
        for (int bb = bb0; bb <= bb1; bb++) {
            for (int ks = 0; ks < 2; ks++, pass++) {
                uint32_t base = sb + (uint32_t)(pass & 3)*MM_STGB;
                #pragma unroll
                for (int i2 = 0; i2 < 4; i2++) {
                    int c = tid + 256*i2;
                    int mat = c >> 8, cc = c & 255;
                    int row = cc >> 1, col = (cc & 1)*8;
                    if (mat < 2) {
                        int m = m0 + row;
                        int ok = (m < BSQ) && (m / SEQ == bb);
                        int t = m - bb*SEQ;
                        const __nv_bfloat16* srcA = (mat ? g_xvl : g_xvh) +
                            (size_t)code*BB*SEQP*32 + ((size_t)bb*SEQP + (ok ? t : 0))*32 + ks*16 + col;
                        cp16(base + mat*MM_MATB + (uint32_t)(row*24 + col)*2, srcA, ok ? 16 : 0);
                    } else {
                        const __nv_bfloat16* srcB = ((mat == 3) ? g_ubl : g_ubh) +
                            (size_t)code*BB*DIM*32 + ((size_t)bb*DIM + n0 + row)*32 + ks*16 + col;
                        cp16(base + mat*MM_MATB + (uint32_t)(row*24 + col)*2, srcB, 16);
                    }
                }
                CP_COMMIT();
                CP_WAIT0();
                __syncthreads();

                uint32_t ah[4][4], al[4][4], bh[8], bl[8];
                #pragma unroll
                for (int i = 0; i < 4; i++) {
                    uint32_t off = ((aRow + i*16)*24 + aCol)*2;
                    ldsm_x4(ah[i][0], ah[i][1], ah[i][2], ah[i][3], base + 0*MM_MATB + off);
                    ldsm_x4(al[i][0], al[i][1], al[i][2], al[i][3], base + 1*MM_MATB + off);
                }
                #pragma unroll
                for (int g = 0; g < 2; g++) {
                    uint32_t off = ((bRowBase + g*16)*24 + bCol)*2;
                    ldsm_x4(bh[g*4+0], bh[g*4+1], bh[g*4+2], bh[g*4+3], base + 2*MM_MATB + off);
                    ldsm_x4(bl[g*4+0], bl[g*4+1], bl[g*4+2], bl[g*4+3], base + 3*MM_MATB + off);
                }
                #pragma unroll
                for (int i = 0; i < 4; i++) {
                    #pragma unroll
                    for (int j = 0; j < 4; j++) {
                        mma_bf16(acc[i][j], ah[i], bh[j*2], bh[j*2+1]);
                        mma_bf16(acc[i][j], ah[i], bl[j*2], bl[j*2+1]);
                        mma_bf16(acc[i][j], al[i], bh[j*2], bh[j*2+1]);
                    }
                }
            }
        }
    }

    /* ---- epilogue ---- */
    float scale = (code == 0) ? QSCALE : 1.0f;
    __nv_bfloat16* Hd = (code==0)?g_aqh:(code==1)?g_akh:g_avh;
    __nv_bfloat16* Ld = (code==0)?g_aql:(code==1)?g_akl:g_avl;
    #pragma unroll
    for (int j = 0; j < 4; j++) {
        int col = n0 + warp_n*32 + j*8 + (lane & 3)*2;
        float b0v = bias[col], b1v = bias[col+1];
        int hh = col >> 6, d0 = col & 63;
        #pragma unroll
        for (int i = 0; i < 4; i++) {
            #pragma unroll
            for (int half = 0; half < 2; half++) {
                int m = m0 + warp_m*64 + i*16 + (lane >> 2) + half*8;
                if (m >= BSQ) continue;
                float v0 = (acc[i][j][half*2]   + b0v)*scale;
                float v1 = (acc[i][j][half*2+1] + b1v)*scale;
                if (code == 3) {
                    *(float2*)(Yext + (size_t)m*DIM + col) = make_float2(v0, v1);
                } else {
                    int b = m / SEQ;
                    int t = m - b*SEQ;
                    float h0 = __bfloat162float(__float2bfloat16(v0));
                    float h1 = __bfloat162float(__float2bfloat16(v1));
                    size_t o = ((size_t)((b*NH + hh)*SEQP) + t)*HD + d0;
                    *(uint32_t*)(Hd + o) = pack_bf2(h0, h1);
                    *(uint32_t*)(Ld + o) = pack_bf2(v0 - h0, v1 - h1);
                }
            }
        }
    }
}

/* ---------------- xvmma_qkv: xv(p=0..2) = X @ [Vb0;Vb1;Vb2]^T ------------- */
#define X3_ABYT 13824
#define X3_BBYT 13824
#define X3_STGB (2*X3_ABYT + 2*X3_BBYT)
#define X3_SMEM (2*X3_STGB)

__device__ __forceinline__ void x3_load_stage(uint32_t sb, int buf, int k0,
                                              int b, int mt, int tid)
{
    uint32_t base = sb + buf*X3_STGB;
    #pragma unroll
    for (int i = 0; i < 16; i++) {
        int c = tid + 192*i;
        if (c >= 3072) break;
        int m4 = c / 768;
        int cc2 = c - m4*768;
        int row = cc2 >> 3, col8 = (cc2 & 7)*8;
        if (m4 < 2) {
            int t = mt*96 + row;
            int ok = t < SEQ;
            const __nv_bfloat16* src = (m4 ? g_xl : g_xh) +
                ((size_t)b*SEQ + (ok ? t : 0))*DIM + k0 + col8;
            cp16(base + m4*X3_ABYT + (uint32_t)(row*72 + col8)*2, src, ok ? 16 : 0);
        } else {
            int p = row >> 5, jr = row & 31;
            const __nv_bfloat16* src = ((m4 == 3) ? g_vbl : g_vbh) +
                (size_t)p*BB*32*DIM + ((size_t)b*32 + jr)*DIM + k0 + col8;
            cp16(base + 2*X3_ABYT + (m4 - 2)*X3_BBYT + (uint32_t)(row*72 + col8)*2, src, 16);
        }
    }
}

__global__ void __launch_bounds__(192, 1) xvmma_qkv_kernel()
{
    extern __shared__ __align__(16) char xsm[];
    uint32_t sb = smem_u32(xsm);
    int tid = threadIdx.x, lane = tid & 31, w = tid >> 5;
    int mt = blockIdx.x, b = blockIdx.y;

    float acc[12][4];
    #pragma unroll
    for (int j = 0; j < 12; j++)
        #pragma unroll
        for (int q = 0; q < 4; q++) acc[j][q] = 0.f;

    uint32_t aRow = (uint32_t)(w*16 + (lane & 15));
    uint32_t aCol = (uint32_t)((lane >> 4)*8);
    uint32_t bRow = (uint32_t)((lane & 7) + ((lane >> 4) << 3));
    uint32_t bCol = (uint32_t)(((lane >> 3) & 1)*8);

    x3_load_stage(sb, 0, 0, b, mt, tid);
    CP_COMMIT();

    for (int s = 0; s < 16; s++) {
        if (s + 1 < 16) {
            x3_load_stage(sb, (s+1)&1, (s+1)*64, b, mt, tid);
            CP_COMMIT();
            CP_WAIT1();
        } else {
            CP_WAIT0();
        }
        __syncthreads();
        uint32_t stg = sb + (s&1)*X3_STGB;
        #pragma unroll
        for (int kt = 0; kt < 4; kt++) {
            uint32_t ah[4], al[4];
            uint32_t off = (aRow*72 + kt*16 + aCol)*2;
            ldsm_x4(ah[0], ah[1], ah[2], ah[3], stg + off);
            ldsm_x4(al[0], al[1], al[2], al[3], stg + X3_ABYT + off);
            #pragma unroll
            for (int g = 0; g < 6; g++) {
                uint32_t bo = ((bRow + g*16)*72 + kt*16 + bCol)*2;
                uint32_t bh[4], bl[4];
                ldsm_x4(bh[0], bh[1], bh[2], bh[3], stg + 2*X3_ABYT + bo);
                ldsm_x4(bl[0], bl[1], bl[2], bl[3], stg + 2*X3_ABYT + X3_BBYT + bo);
                #pragma unroll
                for (int r = 0; r < 2; r++) {
                    int jj = g*2 + r;
                    mma_bf16(acc[jj], ah, bh[r*2], bh[r*2+1]);
                    mma_bf16(acc[jj], ah, bl[r*2], bl[r*2+1]);
                    mma_bf16(acc[jj], al, bh[r*2], bh[r*2+1]);
                }
            }
        }
        __syncthreads();
    }

    int r0 = mt*96 + w*16 + (lane >> 2);
    int r1 = r0 + 8;
    #pragma unroll
    for (int j = 0; j < 12; j++) {
        int n = j*8 + (lane & 3)*2;
        int p = n >> 5, coln = n & 31;
        size_t xvoff = (size_t)p*BB*SEQP*32;
        if (r0 < SEQ) {
            float p0 = acc[j][0], p1 = acc[j][1];
            float h0 = __bfloat162float(__float2bfloat16(p0));
            float h1 = __bfloat162float(__float2bfloat16(p1));
            size_t o = xvoff + ((size_t)b*SEQP + r0)*32 + coln;
            *(uint32_t*)(g_xvh + o) = pack_bf2(h0, h1);
            *(uint32_t*)(g_xvl + o) = pack_bf2(p0 - h0, p1 - h1);
        }
        if (r1 < SEQ) {
            float p0 = acc[j][2], p1 = acc[j][3];
            float h0 = __bfloat162float(__float2bfloat16(p0));
            float h1 = __bfloat162float(__float2bfloat16(p1));
            size_t o = xvoff + ((size_t)b*SEQP + r1)*32 + coln;
            *(uint32_t*)(g_xvh + o) = pack_bf2(h0, h1);
            *(uint32_t*)(g_xvl + o) = pack_bf2(p0 - h0, p1 - h1);
        }
    }
}

/* ---------------- xvmma (single p = 3, ctx) -------------------- */
#define XV_ABYT 13824
#define XV_BBYT 4608
#define XV_STGB (2*XV_ABYT + 2*XV_BBYT)
#define XV_SMEM (2*XV_STGB)

__device__ __forceinline__ void xv_load_stage(uint32_t sb, int buf, int k0,
                                              int b, int mt, int tid, int p)
{
    uint32_t base = sb + buf*XV_STGB;
    size_t vboff = (size_t)p*BB*32*DIM;
    #pragma unroll
    for (int i = 0; i < 11; i++) {
        int c = tid + 192*i;
        if (c >= 2048) break;
        if (c < 1536) {
            int mat = (c >= 768);
            int cc = c - (mat ? 768 : 0);
            int row = cc >> 3, col8 = (cc & 7)*8;
            int t = mt*96 + row;
            int ok = t < SEQ;
            const __nv_bfloat16* src = (mat ? g_xl : g_xh) +
                ((size_t)b*SEQ + (ok ? t : 0))*DIM + k0 + col8;
            cp16(base + mat*XV_ABYT + (uint32_t)(row*72 + col8)*2, src, ok ? 16 : 0);
        } else {
            int c2 = c - 1536;
            int mat = c2 >> 8;
            int cc = c2 & 255;
            int row = cc >> 3, col8 = (cc & 7)*8;
            const __nv_bfloat16* src = (mat ? g_vbl : g_vbh) + vboff +
                ((size_t)b*32 + row)*DIM + k0 + col8;
            cp16(base + 2*XV_ABYT + mat*XV_BBYT + (uint32_t)(row*72 + col8)*2, src, 16);
        }
    }
}

__global__ void __launch_bounds__(192, 1) xvmma_kernel(int p)
{
    extern __shared__ __align__(16) char xsm[];
    uint32_t sb = smem_u32(xsm);
    int tid = threadIdx.x, lane = tid & 31, w = tid >> 5;
    int mt = blockIdx.x, b = blockIdx.y;

    float acc[4][4];
    #pragma unroll
    for (int j = 0; j < 4; j++)
        #pragma unroll
        for (int q = 0; q < 4; q++) acc[j][q] = 0.f;

    uint32_t aRow = (uint32_t)(w*16 + (lane & 15));
    uint32_t aCol = (uint32_t)((lane >> 4)*8);
    uint32_t bRow = (uint32_t)((lane & 7) + ((lane >> 4) << 3));
    uint32_t bCol = (uint32_t)(((lane >> 3) & 1)*8);

    xv_load_stage(sb, 0, 0, b, mt, tid, p);
    CP_COMMIT();

    for (int s = 0; s < 16; s++) {
        if (s + 1 < 16) {
            xv_load_stage(sb, (s+1)&1, (s+1)*64, b, mt, tid, p);
            CP_COMMIT();
            CP_WAIT1();
        } else {
            CP_WAIT0();
        }
        __syncthreads();
        uint32_t stg = sb + (s&1)*XV_STGB;
        #pragma unroll
        for (int kt = 0; kt < 4; kt++) {
            uint32_t ah[4], al[4], bh2[8], bl2[8];
            uint32_t off = (aRow*72 + kt*16 + aCol)*2;
            ldsm_x4(ah[0], ah[1], ah[2], ah[3], stg + off);
            ldsm_x4(al[0], al[1], al[2], al[3], stg + XV_ABYT + off);
            #pragma unroll
            for (int g = 0; g < 2; g++) {
                uint32_t bo = ((bRow + g*16)*72 + kt*16 + bCol)*2;
                ldsm_x4(bh2[g*4+0], bh2[g*4+1], bh2[g*4+2], bh2[g*4+3],
                        stg + 2*XV_ABYT + bo);
                ldsm_x4(bl2[g*4+0], bl2[g*4+1], bl2[g*4+2], bl2[g*4+3],
                        stg + 2*XV_ABYT + XV_BBYT + bo);
            }
            #pragma unroll
            for (int j = 0; j < 4; j++) {
                mma_bf16(acc[j], ah, bh2[j*2], bh2[j*2+1]);
                mma_bf16(acc[j], ah, bl2[j*2], bl2[j*2+1]);
                mma_bf16(acc[j], al, bh2[j*2], bh2[j*2+1]);
            }
        }
        __syncthreads();
    }

    size_t xvoff = (size_t)p*BB*SEQP*32;
    int r0 = mt*96 + w*16 + (lane >> 2);
    int r1 = r0 + 8;
    #pragma unroll
    for (int j = 0; j < 4; j++) {
        int col = j*8 + (lane & 3)*2;
        if (r0 < SEQ) {
            float p0 = acc[j][0], p1 = acc[j][1];
            float h0 = __bfloat162float(__float2bfloat16(p0));
            float h1 = __bfloat162float(__float2bfloat16(p1));
            size_t o = xvoff + ((size_t)b*SEQP + r0)*32 + col;
            *(uint32_t*)(g_xvh + o) = pack_bf2(h0, h1);
            *(uint32_t*)(g_xvl + o) = pack_bf2(p0 - h0, p1 - h1);
        }
        if (r1 < SEQ) {
            float p0 = acc[j][2], p1 = acc[j][3];
            float h0 = __bfloat162float(__float2bfloat16(p0));
            float h1 = __bfloat162float(__float2bfloat16(p1));
            size_t o = xvoff + ((size_t)b*SEQP + r1)*32 + col;
            *(uint32_t*)(g_xvh + o) = pack_bf2(h0, h1);
            *(uint32_t*)(g_xvl + o) = pack_bf2(p0 - h0, p1 - h1);
        }
    }
}

/* ---------------- fused flash attention (KV chunk = 32, 9 chunks) --------- */
#define FA_QBYTES  13824
#define FA_MATB    4608
#define FA_STGB    (4*FA_MATB)
#define FA_KVBASE  (2*FA_QBYTES)
#define FA_SMEM    (FA_KVBASE + 2*FA_STGB)
#define FA_NC      9

__device__ __forceinline__ void fa_load_kv(uint32_t sb, int buf, int t0,
                                           int bh, int tid)
{
    uint32_t base = sb + FA_KVBASE + buf*FA_STGB;
    size_t goff = (size_t)bh*SEQP*HD + (size_t)t0*HD;
    const __nv_bfloat16* srcs[4] = {g_akh + goff, g_akl + goff, g_avh + goff, g_avl + goff};
    #pragma unroll
    for (int i = 0; i < 6; i++) {
        int c = tid + 192*i;
        if (c < 1024) {
            int mat = c >> 8, cc = c & 255;
            int row = cc >> 3, col8 = (cc & 7)*8;
            cp16(base + mat*FA_MATB + (uint32_t)(row*72 + col8)*2,
                 srcs[mat] + (size_t)row*HD + col8, 16);
        }
    }
}

__global__ void __launch_bounds__(192, 3) fa_kernel()
{
    extern __shared__ __align__(16) char fsm[];
    uint32_t sb = smem_u32(fsm);
    int tid = threadIdx.x, lane = tid & 31, w = tid >> 5;
    int mt = blockIdx.x, bh = blockIdx.y;
    int b = bh >> 4, hh = bh & 15;

    {
        const __nv_bfloat16* qs[2] = {g_aqh, g_aql};
        #pragma unroll
        for (int mat = 0; mat < 2; mat++) {
            const __nv_bfloat16* src = qs[mat] + ((size_t)bh*SEQP + mt*96)*HD;
            #pragma unroll
            for (int it = 0; it < 4; it++) {
                int c = tid + 192*it;
                int row = c >> 3, col8 = (c & 7)*8;
                uint4 v = *(const uint4*)(src + (size_t)row*HD + col8);
                *(uint4*)(fsm + mat*FA_QBYTES + (row*72 + col8)*2) = v;
            }
        }
    }
    fa_load_kv(sb, 0, 0, bh, tid);
    CP_COMMIT();
    __syncthreads();

    uint32_t qh[4][4], ql[4][4];
    {
        uint32_t aRow = (uint32_t)(w*16 + (lane & 15));
        uint32_t aCol = (uint32_t)((lane >> 4)*8);
        #pragma unroll
        for (int kt = 0; kt < 4; kt++) {
            uint32_t off = (aRow*72 + kt*16 + aCol)*2;
            ldsm_x4(qh[kt][0], qh[kt][1], qh[kt][2], qh[kt][3], sb + off);
            ldsm_x4(ql[kt][0], ql[kt][1], ql[kt][2], ql[kt][3], sb + FA_QBYTES + off);
        }
    }

    float o[8][4];
    #pragma unroll
    for (int j = 0; j < 8; j++)
        #pragma unroll
        for (int q = 0; q < 4; q++) o[j][q] = 0.f;
    float mr0 = -1e30f, mr1 = -1e30f, l0 = 0.f, l1 = 0.f;

    uint32_t kRow = (uint32_t)((lane & 7) + ((lane >> 4) << 3));
    uint32_t kCol = (uint32_t)(((lane >> 3) & 1)*8);
    uint32_t vRow = (uint32_t)(lane & 15);
    uint32_t vCol = (uint32_t)((lane >> 4) << 3);

    for (int c = 0; c < FA_NC; c++) {
        if (c + 1 < FA_NC) {
            fa_load_kv(sb, (c+1)&1, (c+1)*32, bh, tid);
            CP_COMMIT();
            CP_WAIT1();
        } else {
            CP_WAIT0();
        }
        __syncthreads();
        uint32_t stg = sb + FA_KVBASE + (c&1)*FA_STGB;

        float S[4][4];
        #pragma unroll
        for (int j = 0; j < 4; j++)
            #pragma unroll
            for (int q = 0; q < 4; q++) S[j][q] = 0.f;

        #pragma unroll
        for (int kt = 0; kt < 4; kt++) {
            #pragma unroll
            for (int g = 0; g < 2; g++) {
                uint32_t off = ((kRow + g*16)*72 + kt*16 + kCol)*2;
                uint32_t h0,h1,h2,h3, e0,e1,e2,e3;
                ldsm_x4(h0,h1,h2,h3, stg + 0*FA_MATB + off);
                ldsm_x4(e0,e1,e2,e3, stg + 1*FA_MATB + off);
                mma_bf16(S[2*g],   qh[kt], h0, h1);
                mma_bf16(S[2*g],   qh[kt], e0, e1);
                mma_bf16(S[2*g],   ql[kt], h0, h1);
                mma_bf16(S[2*g+1], qh[kt], h2, h3);
                mma_bf16(S[2*g+1], qh[kt], e2, e3);
                mma_bf16(S[2*g+1], ql[kt], h2, h3);
            }
        }

        if (c == FA_NC - 1) {
            #pragma unroll
            for (int j = 0; j < 4; j++) {
                int tb = (FA_NC-1)*32 + j*8 + (lane & 3)*2;
                if (tb     >= SEQ) { S[j][0] = -1e30f; S[j][2] = -1e30f; }
                if (tb + 1 >= SEQ) { S[j][1] = -1e30f; S[j][3] = -1e30f; }
            }
        }

        float mx0 = -1e30f, mx1 = -1e30f;
        #pragma unroll
        for (int j = 0; j < 4; j++) {
            mx0 = fmaxf(mx0, fmaxf(S[j][0], S[j][1]));
            mx1 = fmaxf(mx1, fmaxf(S[j][2], S[j][3]));
        }
        mx0 = fmaxf(mx0, __shfl_xor_sync(0xffffffffu, mx0, 1));
        mx0 = fmaxf(mx0, __shfl_xor_sync(0xffffffffu, mx0, 2));
        mx1 = fmaxf(mx1, __shfl_xor_sync(0xffffffffu, mx1, 1));
        mx1 = fmaxf(mx1, __shfl_xor_sync(0xffffffffu, mx1, 2));
        float mn0 = fmaxf(mr0, mx0), mn1 = fmaxf(mr1, mx1);
        float sc0 = expf(mr0 - mn0), sc1 = expf(mr1 - mn1);
        mr0 = mn0; mr1 = mn1;

        uint32_t ph[2][4], pl[2][4];
        float rs0 = 0.f, rs1 = 0.f;
        #pragma unroll
        for (int j = 0; j < 4; j++) {
            float p0 = expf(S[j][0] - mn0), p1 = expf(S[j][1] - mn0);
            float p2 = expf(S[j][2] - mn1), p3 = expf(S[j][3] - mn1);
            rs0 += p0 + p1; rs1 += p2 + p3;
            float h0 = __bfloat162float(__float2bfloat16(p0));
            float h1 = __bfloat162float(__float2bfloat16(p1));
            float h2 = __bfloat162float(__float2bfloat16(p2));
            float h3 = __bfloat162float(__float2bfloat16(p3));
            int kt2 = j >> 1, hb = (j & 1)*2;
            ph[kt2][hb]   = pack_bf2(h0, h1);
            ph[kt2][hb+1] = pack_bf2(h2, h3);
            pl[kt2][hb]   = pack_bf2(p0 - h0, p1 - h1);
            pl[kt2][hb+1] = pack_bf2(p2 - h2, p3 - h3);
        }
        rs0 += __shfl_xor_sync(0xffffffffu, rs0, 1);
        rs0 += __shfl_xor_sync(0xffffffffu, rs0, 2);
        rs1 += __shfl_xor_sync(0xffffffffu, rs1, 1);
        rs1 += __shfl_xor_sync(0xffffffffu, rs1, 2);
        l0 = l0*sc0 + rs0;
        l1 = l1*sc1 + rs1;

        #pragma unroll
        for (int j = 0; j < 8; j++) {
            o[j][0] *= sc0; o[j][1] *= sc0;
            o[j][2] *= sc1; o[j][3] *= sc1;
        }

        #pragma unroll
        for (int kt2 = 0; kt2 < 2; kt2++) {
            #pragma unroll
            for (int g = 0; g < 4; g++) {
                uint32_t off = ((kt2*16 + vRow)*72 + g*16 + vCol)*2;
                uint32_t h0,h1,h2,h3, e0,e1,e2,e3;
                ldsm_x4_t(h0,h1,h2,h3, stg + 2*FA_MATB + off);
                ldsm_x4_t(e0,e1,e2,e3, stg + 3*FA_MATB + off);
                mma_bf16(o[2*g],   ph[kt2], h0, h1);
                mma_bf16(o[2*g],   ph[kt2], e0, e1);
                mma_bf16(o[2*g],   pl[kt2], h0, h1);
                mma_bf16(o[2*g+1], ph[kt2], h2, h3);
                mma_bf16(o[2*g+1], ph[kt2], e2, e3);
                mma_bf16(o[2*g+1], pl[kt2], h2, h3);
            }
        }
        __syncthreads();
    }

    float inv0 = 1.f/l0, inv1 = 1.f/l1;
    int r0 = mt*96 + w*16 + (lane >> 2);
    int r1 = r0 + 8;
    #pragma unroll
    for (int j = 0; j < 8; j++) {
        int d = hh*HD + j*8 + (lane & 3)*2;
        if (r0 < SEQ) {
            float v0 = o[j][0]*inv0, v1 = o[j][1]*inv0;
            float h0 = __bfloat162float(__float2bfloat16(v0));
            float h1 = __bfloat162float(__float2bfloat16(v1));
            size_t off = (size_t)(b*SEQ + r0)*DIM + d;
            *(uint32_t*)(g_xh + off) = pack_bf2(h0, h1);
            *(uint32_t*)(g_xl + off) = pack_bf2(v0 - h0, v1 - h1);
        }
        if (r1 < SEQ) {
            float v0 = o[j][2]*inv1, v1 = o[j][3]*inv1;
            float h0 = __bfloat162float(__float2bfloat16(v0));
            float h1 = __bfloat162float(__float2bfloat16(v1));
            size_t off = (size_t)(b*SEQ + r1)*DIM + d;
            *(uint32_t*)(g_xh + off) = pack_bf2(h0, h1);
            *(uint32_t*)(g_xl + off) = pack_bf2(v0 - h0, v1 - h1);
        }
    }
}

/* ---------------- launch ---------------- */
extern "C" void kernel_launch(void* const* d_in, const int* in_sizes, int n_in,
                              void* d_out, int out_size)
{
    const float* x   = (const float*)d_in[0];
    const float* gw1 = (const float*)d_in[1];
    const float* gb1 = (const float*)d_in[2];
    const float* gw2 = (const float*)d_in[3];
    const float* gb2 = (const float*)d_in[4];
    const float* Wm[4] = {(const float*)d_in[5],  (const float*)d_in[10],
                          (const float*)d_in[15], (const float*)d_in[20]};
    const float* Uu[4] = {(const float*)d_in[6],  (const float*)d_in[11],
                          (const float*)d_in[16], (const float*)d_in[21]};
    const float* Ss[4] = {(const float*)d_in[7],  (const float*)d_in[12],
                          (const float*)d_in[17], (const float*)d_in[22]};
    const float* Vv[4] = {(const float*)d_in[8],  (const float*)d_in[13],
                          (const float*)d_in[18], (const float*)d_in[23]};
    const float* bbv[4] = {(const float*)d_in[9],  (const float*)d_in[14],
                           (const float*)d_in[19], (const float*)d_in[24]};
    float* out = (float*)d_out;

    cudaFuncSetAttribute(mm_kernel, cudaFuncAttributeMaxDynamicSharedMemorySize, MM_SMEM);
    cudaFuncSetAttribute(fa_kernel, cudaFuncAttributeMaxDynamicSharedMemorySize, FA_SMEM);
    cudaFuncSetAttribute(xvmma_kernel, cudaFuncAttributeMaxDynamicSharedMemorySize, XV_SMEM);
    cudaFuncSetAttribute(xvmma_qkv_kernel, cudaFuncAttributeMaxDynamicSharedMemorySize, X3_SMEM);

    pool_kernel<<<dim3(BB, 8), 128>>>(x);
    gating_mlp_kernel<<<BB, GHID>>>(gw1, gb1, gw2, gb2);

    int nx4 = BSQ*DIM/4;
    int nw4 = DIM*DIM/4;
    convx_kernel<<<(nx4 + 255)/256, 256>>>(x, nx4);
    convw_kernel<<<dim3((nw4 + 255)/256, 4), 256>>>(Wm[0], Wm[1], Wm[2], Wm[3]);

    vconv_kernel<<<dim3(BB, 32, 4), 256>>>(Vv[0], Vv[1], Vv[2], Vv[3],
                                           Ss[0], Ss[1], Ss[2], Ss[3]);
    uconv_kernel<<<dim3(BB, 4, 4), 256>>>(Uu[0], Uu[1], Uu[2], Uu[3]);

    xvmma_qkv_kernel<<<dim3(3, BB), 192, X3_SMEM>>>();

    dim3 gmm(8, 65, 3);
    mm_kernel<<<gmm, 256, MM_SMEM>>>(-1, bbv[0], bbv[1], bbv[2], nullptr);

    fa_kernel<<<dim3(3, BB*NH), 192, FA_SMEM>>>();

    xvmma_kernel<<<dim3(3, BB), 192, XV_SMEM>>>(3);
    mm_kernel<<<dim3(8, 65, 1), 256, MM_SMEM>>>(3, bbv[3], bbv[3], bbv[3], out);
}

// round 13
// speedup vs baseline: 1.0234x; 1.0234x over previous
#include <cuda_runtime.h>
#include <cuda_bf16.h>
#include <cstdint>
#include <math.h>

#define BB   32
#define SEQ  257
#define SEQP 320
#define DIM  1024
#define NH   16
#define HD   64
#define NEXP 8
#define RNK  16
#define GHID 256
#define BSQ  (BB*SEQ)          /* 8224 tokens */
#define QSCALE 0.125f

/* ---------------- scratch (device globals; no allocations) ---------------- */
static __device__ float g_pooled[BB*DIM];
static __device__ float g_gates[BB*2];
static __device__ int   g_idx  [BB*2];
static __device__ __align__(16) __nv_bfloat16 g_xh[(size_t)BSQ*DIM];
static __device__ __align__(16) __nv_bfloat16 g_xl[(size_t)BSQ*DIM];
static __device__ __align__(16) __nv_bfloat16 g_wh[(size_t)4*DIM*DIM];
static __device__ __align__(16) __nv_bfloat16 g_wl[(size_t)4*DIM*DIM];
static __device__ __align__(16) __nv_bfloat16 g_vbh[(size_t)4*BB*32*DIM];
static __device__ __align__(16) __nv_bfloat16 g_vbl[(size_t)4*BB*32*DIM];
static __device__ __align__(16) __nv_bfloat16 g_ubh[(size_t)4*BB*DIM*32];
static __device__ __align__(16) __nv_bfloat16 g_ubl[(size_t)4*BB*DIM*32];
static __device__ __align__(16) __nv_bfloat16 g_xvh[(size_t)4*BB*SEQP*32];
static __device__ __align__(16) __nv_bfloat16 g_xvl[(size_t)4*BB*SEQP*32];
static __device__ __align__(16) __nv_bfloat16 g_aqh[(size_t)BB*NH*SEQP*HD];
static __device__ __align__(16) __nv_bfloat16 g_aql[(size_t)BB*NH*SEQP*HD];
static __device__ __align__(16) __nv_bfloat16 g_akh[(size_t)BB*NH*SEQP*HD];
static __device__ __align__(16) __nv_bfloat16 g_akl[(size_t)BB*NH*SEQP*HD];
static __device__ __align__(16) __nv_bfloat16 g_avh[(size_t)BB*NH*SEQP*HD];
static __device__ __align__(16) __nv_bfloat16 g_avl[(size_t)BB*NH*SEQP*HD];

/* ---------------- small PTX helpers ---------------- */
__device__ __forceinline__ uint32_t smem_u32(const void* p) {
    uint32_t a;
    asm("{ .reg .u64 t; cvta.to.shared.u64 t, %1; cvt.u32.u64 %0, t; }" : "=r"(a) : "l"(p));
    return a;
}
__device__ __forceinline__ void cp16(uint32_t dst, const void* src, int srcBytes) {
    asm volatile("cp.async.cg.shared.global [%0], [%1], 16, %2;"
                 :: "r"(dst), "l"(src), "r"(srcBytes) : "memory");
}
#define CP_COMMIT() asm volatile("cp.async.commit_group;" ::: "memory")
#define CP_WAIT0()  asm volatile("cp.async.wait_group 0;" ::: "memory")

__device__ __forceinline__ void ldsm_x4(uint32_t& r0, uint32_t& r1, uint32_t& r2, uint32_t& r3,
                                        uint32_t addr) {
    asm volatile("ldmatrix.sync.aligned.m8n8.x4.shared.b16 {%0,%1,%2,%3}, [%4];"
                 : "=r"(r0), "=r"(r1), "=r"(r2), "=r"(r3) : "r"(addr));
}
__device__ __forceinline__ void ldsm_x4_t(uint32_t& r0, uint32_t& r1, uint32_t& r2, uint32_t& r3,
                                          uint32_t addr) {
    asm volatile("ldmatrix.sync.aligned.m8n8.x4.trans.shared.b16 {%0,%1,%2,%3}, [%4];"
                 : "=r"(r0), "=r"(r1), "=r"(r2), "=r"(r3) : "r"(addr));
}
__device__ __forceinline__ void mma_bf16(float* c, const uint32_t* a, uint32_t b0, uint32_t b1) {
    asm volatile("mma.sync.aligned.m16n8k16.row.col.f32.bf16.bf16.f32 "
                 "{%0,%1,%2,%3}, {%4,%5,%6,%7}, {%8,%9}, {%0,%1,%2,%3};"
                 : "+f"(c[0]), "+f"(c[1]), "+f"(c[2]), "+f"(c[3])
                 : "r"(a[0]), "r"(a[1]), "r"(a[2]), "r"(a[3]), "r"(b0), "r"(b1));
}
__device__ __forceinline__ uint32_t pack_bf2(float lo, float hi) {
    __nv_bfloat16 l = __float2bfloat16(lo), h = __float2bfloat16(hi);
    return ((uint32_t)__bfloat16_as_ushort(h) << 16) | (uint32_t)__bfloat16_as_ushort(l);
}

/* ---------------- pooling (parallel) + gating MLP ---------------- */
__global__ void pool_kernel(const float* __restrict__ x)
{
    int b = blockIdx.x;
    int d = blockIdx.y*128 + threadIdx.x;
    const float* xp = x + (size_t)b*SEQ*DIM + d;
    float s = 0.f;
    #pragma unroll 4
    for (int t = 0; t < SEQ; t++) s += xp[(size_t)t*DIM];
    g_pooled[b*DIM + d] = s * (1.0f/SEQ);
}

__global__ void gating_mlp_kernel(const float* __restrict__ gw1, const float* __restrict__ gb1,
                                  const float* __restrict__ gw2, const float* __restrict__ gb2)
{
    int b = blockIdx.x;
    __shared__ float h[GHID];
    __shared__ float logits[NEXP];
    int tid = threadIdx.x;
    const float* pooled = g_pooled + b*DIM;
    {
        float a = gb1[tid];
        const float* w = gw1 + (size_t)tid*DIM;
        #pragma unroll 4
        for (int d = 0; d < DIM; d++) a += pooled[d]*w[d];
        h[tid] = fmaxf(a, 0.f);
    }
    __syncthreads();
    if (tid < NEXP) {
        float a = gb2[tid];
        const float* w = gw2 + tid*GHID;
        for (int d = 0; d < GHID; d++) a += h[d]*w[d];
        logits[tid] = a;
    }
    __syncthreads();
    if (tid == 0) {
        int i0 = 0;
        for (int e = 1; e < NEXP; e++) if (logits[e] > logits[i0]) i0 = e;
        int i1 = -1;
        for (int e = 0; e < NEXP; e++) {
            if (e == i0) continue;
            if (i1 < 0 || logits[e] > logits[i1]) i1 = e;
        }
        float v0 = logits[i0], v1 = logits[i1];
        float e0 = expf(v0 - v0), e1 = expf(v1 - v0);
        float inv = 1.f/(e0 + e1);
        g_gates[b*2]   = e0*inv;
        g_gates[b*2+1] = e1*inv;
        g_idx[b*2]   = i0;
        g_idx[b*2+1] = i1;
    }
}

/* ---------------- fp32 -> (bf16 hi, bf16 lo) ---------------- */
__device__ __forceinline__ void split4(float4 v, ushort4& hh, ushort4& ll)
{
    __nv_bfloat16 t;
    t = __float2bfloat16(v.x); hh.x = __bfloat16_as_ushort(t);
    ll.x = __bfloat16_as_ushort(__float2bfloat16(v.x - __bfloat162float(t)));
    t = __float2bfloat16(v.y); hh.y = __bfloat16_as_ushort(t);
    ll.y = __bfloat16_as_ushort(__float2bfloat16(v.y - __bfloat162float(t)));
    t = __float2bfloat16(v.z); hh.z = __bfloat16_as_ushort(t);
    ll.z = __bfloat16_as_ushort(__float2bfloat16(v.z - __bfloat162float(t)));
    t = __float2bfloat16(v.w); hh.w = __bfloat16_as_ushort(t);
    ll.w = __bfloat16_as_ushort(__float2bfloat16(v.w - __bfloat162float(t)));
}

__global__ void convx_kernel(const float* __restrict__ s, int n4)
{
    int i = blockIdx.x*256 + threadIdx.x;
    if (i >= n4) return;
    ushort4 hh, ll;
    split4(((const float4*)s)[i], hh, ll);
    ((ushort4*)g_xh)[i] = hh;
    ((ushort4*)g_xl)[i] = ll;
}

__global__ void convw_kernel(const float* __restrict__ w0, const float* __restrict__ w1,
                             const float* __restrict__ w2, const float* __restrict__ w3)
{
    int p = blockIdx.y;
    const float* s = (p==0)?w0:(p==1)?w1:(p==2)?w2:w3;
    int i = blockIdx.x*256 + threadIdx.x;
    ushort4 hh, ll;
    split4(((const float4*)s)[i], hh, ll);
    size_t o = (size_t)p*(DIM*DIM/4) + i;
    ((ushort4*)g_wh)[o] = hh;
    ((ushort4*)g_wl)[o] = ll;
}

/* ---------------- vconv / uconv ---------------- */
__global__ void vconv_kernel(const float* __restrict__ V0, const float* __restrict__ V1,
                             const float* __restrict__ V2, const float* __restrict__ V3,
                             const float* __restrict__ S0, const float* __restrict__ S1,
                             const float* __restrict__ S2, const float* __restrict__ S3)
{
    int b = blockIdx.x, j = blockIdx.y, p = blockIdx.z;
    const float* Vm = (p==0)?V0:(p==1)?V1:(p==2)?V2:V3;
    const float* Sm = (p==0)?S0:(p==1)?S1:(p==2)?S2:S3;
    int half = j >> 4, r = j & 15;
    int e = g_idx[b*2 + half];
    float sc = g_gates[b*2 + half] * Sm[e*RNK + r];
    float4 v = ((const float4*)(Vm + ((size_t)e*RNK + r)*DIM))[threadIdx.x];
    v.x *= sc; v.y *= sc; v.z *= sc; v.w *= sc;
    ushort4 hh, ll;
    split4(v, hh, ll);
    size_t o = ((size_t)p*BB*32 + (size_t)b*32 + j)*DIM/4 + threadIdx.x;
    ((ushort4*)g_vbh)[o] = hh;
    ((ushort4*)g_vbl)[o] = ll;
}

__global__ void uconv_kernel(const float* __restrict__ U0, const float* __restrict__ U1,
                             const float* __restrict__ U2, const float* __restrict__ U3)
{
    int b = blockIdx.x, p = blockIdx.z;
    const float* U = (p==0)?U0:(p==1)?U1:(p==2)?U2:U3;
    int n = blockIdx.y*256 + threadIdx.x;
    int i0 = g_idx[b*2], i1 = g_idx[b*2+1];
    const float* u0 = U + ((size_t)i0*DIM + n)*RNK;
    const float* u1 = U + ((size_t)i1*DIM + n)*RNK;
    __nv_bfloat16* H = g_ubh + ((size_t)p*BB*DIM + (size_t)b*DIM + n)*32;
    __nv_bfloat16* L = g_ubl + ((size_t)p*BB*DIM + (size_t)b*DIM + n)*32;
    #pragma unroll
    for (int r = 0; r < 16; r++) {
        float v0 = u0[r], v1 = u1[r];
        __nv_bfloat16 h0 = __float2bfloat16(v0);
        H[r]      = h0;
        L[r]      = __float2bfloat16(v0 - __bfloat162float(h0));
        __nv_bfloat16 h1 = __float2bfloat16(v1);
        H[16 + r] = h1;
        L[16 + r] = __float2bfloat16(v1 - __bfloat162float(h1));
    }
}

/* ---------------- fused GEMM: Y = (X@W^T + bias + xv@Ub^T) * scale -------- */
/* 2-stage, BK=32; single __syncthreads per stage: wait -> sync -> load -> compute */
#define MAT_BYTES (128*40*2)            /* 10240 */
#define STG_BYTES (4*MAT_BYTES)         /* 40960 */
#define MM_SMEM   (2*STG_BYTES)         /* 81920 */

__device__ __forceinline__ void mm_load_stage(uint32_t sb, int buf, int k0,
    const __nv_bfloat16* Ah, const __nv_bfloat16* Al,
    const __nv_bfloat16* Bh, const __nv_bfloat16* Bl,
    int m0, int n0, int tid)
{
    uint32_t base = sb + buf*STG_BYTES;
    const __nv_bfloat16* srcs[4] = {Ah, Al, Bh, Bl};
    #pragma unroll
    for (int i = 0; i < 8; i++) {
        int c = tid + 256*i;
        int mat = c >> 9;
        int cc  = c & 511;
        int row = cc >> 2;
        int col = (cc & 3) * 8;
        const __nv_bfloat16* p = srcs[mat];
        int grow = ((mat < 2) ? m0 : n0) + row;
        int ok = (mat >= 2) || (grow < BSQ);
        const void* src = p + ((size_t)(ok ? grow : 0))*DIM + k0 + col;
        uint32_t dst = base + mat*MAT_BYTES + (uint32_t)(row*40 + col)*2;
        cp16(dst, src, ok ? 16 : 0);
    }
}

__global__ void __launch_bounds__(256, 2) mm_kernel(int base_code,
    const float* __restrict__ bias0, const float* __restrict__ bias1,
    const float* __restrict__ bias2, float* __restrict__ Yext)
{
    extern __shared__ __align__(128) char smem[];
    int code = (base_code < 0) ? (int)blockIdx.z : base_code;
    const __nv_bfloat16* Ah = g_xh;
    const __nv_bfloat16* Al = g_xl;
    const __nv_bfloat16* Bh = g_wh + (size_t)code*DIM*DIM;
    const __nv_bfloat16* Bl = g_wl + (size_t)code*DIM*DIM;
    const float* bias = (code==0)?bias0:(code==1)?bias1:(code==2)?bias2:bias0;

    uint32_t sb = smem_u32(smem);
    int tid = threadIdx.x;
    int lane = tid & 31;
    int wid = tid >> 5;
    int warp_m = wid >> 2;
    int warp_n = wid & 3;
    int n0 = blockIdx.x*128, m0 = blockIdx.y*128;

    float acc[4][4][4];
    #pragma unroll
    for (int i = 0; i < 4; i++)
        #pragma unroll
        for (int j = 0; j < 4; j++)
            #pragma unroll
            for (int q = 0; q < 4; q++) acc[i][j][q] = 0.f;

    uint32_t aRow = (uint32_t)(warp_m*64 + (lane & 15));
    uint32_t aCol = (uint32_t)((lane >> 4) * 8);
    uint32_t bRowBase = (uint32_t)(warp_n*32 + (lane & 7) + ((lane >> 4) << 3));
    uint32_t bCol = (uint32_t)(((lane >> 3) & 1) * 8);

    mm_load_stage(sb, 0, 0, Ah, Al, Bh, Bl, m0, n0, tid);
    CP_COMMIT();

    const int NK = DIM/32;
    for (int s = 0; s < NK; s++) {
        CP_WAIT0();
        __syncthreads();
        if (s + 1 < NK) {
            mm_load_stage(sb, (s+1)&1, (s+1)*32, Ah, Al, Bh, Bl, m0, n0, tid);
            CP_COMMIT();
        }

        uint32_t stg = sb + (s&1)*STG_BYTES;
        #pragma unroll
        for (int kk = 0; kk < 32; kk += 16) {
            uint32_t ah[4][4], al[4][4], bh[8], bl[8];
            #pragma unroll
            for (int i = 0; i < 4; i++) {
                uint32_t off = ((aRow + i*16)*40 + kk + aCol)*2;
                ldsm_x4(ah[i][0], ah[i][1], ah[i][2], ah[i][3], stg + 0*MAT_BYTES + off);
                ldsm_x4(al[i][0], al[i][1], al[i][2], al[i][3], stg + 1*MAT_BYTES + off);
            }
            #pragma unroll
            for (int g = 0; g < 2; g++) {
                uint32_t off = ((bRowBase + g*16)*40 + kk + bCol)*2;
                ldsm_x4(bh[g*4+0], bh[g*4+1], bh[g*4+2], bh[g*4+3], stg + 2*MAT_BYTES + off);
                ldsm_x4(bl[g*4+0], bl[g*4+1], bl[g*4+2], bl[g*4+3], stg + 3*MAT_BYTES + off);
            }
            #pragma unroll
            for (int i = 0; i < 4; i++) {
                #pragma unroll
                for (int j = 0; j < 4; j++) {
                    mma_bf16(acc[i][j], ah[i], bh[j*2], bh[j*2+1]);
                    mma_bf16(acc[i][j], ah[i], bl[j*2], bl[j*2+1]);
                    mma_bf16(acc[i][j], al[i], bh[j*2], bh[j*2+1]);
                }
            }
        }
    }

    /* ---- fused rank-32 MoE correction: one pass per batch in this tile ---- */
    {
        int mlast = m0 + 127; if (mlast >= BSQ) mlast = BSQ - 1;
        int bb0 = m0 / SEQ, bb1 = mlast / SEQ;
        for (int bb = bb0; bb <= bb1; bb++) {
            uint32_t base = sb + ((bb - bb0) & 1)*STG_BYTES;
            /* wait until all warps finished reading this buffer (mainloop or prev pass) */
            __syncthreads();
            #pragma unroll
            for (int i2 = 0; i2 < 4; i2++) {
                int c = tid + 256*i2;
                int mat = c >> 9, cc = c & 511;
                int row = cc >> 2, col = (cc & 3)*8;
                int m = m0 + row;
                int ok = (m < BSQ) && (m / SEQ == bb);
                int t = m - bb*SEQ;
                const __nv_bfloat16* srcA = (mat ? g_xvl : g_xvh) +
                    (size_t)code*BB*SEQP*32 + ((size_t)bb*SEQP + (ok ? t : 0))*32 + col;
                cp16(base + mat*MAT_BYTES + (uint32_t)(row*40 + col)*2, srcA, ok ? 16 : 0);
            }
            #pragma unroll
            for (int i2 = 0; i2 < 4; i2++) {
                int c = tid + 256*i2;
                int mat = c >> 9, cc = c & 511;
                int row = cc >> 2, col = (cc & 3)*8;
                const __nv_bfloat16* srcB = (mat ? g_ubl : g_ubh) +
                    (size_t)code*BB*DIM*32 + ((size_t)bb*DIM + n0 + row)*32 + col;
                cp16(base + (2 + mat)*MAT_BYTES + (uint32_t)(row*40 + col)*2, srcB, 16);
            }
            CP_COMMIT();
            CP_WAIT0();
            __syncthreads();
            #pragma unroll
            for (int kk = 0; kk < 32; kk += 16) {
                uint32_t ah[4][4], al[4][4], bh[8], bl[8];
                #pragma unroll
                for (int i = 0; i < 4; i++) {
                    uint32_t off = ((aRow + i*16)*40 + kk + aCol)*2;
                    ldsm_x4(ah[i][0], ah[i][1], ah[i][2], ah[i][3], base + 0*MAT_BYTES + off);
                    ldsm_x4(al[i][0], al[i][1], al[i][2], al[i][3], base + 1*MAT_BYTES + off);
                }
                #pragma unroll
                for (int g = 0; g < 2; g++) {
                    uint32_t off = ((bRowBase + g*16)*40 + kk + bCol)*2;
                    ldsm_x4(bh[g*4+0], bh[g*4+1], bh[g*4+2], bh[g*4+3], base + 2*MAT_BYTES + off);
                    ldsm_x4(bl[g*4+0], bl[g*4+1], bl[g*4+2], bl[g*4+3], base + 3*MAT_BYTES + off);
                }
                #pragma unroll
                for (int i = 0; i < 4; i++) {
                    #pragma unroll
                    for (int j = 0; j < 4; j++) {
                        mma_bf16(acc[i][j], ah[i], bh[j*2], bh[j*2+1]);
                        mma_bf16(acc[i][j], ah[i], bl[j*2], bl[j*2+1]);
                        mma_bf16(acc[i][j], al[i], bh[j*2], bh[j*2+1]);
                    }
                }
            }
        }
    }

    /* ---- epilogue ---- */
    float scale = (code == 0) ? QSCALE : 1.0f;
    __nv_bfloat16* Hd = (code==0)?g_aqh:(code==1)?g_akh:g_avh;
    __nv_bfloat16* Ld = (code==0)?g_aql:(code==1)?g_akl:g_avl;
    #pragma unroll
    for (int j = 0; j < 4; j++) {
        int col = n0 + warp_n*32 + j*8 + (lane & 3)*2;
        float b0v = bias[col], b1v = bias[col+1];
        int hh = col >> 6, d0 = col & 63;
        #pragma unroll
        for (int i = 0; i < 4; i++) {
            #pragma unroll
            for (int half = 0; half < 2; half++) {
                int m = m0 + warp_m*64 + i*16 + (lane >> 2) + half*8;
                if (m >= BSQ) continue;
                float v0 = (acc[i][j][half*2]   + b0v)*scale;
                float v1 = (acc[i][j][half*2+1] + b1v)*scale;
                if (code == 3) {
                    *(float2*)(Yext + (size_t)m*DIM + col) = make_float2(v0, v1);
                } else {
                    int b = m / SEQ;
                    int t = m - b*SEQ;
                    float h0 = __bfloat162float(__float2bfloat16(v0));
                    float h1 = __bfloat162float(__float2bfloat16(v1));
                    size_t o = ((size_t)((b*NH + hh)*SEQP) + t)*HD + d0;
                    *(uint32_t*)(Hd + o) = pack_bf2(h0, h1);
                    *(uint32_t*)(Ld + o) = pack_bf2(v0 - h0, v1 - h1);
                }
            }
        }
    }
}

/* ---------------- xvmma_qkv: xv(p=0..2) = X @ [Vb0;Vb1;Vb2]^T ------------- */
#define X3_ABYT 13824
#define X3_BBYT 13824
#define X3_STGB (2*X3_ABYT + 2*X3_BBYT)
#define X3_SMEM (2*X3_STGB)

__device__ __forceinline__ void x3_load_stage(uint32_t sb, int buf, int k0,
                                              int b, int mt, int tid)
{
    uint32_t base = sb + buf*X3_STGB;
    #pragma unroll
    for (int i = 0; i < 16; i++) {
        int c = tid + 192*i;
        if (c >= 3072) break;
        int m4 = c / 768;
        int cc2 = c - m4*768;
        int row = cc2 >> 3, col8 = (cc2 & 7)*8;
        if (m4 < 2) {
            int t = mt*96 + row;
            int ok = t < SEQ;
            const __nv_bfloat16* src = (m4 ? g_xl : g_xh) +
                ((size_t)b*SEQ + (ok ? t : 0))*DIM + k0 + col8;
            cp16(base + m4*X3_ABYT + (uint32_t)(row*72 + col8)*2, src, ok ? 16 : 0);
        } else {
            int p = row >> 5, jr = row & 31;
            const __nv_bfloat16* src = ((m4 == 3) ? g_vbl : g_vbh) +
                (size_t)p*BB*32*DIM + ((size_t)b*32 + jr)*DIM + k0 + col8;
            cp16(base + 2*X3_ABYT + (m4 - 2)*X3_BBYT + (uint32_t)(row*72 + col8)*2, src, 16);
        }
    }
}

__global__ void __launch_bounds__(192, 1) xvmma_qkv_kernel()
{
    extern __shared__ __align__(16) char xsm[];
    uint32_t sb = smem_u32(xsm);
    int tid = threadIdx.x, lane = tid & 31, w = tid >> 5;
    int mt = blockIdx.x, b = blockIdx.y;

    float acc[12][4];
    #pragma unroll
    for (int j = 0; j < 12; j++)
        #pragma unroll
        for (int q = 0; q < 4; q++) acc[j][q] = 0.f;

    uint32_t aRow = (uint32_t)(w*16 + (lane & 15));
    uint32_t aCol = (uint32_t)((lane >> 4)*8);
    uint32_t bRow = (uint32_t)((lane & 7) + ((lane >> 4) << 3));
    uint32_t bCol = (uint32_t)(((lane >> 3) & 1)*8);

    x3_load_stage(sb, 0, 0, b, mt, tid);
    CP_COMMIT();

    for (int s = 0; s < 16; s++) {
        CP_WAIT0();
        __syncthreads();
        if (s + 1 < 16) {
            x3_load_stage(sb, (s+1)&1, (s+1)*64, b, mt, tid);
            CP_COMMIT();
        }
        uint32_t stg = sb + (s&1)*X3_STGB;
        #pragma unroll
        for (int kt = 0; kt < 4; kt++) {
            uint32_t ah[4], al[4];
            uint32_t off = (aRow*72 + kt*16 + aCol)*2;
            ldsm_x4(ah[0], ah[1], ah[2], ah[3], stg + off);
            ldsm_x4(al[0], al[1], al[2], al[3], stg + X3_ABYT + off);
            #pragma unroll
            for (int g = 0; g < 6; g++) {
                uint32_t bo = ((bRow + g*16)*72 + kt*16 + bCol)*2;
                uint32_t bh[4], bl[4];
                ldsm_x4(bh[0], bh[1], bh[2], bh[3], stg + 2*X3_ABYT + bo);
                ldsm_x4(bl[0], bl[1], bl[2], bl[3], stg + 2*X3_ABYT + X3_BBYT + bo);
                #pragma unroll
                for (int r = 0; r < 2; r++) {
                    int jj = g*2 + r;
                    mma_bf16(acc[jj], ah, bh[r*2], bh[r*2+1]);
                    mma_bf16(acc[jj], ah, bl[r*2], bl[r*2+1]);
                    mma_bf16(acc[jj], al, bh[r*2], bh[r*2+1]);
                }
            }
        }
    }

    int r0 = mt*96 + w*16 + (lane >> 2);
    int r1 = r0 + 8;
    #pragma unroll
    for (int j = 0; j < 12; j++) {
        int n = j*8 + (lane & 3)*2;
        int p = n >> 5, coln = n & 31;
        size_t xvoff = (size_t)p*BB*SEQP*32;
        if (r0 < SEQ) {
            float p0 = acc[j][0], p1 = acc[j][1];
            float h0 = __bfloat162float(__float2bfloat16(p0));
            float h1 = __bfloat162float(__float2bfloat16(p1));
            size_t o = xvoff + ((size_t)b*SEQP + r0)*32 + coln;
            *(uint32_t*)(g_xvh + o) = pack_bf2(h0, h1);
            *(uint32_t*)(g_xvl + o) = pack_bf2(p0 - h0, p1 - h1);
        }
        if (r1 < SEQ) {
            float p0 = acc[j][2], p1 = acc[j][3];
            float h0 = __bfloat162float(__float2bfloat16(p0));
            float h1 = __bfloat162float(__float2bfloat16(p1));
            size_t o = xvoff + ((size_t)b*SEQP + r1)*32 + coln;
            *(uint32_t*)(g_xvh + o) = pack_bf2(h0, h1);
            *(uint32_t*)(g_xvl + o) = pack_bf2(p0 - h0, p1 - h1);
        }
    }
}

/* ---------------- xvmma (single p = 3, ctx) -------------------- */
#define XV_ABYT 13824
#define XV_BBYT 4608
#define XV_STGB (2*XV_ABYT + 2*XV_BBYT)
#define XV_SMEM (2*XV_STGB)

__device__ __forceinline__ void xv_load_stage(uint32_t sb, int buf, int k0,
                                              int b, int mt, int tid, int p)
{
    uint32_t base = sb + buf*XV_STGB;
    size_t vboff = (size_t)p*BB*32*DIM;
    #pragma unroll
    for (int i = 0; i < 11; i++) {
        int c = tid + 192*i;
        if (c >= 2048) break;
        if (c < 1536) {
            int mat = (c >= 768);
            int cc = c - (mat ? 768 : 0);
            int row = cc >> 3, col8 = (cc & 7)*8;
            int t = mt*96 + row;
            int ok = t < SEQ;
            const __nv_bfloat16* src = (mat ? g_xl : g_xh) +
                ((size_t)b*SEQ + (ok ? t : 0))*DIM + k0 + col8;
            cp16(base + mat*XV_ABYT + (uint32_t)(row*72 + col8)*2, src, ok ? 16 : 0);
        } else {
            int c2 = c - 1536;
            int mat = c2 >> 8;
            int cc = c2 & 255;
            int row = cc >> 3, col8 = (cc & 7)*8;
            const __nv_bfloat16* src = (mat ? g_vbl : g_vbh) + vboff +
                ((size_t)b*32 + row)*DIM + k0 + col8;
            cp16(base + 2*XV_ABYT + mat*XV_BBYT + (uint32_t)(row*72 + col8)*2, src, 16);
        }
    }
}

__global__ void __launch_bounds__(192, 1) xvmma_kernel(int p)
{
    extern __shared__ __align__(16) char xsm[];
    uint32_t sb = smem_u32(xsm);
    int tid = threadIdx.x, lane = tid & 31, w = tid >> 5;
    int mt = blockIdx.x, b = blockIdx.y;

    float acc[4][4];
    #pragma unroll
    for (int j = 0; j < 4; j++)
        #pragma unroll
        for (int q = 0; q < 4; q++) acc[j][q] = 0.f;

    uint32_t aRow = (uint32_t)(w*16 + (lane & 15));
    uint32_t aCol = (uint32_t)((lane >> 4)*8);
    uint32_t bRow = (uint32_t)((lane & 7) + ((lane >> 4) << 3));
    uint32_t bCol = (uint32_t)(((lane >> 3) & 1)*8);

    xv_load_stage(sb, 0, 0, b, mt, tid, p);
    CP_COMMIT();

    for (int s = 0; s < 16; s++) {
        CP_WAIT0();
        __syncthreads();
        if (s + 1 < 16) {
            xv_load_stage(sb, (s+1)&1, (s+1)*64, b, mt, tid, p);
            CP_COMMIT();
        }
        uint32_t stg = sb + (s&1)*XV_STGB;
        #pragma unroll
        for (int kt = 0; kt < 4; kt++) {
            uint32_t ah[4], al[4], bh2[8], bl2[8];
            uint32_t off = (aRow*72 + kt*16 + aCol)*2;
            ldsm_x4(ah[0], ah[1], ah[2], ah[3], stg + off);
            ldsm_x4(al[0], al[1], al[2], al[3], stg + XV_ABYT + off);
            #pragma unroll
            for (int g = 0; g < 2; g++) {
                uint32_t bo = ((bRow + g*16)*72 + kt*16 + bCol)*2;
                ldsm_x4(bh2[g*4+0], bh2[g*4+1], bh2[g*4+2], bh2[g*4+3],
                        stg + 2*XV_ABYT + bo);
                ldsm_x4(bl2[g*4+0], bl2[g*4+1], bl2[g*4+2], bl2[g*4+3],
                        stg + 2*XV_ABYT + XV_BBYT + bo);
            }
            #pragma unroll
            for (int j = 0; j < 4; j++) {
                mma_bf16(acc[j], ah, bh2[j*2], bh2[j*2+1]);
                mma_bf16(acc[j], ah, bl2[j*2], bl2[j*2+1]);
                mma_bf16(acc[j], al, bh2[j*2], bh2[j*2+1]);
            }
        }
    }

    size_t xvoff = (size_t)p*BB*SEQP*32;
    int r0 = mt*96 + w*16 + (lane >> 2);
    int r1 = r0 + 8;
    #pragma unroll
    for (int j = 0; j < 4; j++) {
        int col = j*8 + (lane & 3)*2;
        if (r0 < SEQ) {
            float p0 = acc[j][0], p1 = acc[j][1];
            float h0 = __bfloat162float(__float2bfloat16(p0));
            float h1 = __bfloat162float(__float2bfloat16(p1));
            size_t o = xvoff + ((size_t)b*SEQP + r0)*32 + col;
            *(uint32_t*)(g_xvh + o) = pack_bf2(h0, h1);
            *(uint32_t*)(g_xvl + o) = pack_bf2(p0 - h0, p1 - h1);
        }
        if (r1 < SEQ) {
            float p0 = acc[j][2], p1 = acc[j][3];
            float h0 = __bfloat162float(__float2bfloat16(p0));
            float h1 = __bfloat162float(__float2bfloat16(p1));
            size_t o = xvoff + ((size_t)b*SEQP + r1)*32 + col;
            *(uint32_t*)(g_xvh + o) = pack_bf2(h0, h1);
            *(uint32_t*)(g_xvl + o) = pack_bf2(p0 - h0, p1 - h1);
        }
    }
}

/* ---------------- fused flash attention (KV chunk = 32, 9 chunks) --------- */
#define FA_QBYTES  13824
#define FA_MATB    4608
#define FA_STGB    (4*FA_MATB)
#define FA_KVBASE  (2*FA_QBYTES)
#define FA_SMEM    (FA_KVBASE + 2*FA_STGB)
#define FA_NC      9

__device__ __forceinline__ void fa_load_kv(uint32_t sb, int buf, int t0,
                                           int bh, int tid)
{
    uint32_t base = sb + FA_KVBASE + buf*FA_STGB;
    size_t goff = (size_t)bh*SEQP*HD + (size_t)t0*HD;
    const __nv_bfloat16* srcs[4] = {g_akh + goff, g_akl + goff, g_avh + goff, g_avl + goff};
    #pragma unroll
    for (int i = 0; i < 6; i++) {
        int c = tid + 192*i;
        if (c < 1024) {
            int mat = c >> 8, cc = c & 255;
            int row = cc >> 3, col8 = (cc & 7)*8;
            cp16(base + mat*FA_MATB + (uint32_t)(row*72 + col8)*2,
                 srcs[mat] + (size_t)row*HD + col8, 16);
        }
    }
}

__global__ void __launch_bounds__(192, 3) fa_kernel()
{
    extern __shared__ __align__(16) char fsm[];
    uint32_t sb = smem_u32(fsm);
    int tid = threadIdx.x, lane = tid & 31, w = tid >> 5;
    int mt = blockIdx.x, bh = blockIdx.y;
    int b = bh >> 4, hh = bh & 15;

    {
        const __nv_bfloat16* qs[2] = {g_aqh, g_aql};
        #pragma unroll
        for (int mat = 0; mat < 2; mat++) {
            const __nv_bfloat16* src = qs[mat] + ((size_t)bh*SEQP + mt*96)*HD;
            #pragma unroll
            for (int it = 0; it < 4; it++) {
                int c = tid + 192*it;
                int row = c >> 3, col8 = (c & 7)*8;
                uint4 v = *(const uint4*)(src + (size_t)row*HD + col8);
                *(uint4*)(fsm + mat*FA_QBYTES + (row*72 + col8)*2) = v;
            }
        }
    }
    fa_load_kv(sb, 0, 0, bh, tid);
    CP_COMMIT();
    __syncthreads();

    uint32_t qh[4][4], ql[4][4];
    {
        uint32_t aRow = (uint32_t)(w*16 + (lane & 15));
        uint32_t aCol = (uint32_t)((lane >> 4)*8);
        #pragma unroll
        for (int kt = 0; kt < 4; kt++) {
            uint32_t off = (aRow*72 + kt*16 + aCol)*2;
            ldsm_x4(qh[kt][0], qh[kt][1], qh[kt][2], qh[kt][3], sb + off);
            ldsm_x4(ql[kt][0], ql[kt][1], ql[kt][2], ql[kt][3], sb + FA_QBYTES + off);
        }
    }

    float o[8][4];
    #pragma unroll
    for (int j = 0; j < 8; j++)
        #pragma unroll
        for (int q = 0; q < 4; q++) o[j][q] = 0.f;
    float mr0 = -1e30f, mr1 = -1e30f, l0 = 0.f, l1 = 0.f;

    uint32_t kRow = (uint32_t)((lane & 7) + ((lane >> 4) << 3));
    uint32_t kCol = (uint32_t)(((lane >> 3) & 1)*8);
    uint32_t vRow = (uint32_t)(lane & 15);
    uint32_t vCol = (uint32_t)((lane >> 4) << 3);

    for (int c = 0; c < FA_NC; c++) {
        CP_WAIT0();
        __syncthreads();
        if (c + 1 < FA_NC) {
            fa_load_kv(sb, (c+1)&1, (c+1)*32, bh, tid);
            CP_COMMIT();
        }
        uint32_t stg = sb + FA_KVBASE + (c&1)*FA_STGB;

        float S[4][4];
        #pragma unroll
        for (int j = 0; j < 4; j++)
            #pragma unroll
            for (int q = 0; q < 4; q++) S[j][q] = 0.f;

        #pragma unroll
        for (int kt = 0; kt < 4; kt++) {
            #pragma unroll
            for (int g = 0; g < 2; g++) {
                uint32_t off = ((kRow + g*16)*72 + kt*16 + kCol)*2;
                uint32_t h0,h1,h2,h3, e0,e1,e2,e3;
                ldsm_x4(h0,h1,h2,h3, stg + 0*FA_MATB + off);
                ldsm_x4(e0,e1,e2,e3, stg + 1*FA_MATB + off);
                mma_bf16(S[2*g],   qh[kt], h0, h1);
                mma_bf16(S[2*g],   qh[kt], e0, e1);
                mma_bf16(S[2*g],   ql[kt], h0, h1);
                mma_bf16(S[2*g+1], qh[kt], h2, h3);
                mma_bf16(S[2*g+1], qh[kt], e2, e3);
                mma_bf16(S[2*g+1], ql[kt], h2, h3);
            }
        }

        if (c == FA_NC - 1) {
            #pragma unroll
            for (int j = 0; j < 4; j++) {
                int tb = (FA_NC-1)*32 + j*8 + (lane & 3)*2;
                if (tb     >= SEQ) { S[j][0] = -1e30f; S[j][2] = -1e30f; }
                if (tb + 1 >= SEQ) { S[j][1] = -1e30f; S[j][3] = -1e30f; }
            }
        }

        float mx0 = -1e30f, mx1 = -1e30f;
        #pragma unroll
        for (int j = 0; j < 4; j++) {
            mx0 = fmaxf(mx0, fmaxf(S[j][0], S[j][1]));
            mx1 = fmaxf(mx1, fmaxf(S[j][2], S[j][3]));
        }
        mx0 = fmaxf(mx0, __shfl_xor_sync(0xffffffffu, mx0, 1));
        mx0 = fmaxf(mx0, __shfl_xor_sync(0xffffffffu, mx0, 2));
        mx1 = fmaxf(mx1, __shfl_xor_sync(0xffffffffu, mx1, 1));
        mx1 = fmaxf(mx1, __shfl_xor_sync(0xffffffffu, mx1, 2));
        float mn0 = fmaxf(mr0, mx0), mn1 = fmaxf(mr1, mx1);
        float sc0 = expf(mr0 - mn0), sc1 = expf(mr1 - mn1);
        mr0 = mn0; mr1 = mn1;

        uint32_t ph[2][4], pl[2][4];
        float rs0 = 0.f, rs1 = 0.f;
        #pragma unroll
        for (int j = 0; j < 4; j++) {
            float p0 = expf(S[j][0] - mn0), p1 = expf(S[j][1] - mn0);
            float p2 = expf(S[j][2] - mn1), p3 = expf(S[j][3] - mn1);
            rs0 += p0 + p1; rs1 += p2 + p3;
            float h0 = __bfloat162float(__float2bfloat16(p0));
            float h1 = __bfloat162float(__float2bfloat16(p1));
            float h2 = __bfloat162float(__float2bfloat16(p2));
            float h3 = __bfloat162float(__float2bfloat16(p3));
            int kt2 = j >> 1, hb = (j & 1)*2;
            ph[kt2][hb]   = pack_bf2(h0, h1);
            ph[kt2][hb+1] = pack_bf2(h2, h3);
            pl[kt2][hb]   = pack_bf2(p0 - h0, p1 - h1);
            pl[kt2][hb+1] = pack_bf2(p2 - h2, p3 - h3);
        }
        rs0 += __shfl_xor_sync(0xffffffffu, rs0, 1);
        rs0 += __shfl_xor_sync(0xffffffffu, rs0, 2);
        rs1 += __shfl_xor_sync(0xffffffffu, rs1, 1);
        rs1 += __shfl_xor_sync(0xffffffffu, rs1, 2);
        l0 = l0*sc0 + rs0;
        l1 = l1*sc1 + rs1;

        #pragma unroll
        for (int j = 0; j < 8; j++) {
            o[j][0] *= sc0; o[j][1] *= sc0;
            o[j][2] *= sc1; o[j][3] *= sc1;
        }

        #pragma unroll
        for (int kt2 = 0; kt2 < 2; kt2++) {
            #pragma unroll
            for (int g = 0; g < 4; g++) {
                uint32_t off = ((kt2*16 + vRow)*72 + g*16 + vCol)*2;
                uint32_t h0,h1,h2,h3, e0,e1,e2,e3;
                ldsm_x4_t(h0,h1,h2,h3, stg + 2*FA_MATB + off);
                ldsm_x4_t(e0,e1,e2,e3, stg + 3*FA_MATB + off);
                mma_bf16(o[2*g],   ph[kt2], h0, h1);
                mma_bf16(o[2*g],   ph[kt2], e0, e1);
                mma_bf16(o[2*g],   pl[kt2], h0, h1);
                mma_bf16(o[2*g+1], ph[kt2], h2, h3);
                mma_bf16(o[2*g+1], ph[kt2], e2, e3);
                mma_bf16(o[2*g+1], pl[kt2], h2, h3);
            }
        }
    }

    float inv0 = 1.f/l0, inv1 = 1.f/l1;
    int r0 = mt*96 + w*16 + (lane >> 2);
    int r1 = r0 + 8;
    #pragma unroll
    for (int j = 0; j < 8; j++) {
        int d = hh*HD + j*8 + (lane & 3)*2;
        if (r0 < SEQ) {
            float v0 = o[j][0]*inv0, v1 = o[j][1]*inv0;
            float h0 = __bfloat162float(__float2bfloat16(v0));
            float h1 = __bfloat162float(__float2bfloat16(v1));
            size_t off = (size_t)(b*SEQ + r0)*DIM + d;
            *(uint32_t*)(g_xh + off) = pack_bf2(h0, h1);
            *(uint32_t*)(g_xl + off) = pack_bf2(v0 - h0, v1 - h1);
        }
        if (r1 < SEQ) {
            float v0 = o[j][2]*inv1, v1 = o[j][3]*inv1;
            float h0 = __bfloat162float(__float2bfloat16(v0));
            float h1 = __bfloat162float(__float2bfloat16(v1));
            size_t off = (size_t)(b*SEQ + r1)*DIM + d;
            *(uint32_t*)(g_xh + off) = pack_bf2(h0, h1);
            *(uint32_t*)(g_xl + off) = pack_bf2(v0 - h0, v1 - h1);
        }
    }
}

/* ---------------- launch ---------------- */
extern "C" void kernel_launch(void* const* d_in, const int* in_sizes, int n_in,
                              void* d_out, int out_size)
{
    const float* x   = (const float*)d_in[0];
    const float* gw1 = (const float*)d_in[1];
    const float* gb1 = (const float*)d_in[2];
    const float* gw2 = (const float*)d_in[3];
    const float* gb2 = (const float*)d_in[4];
    const float* Wm[4] = {(const float*)d_in[5],  (const float*)d_in[10],
                          (const float*)d_in[15], (const float*)d_in[20]};
    const float* Uu[4] = {(const float*)d_in[6],  (const float*)d_in[11],
                          (const float*)d_in[16], (const float*)d_in[21]};
    const float* Ss[4] = {(const float*)d_in[7],  (const float*)d_in[12],
                          (const float*)d_in[17], (const float*)d_in[22]};
    const float* Vv[4] = {(const float*)d_in[8],  (const float*)d_in[13],
                          (const float*)d_in[18], (const float*)d_in[23]};
    const float* bbv[4] = {(const float*)d_in[9],  (const float*)d_in[14],
                           (const float*)d_in[19], (const float*)d_in[24]};
    float* out = (float*)d_out;

    cudaFuncSetAttribute(mm_kernel, cudaFuncAttributeMaxDynamicSharedMemorySize, MM_SMEM);
    cudaFuncSetAttribute(fa_kernel, cudaFuncAttributeMaxDynamicSharedMemorySize, FA_SMEM);
    cudaFuncSetAttribute(xvmma_kernel, cudaFuncAttributeMaxDynamicSharedMemorySize, XV_SMEM);
    cudaFuncSetAttribute(xvmma_qkv_kernel, cudaFuncAttributeMaxDynamicSharedMemorySize, X3_SMEM);

    pool_kernel<<<dim3(BB, 8), 128>>>(x);
    gating_mlp_kernel<<<BB, GHID>>>(gw1, gb1, gw2, gb2);

    int nx4 = BSQ*DIM/4;
    int nw4 = DIM*DIM/4;
    convx_kernel<<<(nx4 + 255)/256, 256>>>(x, nx4);
    convw_kernel<<<dim3((nw4 + 255)/256, 4), 256>>>(Wm[0], Wm[1], Wm[2], Wm[3]);

    vconv_kernel<<<dim3(BB, 32, 4), 256>>>(Vv[0], Vv[1], Vv[2], Vv[3],
                                           Ss[0], Ss[1], Ss[2], Ss[3]);
    uconv_kernel<<<dim3(BB, 4, 4), 256>>>(Uu[0], Uu[1], Uu[2], Uu[3]);

    xvmma_qkv_kernel<<<dim3(3, BB), 192, X3_SMEM>>>();

    dim3 gmm(8, 65, 3);
    mm_kernel<<<gmm, 256, MM_SMEM>>>(-1, bbv[0], bbv[1], bbv[2], nullptr);

    fa_kernel<<<dim3(3, BB*NH), 192, FA_SMEM>>>();

    xvmma_kernel<<<dim3(3, BB), 192, XV_SMEM>>>(3);
    mm_kernel<<<dim3(8, 65, 1), 256, MM_SMEM>>>(3, bbv[3], bbv[3], bbv[3], out);
}

// round 14
// speedup vs baseline: 1.0317x; 1.0081x over previous
#include <cuda_runtime.h>
#include <cuda_bf16.h>
#include <cstdint>
#include <math.h>

#define BB   32
#define SEQ  257
#define SEQP 320
#define DIM  1024
#define NH   16
#define HD   64
#define NEXP 8
#define RNK  16
#define GHID 256
#define BSQ  (BB*SEQ)          /* 8224 tokens */
#define QSCALE 0.125f

/* ---------------- scratch (device globals; no allocations) ---------------- */
static __device__ float g_pooled[BB*DIM];
static __device__ float g_gates[BB*2];
static __device__ int   g_idx  [BB*2];
static __device__ __align__(16) __nv_bfloat16 g_xh[(size_t)BSQ*DIM];
static __device__ __align__(16) __nv_bfloat16 g_xl[(size_t)BSQ*DIM];
static __device__ __align__(16) __nv_bfloat16 g_wh[(size_t)4*DIM*DIM];
static __device__ __align__(16) __nv_bfloat16 g_wl[(size_t)4*DIM*DIM];
static __device__ __align__(16) __nv_bfloat16 g_vbh[(size_t)4*BB*32*DIM];
static __device__ __align__(16) __nv_bfloat16 g_vbl[(size_t)4*BB*32*DIM];
static __device__ __align__(16) __nv_bfloat16 g_ubh[(size_t)4*BB*DIM*32];
static __device__ __align__(16) __nv_bfloat16 g_ubl[(size_t)4*BB*DIM*32];
static __device__ __align__(16) __nv_bfloat16 g_xvh[(size_t)4*BB*SEQP*32];
static __device__ __align__(16) __nv_bfloat16 g_xvl[(size_t)4*BB*SEQP*32];
static __device__ __align__(16) __nv_bfloat16 g_aqh[(size_t)BB*NH*SEQP*HD];
static __device__ __align__(16) __nv_bfloat16 g_aql[(size_t)BB*NH*SEQP*HD];
static __device__ __align__(16) __nv_bfloat16 g_akh[(size_t)BB*NH*SEQP*HD];
static __device__ __align__(16) __nv_bfloat16 g_akl[(size_t)BB*NH*SEQP*HD];
static __device__ __align__(16) __nv_bfloat16 g_avh[(size_t)BB*NH*SEQP*HD];
static __device__ __align__(16) __nv_bfloat16 g_avl[(size_t)BB*NH*SEQP*HD];

/* ---------------- small PTX helpers ---------------- */
__device__ __forceinline__ uint32_t smem_u32(const void* p) {
    uint32_t a;
    asm("{ .reg .u64 t; cvta.to.shared.u64 t, %1; cvt.u32.u64 %0, t; }" : "=r"(a) : "l"(p));
    return a;
}
__device__ __forceinline__ void cp16(uint32_t dst, const void* src, int srcBytes) {
    asm volatile("cp.async.cg.shared.global [%0], [%1], 16, %2;"
                 :: "r"(dst), "l"(src), "r"(srcBytes) : "memory");
}
#define CP_COMMIT() asm volatile("cp.async.commit_group;" ::: "memory")
#define CP_WAIT0()  asm volatile("cp.async.wait_group 0;" ::: "memory")

__device__ __forceinline__ void ldsm_x4(uint32_t& r0, uint32_t& r1, uint32_t& r2, uint32_t& r3,
                                        uint32_t addr) {
    asm volatile("ldmatrix.sync.aligned.m8n8.x4.shared.b16 {%0,%1,%2,%3}, [%4];"
                 : "=r"(r0), "=r"(r1), "=r"(r2), "=r"(r3) : "r"(addr));
}
__device__ __forceinline__ void ldsm_x4_t(uint32_t& r0, uint32_t& r1, uint32_t& r2, uint32_t& r3,
                                          uint32_t addr) {
    asm volatile("ldmatrix.sync.aligned.m8n8.x4.trans.shared.b16 {%0,%1,%2,%3}, [%4];"
                 : "=r"(r0), "=r"(r1), "=r"(r2), "=r"(r3) : "r"(addr));
}
__device__ __forceinline__ void mma_bf16(float* c, const uint32_t* a, uint32_t b0, uint32_t b1) {
    asm volatile("mma.sync.aligned.m16n8k16.row.col.f32.bf16.bf16.f32 "
                 "{%0,%1,%2,%3}, {%4,%5,%6,%7}, {%8,%9}, {%0,%1,%2,%3};"
                 : "+f"(c[0]), "+f"(c[1]), "+f"(c[2]), "+f"(c[3])
                 : "r"(a[0]), "r"(a[1]), "r"(a[2]), "r"(a[3]), "r"(b0), "r"(b1));
}
__device__ __forceinline__ uint32_t pack_bf2(float lo, float hi) {
    __nv_bfloat16 l = __float2bfloat16(lo), h = __float2bfloat16(hi);
    return ((uint32_t)__bfloat16_as_ushort(h) << 16) | (uint32_t)__bfloat16_as_ushort(l);
}

/* ---------------- pooling (parallel) + gating MLP ---------------- */
__global__ void pool_kernel(const float* __restrict__ x)
{
    int b = blockIdx.x;
    int d = blockIdx.y*128 + threadIdx.x;
    const float* xp = x + (size_t)b*SEQ*DIM + d;
    float s = 0.f;
    #pragma unroll 4
    for (int t = 0; t < SEQ; t++) s += xp[(size_t)t*DIM];
    g_pooled[b*DIM + d] = s * (1.0f/SEQ);
}

__global__ void gating_mlp_kernel(const float* __restrict__ gw1, const float* __restrict__ gb1,
                                  const float* __restrict__ gw2, const float* __restrict__ gb2)
{
    int b = blockIdx.x;
    __shared__ float h[GHID];
    __shared__ float logits[NEXP];
    int tid = threadIdx.x;
    const float* pooled = g_pooled + b*DIM;
    {
        float a = gb1[tid];
        const float* w = gw1 + (size_t)tid*DIM;
        #pragma unroll 4
        for (int d = 0; d < DIM; d++) a += pooled[d]*w[d];
        h[tid] = fmaxf(a, 0.f);
    }
    __syncthreads();
    if (tid < NEXP) {
        float a = gb2[tid];
        const float* w = gw2 + tid*GHID;
        for (int d = 0; d < GHID; d++) a += h[d]*w[d];
        logits[tid] = a;
    }
    __syncthreads();
    if (tid == 0) {
        int i0 = 0;
        for (int e = 1; e < NEXP; e++) if (logits[e] > logits[i0]) i0 = e;
        int i1 = -1;
        for (int e = 0; e < NEXP; e++) {
            if (e == i0) continue;
            if (i1 < 0 || logits[e] > logits[i1]) i1 = e;
        }
        float v0 = logits[i0], v1 = logits[i1];
        float e0 = expf(v0 - v0), e1 = expf(v1 - v0);
        float inv = 1.f/(e0 + e1);
        g_gates[b*2]   = e0*inv;
        g_gates[b*2+1] = e1*inv;
        g_idx[b*2]   = i0;
        g_idx[b*2+1] = i1;
    }
}

/* ---------------- fp32 -> (bf16 hi, bf16 lo) ---------------- */
__device__ __forceinline__ void split4(float4 v, ushort4& hh, ushort4& ll)
{
    __nv_bfloat16 t;
    t = __float2bfloat16(v.x); hh.x = __bfloat16_as_ushort(t);
    ll.x = __bfloat16_as_ushort(__float2bfloat16(v.x - __bfloat162float(t)));
    t = __float2bfloat16(v.y); hh.y = __bfloat16_as_ushort(t);
    ll.y = __bfloat16_as_ushort(__float2bfloat16(v.y - __bfloat162float(t)));
    t = __float2bfloat16(v.z); hh.z = __bfloat16_as_ushort(t);
    ll.z = __bfloat16_as_ushort(__float2bfloat16(v.z - __bfloat162float(t)));
    t = __float2bfloat16(v.w); hh.w = __bfloat16_as_ushort(t);
    ll.w = __bfloat16_as_ushort(__float2bfloat16(v.w - __bfloat162float(t)));
}

__global__ void convx_kernel(const float* __restrict__ s, int n4)
{
    int i = blockIdx.x*256 + threadIdx.x;
    if (i >= n4) return;
    ushort4 hh, ll;
    split4(((const float4*)s)[i], hh, ll);
    ((ushort4*)g_xh)[i] = hh;
    ((ushort4*)g_xl)[i] = ll;
}

__global__ void convw_kernel(const float* __restrict__ w0, const float* __restrict__ w1,
                             const float* __restrict__ w2, const float* __restrict__ w3)
{
    int p = blockIdx.y;
    const float* s = (p==0)?w0:(p==1)?w1:(p==2)?w2:w3;
    int i = blockIdx.x*256 + threadIdx.x;
    ushort4 hh, ll;
    split4(((const float4*)s)[i], hh, ll);
    size_t o = (size_t)p*(DIM*DIM/4) + i;
    ((ushort4*)g_wh)[o] = hh;
    ((ushort4*)g_wl)[o] = ll;
}

/* ---------------- vuconv: gather+scale V rows AND U cols (merged) --------- */
/* grid (BB, 36, 4): y<32 -> V row y ; y>=32 -> U chunk (y-32)               */
__global__ void vuconv_kernel(const float* __restrict__ V0, const float* __restrict__ V1,
                              const float* __restrict__ V2, const float* __restrict__ V3,
                              const float* __restrict__ S0, const float* __restrict__ S1,
                              const float* __restrict__ S2, const float* __restrict__ S3,
                              const float* __restrict__ U0, const float* __restrict__ U1,
                              const float* __restrict__ U2, const float* __restrict__ U3)
{
    int b = blockIdx.x, y = blockIdx.y, p = blockIdx.z;
    if (y < 32) {
        const float* Vm = (p==0)?V0:(p==1)?V1:(p==2)?V2:V3;
        const float* Sm = (p==0)?S0:(p==1)?S1:(p==2)?S2:S3;
        int j = y;
        int half = j >> 4, r = j & 15;
        int e = g_idx[b*2 + half];
        float sc = g_gates[b*2 + half] * Sm[e*RNK + r];
        float4 v = ((const float4*)(Vm + ((size_t)e*RNK + r)*DIM))[threadIdx.x];
        v.x *= sc; v.y *= sc; v.z *= sc; v.w *= sc;
        ushort4 hh, ll;
        split4(v, hh, ll);
        size_t o = ((size_t)p*BB*32 + (size_t)b*32 + j)*DIM/4 + threadIdx.x;
        ((ushort4*)g_vbh)[o] = hh;
        ((ushort4*)g_vbl)[o] = ll;
    } else {
        const float* U = (p==0)?U0:(p==1)?U1:(p==2)?U2:U3;
        int n = (y - 32)*256 + threadIdx.x;
        int i0 = g_idx[b*2], i1 = g_idx[b*2+1];
        const float* u0 = U + ((size_t)i0*DIM + n)*RNK;
        const float* u1 = U + ((size_t)i1*DIM + n)*RNK;
        __nv_bfloat16* H = g_ubh + ((size_t)p*BB*DIM + (size_t)b*DIM + n)*32;
        __nv_bfloat16* L = g_ubl + ((size_t)p*BB*DIM + (size_t)b*DIM + n)*32;
        #pragma unroll
        for (int r = 0; r < 16; r++) {
            float v0 = u0[r], v1 = u1[r];
            __nv_bfloat16 h0 = __float2bfloat16(v0);
            H[r]      = h0;
            L[r]      = __float2bfloat16(v0 - __bfloat162float(h0));
            __nv_bfloat16 h1 = __float2bfloat16(v1);
            H[16 + r] = h1;
            L[16 + r] = __float2bfloat16(v1 - __bfloat162float(h1));
        }
    }
}

/* ---------------- fused GEMM: Y = (X@W^T + bias + xv@Ub^T) * scale -------- */
/* 2-stage, BK=32; single __syncthreads per stage: wait -> sync -> load -> compute */
#define MAT_BYTES (128*40*2)            /* 10240 */
#define STG_BYTES (4*MAT_BYTES)         /* 40960 */
#define MM_SMEM   (2*STG_BYTES)         /* 81920 */

__device__ __forceinline__ void mm_load_stage(uint32_t sb, int buf, int k0,
    const __nv_bfloat16* Ah, const __nv_bfloat16* Al,
    const __nv_bfloat16* Bh, const __nv_bfloat16* Bl,
    int m0, int n0, int tid)
{
    uint32_t base = sb + buf*STG_BYTES;
    const __nv_bfloat16* srcs[4] = {Ah, Al, Bh, Bl};
    #pragma unroll
    for (int i = 0; i < 8; i++) {
        int c = tid + 256*i;
        int mat = c >> 9;
        int cc  = c & 511;
        int row = cc >> 2;
        int col = (cc & 3) * 8;
        const __nv_bfloat16* p = srcs[mat];
        int grow = ((mat < 2) ? m0 : n0) + row;
        int ok = (mat >= 2) || (grow < BSQ);
        const void* src = p + ((size_t)(ok ? grow : 0))*DIM + k0 + col;
        uint32_t dst = base + mat*MAT_BYTES + (uint32_t)(row*40 + col)*2;
        cp16(dst, src, ok ? 16 : 0);
    }
}

__global__ void __launch_bounds__(256, 2) mm_kernel(int base_code,
    const float* __restrict__ bias0, const float* __restrict__ bias1,
    const float* __restrict__ bias2, float* __restrict__ Yext)
{
    extern __shared__ __align__(128) char smem[];
    int code = (base_code < 0) ? (int)blockIdx.z : base_code;
    const __nv_bfloat16* Ah = g_xh;
    const __nv_bfloat16* Al = g_xl;
    const __nv_bfloat16* Bh = g_wh + (size_t)code*DIM*DIM;
    const __nv_bfloat16* Bl = g_wl + (size_t)code*DIM*DIM;
    const float* bias = (code==0)?bias0:(code==1)?bias1:(code==2)?bias2:bias0;

    uint32_t sb = smem_u32(smem);
    int tid = threadIdx.x;
    int lane = tid & 31;
    int wid = tid >> 5;
    int warp_m = wid >> 2;
    int warp_n = wid & 3;
    int n0 = blockIdx.x*128, m0 = blockIdx.y*128;

    float acc[4][4][4];
    #pragma unroll
    for (int i = 0; i < 4; i++)
        #pragma unroll
        for (int j = 0; j < 4; j++)
            #pragma unroll
            for (int q = 0; q < 4; q++) acc[i][j][q] = 0.f;

    uint32_t aRow = (uint32_t)(warp_m*64 + (lane & 15));
    uint32_t aCol = (uint32_t)((lane >> 4) * 8);
    uint32_t bRowBase = (uint32_t)(warp_n*32 + (lane & 7) + ((lane >> 4) << 3));
    uint32_t bCol = (uint32_t)(((lane >> 3) & 1) * 8);

    mm_load_stage(sb, 0, 0, Ah, Al, Bh, Bl, m0, n0, tid);
    CP_COMMIT();

    const int NK = DIM/32;
    for (int s = 0; s < NK; s++) {
        CP_WAIT0();
        __syncthreads();
        if (s + 1 < NK) {
            mm_load_stage(sb, (s+1)&1, (s+1)*32, Ah, Al, Bh, Bl, m0, n0, tid);
            CP_COMMIT();
        }

        uint32_t stg = sb + (s&1)*STG_BYTES;
        #pragma unroll
        for (int kk = 0; kk < 32; kk += 16) {
            uint32_t ah[4][4], al[4][4], bh[8], bl[8];
            #pragma unroll
            for (int i = 0; i < 4; i++) {
                uint32_t off = ((aRow + i*16)*40 + kk + aCol)*2;
                ldsm_x4(ah[i][0], ah[i][1], ah[i][2], ah[i][3], stg + 0*MAT_BYTES + off);
                ldsm_x4(al[i][0], al[i][1], al[i][2], al[i][3], stg + 1*MAT_BYTES + off);
            }
            #pragma unroll
            for (int g = 0; g < 2; g++) {
                uint32_t off = ((bRowBase + g*16)*40 + kk + bCol)*2;
                ldsm_x4(bh[g*4+0], bh[g*4+1], bh[g*4+2], bh[g*4+3], stg + 2*MAT_BYTES + off);
                ldsm_x4(bl[g*4+0], bl[g*4+1], bl[g*4+2], bl[g*4+3], stg + 3*MAT_BYTES + off);
            }
            #pragma unroll
            for (int i = 0; i < 4; i++) {
                #pragma unroll
                for (int j = 0; j < 4; j++) {
                    mma_bf16(acc[i][j], ah[i], bh[j*2], bh[j*2+1]);
                    mma_bf16(acc[i][j], ah[i], bl[j*2], bl[j*2+1]);
                    mma_bf16(acc[i][j], al[i], bh[j*2], bh[j*2+1]);
                }
            }
        }
    }

    /* ---- fused rank-32 MoE correction: one pass per batch in this tile ---- */
    {
        int mlast = m0 + 127; if (mlast >= BSQ) mlast = BSQ - 1;
        int bb0 = m0 / SEQ, bb1 = mlast / SEQ;
        for (int bb = bb0; bb <= bb1; bb++) {
            uint32_t base = sb + ((bb - bb0) & 1)*STG_BYTES;
            __syncthreads();
            #pragma unroll
            for (int i2 = 0; i2 < 4; i2++) {
                int c = tid + 256*i2;
                int mat = c >> 9, cc = c & 511;
                int row = cc >> 2, col = (cc & 3)*8;
                int m = m0 + row;
                int ok = (m < BSQ) && (m / SEQ == bb);
                int t = m - bb*SEQ;
                const __nv_bfloat16* srcA = (mat ? g_xvl : g_xvh) +
                    (size_t)code*BB*SEQP*32 + ((size_t)bb*SEQP + (ok ? t : 0))*32 + col;
                cp16(base + mat*MAT_BYTES + (uint32_t)(row*40 + col)*2, srcA, ok ? 16 : 0);
            }
            #pragma unroll
            for (int i2 = 0; i2 < 4; i2++) {
                int c = tid + 256*i2;
                int mat = c >> 9, cc = c & 511;
                int row = cc >> 2, col = (cc & 3)*8;
                const __nv_bfloat16* srcB = (mat ? g_ubl : g_ubh) +
                    (size_t)code*BB*DIM*32 + ((size_t)bb*DIM + n0 + row)*32 + col;
                cp16(base + (2 + mat)*MAT_BYTES + (uint32_t)(row*40 + col)*2, srcB, 16);
            }
            CP_COMMIT();
            CP_WAIT0();
            __syncthreads();
            #pragma unroll
            for (int kk = 0; kk < 32; kk += 16) {
                uint32_t ah[4][4], al[4][4], bh[8], bl[8];
                #pragma unroll
                for (int i = 0; i < 4; i++) {
                    uint32_t off = ((aRow + i*16)*40 + kk + aCol)*2;
                    ldsm_x4(ah[i][0], ah[i][1], ah[i][2], ah[i][3], base + 0*MAT_BYTES + off);
                    ldsm_x4(al[i][0], al[i][1], al[i][2], al[i][3], base + 1*MAT_BYTES + off);
                }
                #pragma unroll
                for (int g = 0; g < 2; g++) {
                    uint32_t off = ((bRowBase + g*16)*40 + kk + bCol)*2;
                    ldsm_x4(bh[g*4+0], bh[g*4+1], bh[g*4+2], bh[g*4+3], base + 2*MAT_BYTES + off);
                    ldsm_x4(bl[g*4+0], bl[g*4+1], bl[g*4+2], bl[g*4+3], base + 3*MAT_BYTES + off);
                }
                #pragma unroll
                for (int i = 0; i < 4; i++) {
                    #pragma unroll
                    for (int j = 0; j < 4; j++) {
                        mma_bf16(acc[i][j], ah[i], bh[j*2], bh[j*2+1]);
                        mma_bf16(acc[i][j], ah[i], bl[j*2], bl[j*2+1]);
                        mma_bf16(acc[i][j], al[i], bh[j*2], bh[j*2+1]);
                    }
                }
            }
        }
    }

    /* ---- epilogue ---- */
    float scale = (code == 0) ? QSCALE : 1.0f;
    __nv_bfloat16* Hd = (code==0)?g_aqh:(code==1)?g_akh:g_avh;
    __nv_bfloat16* Ld = (code==0)?g_aql:(code==1)?g_akl:g_avl;
    #pragma unroll
    for (int j = 0; j < 4; j++) {
        int col = n0 + warp_n*32 + j*8 + (lane & 3)*2;
        float b0v = bias[col], b1v = bias[col+1];
        int hh = col >> 6, d0 = col & 63;
        #pragma unroll
        for (int i = 0; i < 4; i++) {
            #pragma unroll
            for (int half = 0; half < 2; half++) {
                int m = m0 + warp_m*64 + i*16 + (lane >> 2) + half*8;
                if (m >= BSQ) continue;
                float v0 = (acc[i][j][half*2]   + b0v)*scale;
                float v1 = (acc[i][j][half*2+1] + b1v)*scale;
                if (code == 3) {
                    *(float2*)(Yext + (size_t)m*DIM + col) = make_float2(v0, v1);
                } else {
                    int b = m / SEQ;
                    int t = m - b*SEQ;
                    float h0 = __bfloat162float(__float2bfloat16(v0));
                    float h1 = __bfloat162float(__float2bfloat16(v1));
                    size_t o = ((size_t)((b*NH + hh)*SEQP) + t)*HD + d0;
                    *(uint32_t*)(Hd + o) = pack_bf2(h0, h1);
                    *(uint32_t*)(Ld + o) = pack_bf2(v0 - h0, v1 - h1);
                }
            }
        }
    }
}

/* ---------------- xvmma_qkv: xv(p=0..2) = X @ [Vb0;Vb1;Vb2]^T ------------- */
#define X3_ABYT 13824
#define X3_BBYT 13824
#define X3_STGB (2*X3_ABYT + 2*X3_BBYT)
#define X3_SMEM (2*X3_STGB)

__device__ __forceinline__ void x3_load_stage(uint32_t sb, int buf, int k0,
                                              int b, int mt, int tid)
{
    uint32_t base = sb + buf*X3_STGB;
    #pragma unroll
    for (int i = 0; i < 16; i++) {
        int c = tid + 192*i;
        if (c >= 3072) break;
        int m4 = c / 768;
        int cc2 = c - m4*768;
        int row = cc2 >> 3, col8 = (cc2 & 7)*8;
        if (m4 < 2) {
            int t = mt*96 + row;
            int ok = t < SEQ;
            const __nv_bfloat16* src = (m4 ? g_xl : g_xh) +
                ((size_t)b*SEQ + (ok ? t : 0))*DIM + k0 + col8;
            cp16(base + m4*X3_ABYT + (uint32_t)(row*72 + col8)*2, src, ok ? 16 : 0);
        } else {
            int p = row >> 5, jr = row & 31;
            const __nv_bfloat16* src = ((m4 == 3) ? g_vbl : g_vbh) +
                (size_t)p*BB*32*DIM + ((size_t)b*32 + jr)*DIM + k0 + col8;
            cp16(base + 2*X3_ABYT + (m4 - 2)*X3_BBYT + (uint32_t)(row*72 + col8)*2, src, 16);
        }
    }
}

__global__ void __launch_bounds__(192, 1) xvmma_qkv_kernel()
{
    extern __shared__ __align__(16) char xsm[];
    uint32_t sb = smem_u32(xsm);
    int tid = threadIdx.x, lane = tid & 31, w = tid >> 5;
    int mt = blockIdx.x, b = blockIdx.y;

    float acc[12][4];
    #pragma unroll
    for (int j = 0; j < 12; j++)
        #pragma unroll
        for (int q = 0; q < 4; q++) acc[j][q] = 0.f;

    uint32_t aRow = (uint32_t)(w*16 + (lane & 15));
    uint32_t aCol = (uint32_t)((lane >> 4)*8);
    uint32_t bRow = (uint32_t)((lane & 7) + ((lane >> 4) << 3));
    uint32_t bCol = (uint32_t)(((lane >> 3) & 1)*8);

    x3_load_stage(sb, 0, 0, b, mt, tid);
    CP_COMMIT();

    for (int s = 0; s < 16; s++) {
        CP_WAIT0();
        __syncthreads();
        if (s + 1 < 16) {
            x3_load_stage(sb, (s+1)&1, (s+1)*64, b, mt, tid);
            CP_COMMIT();
        }
        uint32_t stg = sb + (s&1)*X3_STGB;
        #pragma unroll
        for (int kt = 0; kt < 4; kt++) {
            uint32_t ah[4], al[4];
            uint32_t off = (aRow*72 + kt*16 + aCol)*2;
            ldsm_x4(ah[0], ah[1], ah[2], ah[3], stg + off);
            ldsm_x4(al[0], al[1], al[2], al[3], stg + X3_ABYT + off);
            #pragma unroll
            for (int g = 0; g < 6; g++) {
                uint32_t bo = ((bRow + g*16)*72 + kt*16 + bCol)*2;
                uint32_t bh[4], bl[4];
                ldsm_x4(bh[0], bh[1], bh[2], bh[3], stg + 2*X3_ABYT + bo);
                ldsm_x4(bl[0], bl[1], bl[2], bl[3], stg + 2*X3_ABYT + X3_BBYT + bo);
                #pragma unroll
                for (int r = 0; r < 2; r++) {
                    int jj = g*2 + r;
                    mma_bf16(acc[jj], ah, bh[r*2], bh[r*2+1]);
                    mma_bf16(acc[jj], ah, bl[r*2], bl[r*2+1]);
                    mma_bf16(acc[jj], al, bh[r*2], bh[r*2+1]);
                }
            }
        }
    }

    int r0 = mt*96 + w*16 + (lane >> 2);
    int r1 = r0 + 8;
    #pragma unroll
    for (int j = 0; j < 12; j++) {
        int n = j*8 + (lane & 3)*2;
        int p = n >> 5, coln = n & 31;
        size_t xvoff = (size_t)p*BB*SEQP*32;
        if (r0 < SEQ) {
            float p0 = acc[j][0], p1 = acc[j][1];
            float h0 = __bfloat162float(__float2bfloat16(p0));
            float h1 = __bfloat162float(__float2bfloat16(p1));
            size_t o = xvoff + ((size_t)b*SEQP + r0)*32 + coln;
            *(uint32_t*)(g_xvh + o) = pack_bf2(h0, h1);
            *(uint32_t*)(g_xvl + o) = pack_bf2(p0 - h0, p1 - h1);
        }
        if (r1 < SEQ) {
            float p0 = acc[j][2], p1 = acc[j][3];
            float h0 = __bfloat162float(__float2bfloat16(p0));
            float h1 = __bfloat162float(__float2bfloat16(p1));
            size_t o = xvoff + ((size_t)b*SEQP + r1)*32 + coln;
            *(uint32_t*)(g_xvh + o) = pack_bf2(h0, h1);
            *(uint32_t*)(g_xvl + o) = pack_bf2(p0 - h0, p1 - h1);
        }
    }
}

/* ---------------- xvmma (single p = 3, ctx) -------------------- */
#define XV_ABYT 13824
#define XV_BBYT 4608
#define XV_STGB (2*XV_ABYT + 2*XV_BBYT)
#define XV_SMEM (2*XV_STGB)

__device__ __forceinline__ void xv_load_stage(uint32_t sb, int buf, int k0,
                                              int b, int mt, int tid, int p)
{
    uint32_t base = sb + buf*XV_STGB;
    size_t vboff = (size_t)p*BB*32*DIM;
    #pragma unroll
    for (int i = 0; i < 11; i++) {
        int c = tid + 192*i;
        if (c >= 2048) break;
        if (c < 1536) {
            int mat = (c >= 768);
            int cc = c - (mat ? 768 : 0);
            int row = cc >> 3, col8 = (cc & 7)*8;
            int t = mt*96 + row;
            int ok = t < SEQ;
            const __nv_bfloat16* src = (mat ? g_xl : g_xh) +
                ((size_t)b*SEQ + (ok ? t : 0))*DIM + k0 + col8;
            cp16(base + mat*XV_ABYT + (uint32_t)(row*72 + col8)*2, src, ok ? 16 : 0);
        } else {
            int c2 = c - 1536;
            int mat = c2 >> 8;
            int cc = c2 & 255;
            int row = cc >> 3, col8 = (cc & 7)*8;
            const __nv_bfloat16* src = (mat ? g_vbl : g_vbh) + vboff +
                ((size_t)b*32 + row)*DIM + k0 + col8;
            cp16(base + 2*XV_ABYT + mat*XV_BBYT + (uint32_t)(row*72 + col8)*2, src, 16);
        }
    }
}

__global__ void __launch_bounds__(192, 1) xvmma_kernel(int p)
{
    extern __shared__ __align__(16) char xsm[];
    uint32_t sb = smem_u32(xsm);
    int tid = threadIdx.x, lane = tid & 31, w = tid >> 5;
    int mt = blockIdx.x, b = blockIdx.y;

    float acc[4][4];
    #pragma unroll
    for (int j = 0; j < 4; j++)
        #pragma unroll
        for (int q = 0; q < 4; q++) acc[j][q] = 0.f;

    uint32_t aRow = (uint32_t)(w*16 + (lane & 15));
    uint32_t aCol = (uint32_t)((lane >> 4)*8);
    uint32_t bRow = (uint32_t)((lane & 7) + ((lane >> 4) << 3));
    uint32_t bCol = (uint32_t)(((lane >> 3) & 1)*8);

    xv_load_stage(sb, 0, 0, b, mt, tid, p);
    CP_COMMIT();

    for (int s = 0; s < 16; s++) {
        CP_WAIT0();
        __syncthreads();
        if (s + 1 < 16) {
            xv_load_stage(sb, (s+1)&1, (s+1)*64, b, mt, tid, p);
            CP_COMMIT();
        }
        uint32_t stg = sb + (s&1)*XV_STGB;
        #pragma unroll
        for (int kt = 0; kt < 4; kt++) {
            uint32_t ah[4], al[4], bh2[8], bl2[8];
            uint32_t off = (aRow*72 + kt*16 + aCol)*2;
            ldsm_x4(ah[0], ah[1], ah[2], ah[3], stg + off);
            ldsm_x4(al[0], al[1], al[2], al[3], stg + XV_ABYT + off);
            #pragma unroll
            for (int g = 0; g < 2; g++) {
                uint32_t bo = ((bRow + g*16)*72 + kt*16 + bCol)*2;
                ldsm_x4(bh2[g*4+0], bh2[g*4+1], bh2[g*4+2], bh2[g*4+3],
                        stg + 2*XV_ABYT + bo);
                ldsm_x4(bl2[g*4+0], bl2[g*4+1], bl2[g*4+2], bl2[g*4+3],
                        stg + 2*XV_ABYT + XV_BBYT + bo);
            }
            #pragma unroll
            for (int j = 0; j < 4; j++) {
                mma_bf16(acc[j], ah, bh2[j*2], bh2[j*2+1]);
                mma_bf16(acc[j], ah, bl2[j*2], bl2[j*2+1]);
                mma_bf16(acc[j], al, bh2[j*2], bh2[j*2+1]);
            }
        }
    }

    size_t xvoff = (size_t)p*BB*SEQP*32;
    int r0 = mt*96 + w*16 + (lane >> 2);
    int r1 = r0 + 8;
    #pragma unroll
    for (int j = 0; j < 4; j++) {
        int col = j*8 + (lane & 3)*2;
        if (r0 < SEQ) {
            float p0 = acc[j][0], p1 = acc[j][1];
            float h0 = __bfloat162float(__float2bfloat16(p0));
            float h1 = __bfloat162float(__float2bfloat16(p1));
            size_t o = xvoff + ((size_t)b*SEQP + r0)*32 + col;
            *(uint32_t*)(g_xvh + o) = pack_bf2(h0, h1);
            *(uint32_t*)(g_xvl + o) = pack_bf2(p0 - h0, p1 - h1);
        }
        if (r1 < SEQ) {
            float p0 = acc[j][2], p1 = acc[j][3];
            float h0 = __bfloat162float(__float2bfloat16(p0));
            float h1 = __bfloat162float(__float2bfloat16(p1));
            size_t o = xvoff + ((size_t)b*SEQP + r1)*32 + col;
            *(uint32_t*)(g_xvh + o) = pack_bf2(h0, h1);
            *(uint32_t*)(g_xvl + o) = pack_bf2(p0 - h0, p1 - h1);
        }
    }
}

/* ---------------- fused flash attention (KV chunk = 32, 9 chunks) --------- */
#define FA_QBYTES  13824
#define FA_MATB    4608
#define FA_STGB    (4*FA_MATB)
#define FA_KVBASE  (2*FA_QBYTES)
#define FA_SMEM    (FA_KVBASE + 2*FA_STGB)
#define FA_NC      9

__device__ __forceinline__ void fa_load_kv(uint32_t sb, int buf, int t0,
                                           int bh, int tid)
{
    uint32_t base = sb + FA_KVBASE + buf*FA_STGB;
    size_t goff = (size_t)bh*SEQP*HD + (size_t)t0*HD;
    const __nv_bfloat16* srcs[4] = {g_akh + goff, g_akl + goff, g_avh + goff, g_avl + goff};
    #pragma unroll
    for (int i = 0; i < 6; i++) {
        int c = tid + 192*i;
        if (c < 1024) {
            int mat = c >> 8, cc = c & 255;
            int row = cc >> 3, col8 = (cc & 7)*8;
            cp16(base + mat*FA_MATB + (uint32_t)(row*72 + col8)*2,
                 srcs[mat] + (size_t)row*HD + col8, 16);
        }
    }
}

__global__ void __launch_bounds__(192, 2) fa_kernel()
{
    extern __shared__ __align__(16) char fsm[];
    uint32_t sb = smem_u32(fsm);
    int tid = threadIdx.x, lane = tid & 31, w = tid >> 5;
    int mt = blockIdx.x, bh = blockIdx.y;
    int b = bh >> 4, hh = bh & 15;

    {
        const __nv_bfloat16* qs[2] = {g_aqh, g_aql};
        #pragma unroll
        for (int mat = 0; mat < 2; mat++) {
            const __nv_bfloat16* src = qs[mat] + ((size_t)bh*SEQP + mt*96)*HD;
            #pragma unroll
            for (int it = 0; it < 4; it++) {
                int c = tid + 192*it;
                int row = c >> 3, col8 = (c & 7)*8;
                uint4 v = *(const uint4*)(src + (size_t)row*HD + col8);
                *(uint4*)(fsm + mat*FA_QBYTES + (row*72 + col8)*2) = v;
            }
        }
    }
    fa_load_kv(sb, 0, 0, bh, tid);
    CP_COMMIT();
    __syncthreads();

    uint32_t qh[4][4], ql[4][4];
    {
        uint32_t aRow = (uint32_t)(w*16 + (lane & 15));
        uint32_t aCol = (uint32_t)((lane >> 4)*8);
        #pragma unroll
        for (int kt = 0; kt < 4; kt++) {
            uint32_t off = (aRow*72 + kt*16 + aCol)*2;
            ldsm_x4(qh[kt][0], qh[kt][1], qh[kt][2], qh[kt][3], sb + off);
            ldsm_x4(ql[kt][0], ql[kt][1], ql[kt][2], ql[kt][3], sb + FA_QBYTES + off);
        }
    }

    float o[8][4];
    #pragma unroll
    for (int j = 0; j < 8; j++)
        #pragma unroll
        for (int q = 0; q < 4; q++) o[j][q] = 0.f;
    float mr0 = -1e30f, mr1 = -1e30f, l0 = 0.f, l1 = 0.f;

    uint32_t kRow = (uint32_t)((lane & 7) + ((lane >> 4) << 3));
    uint32_t kCol = (uint32_t)(((lane >> 3) & 1)*8);
    uint32_t vRow = (uint32_t)(lane & 15);
    uint32_t vCol = (uint32_t)((lane >> 4) << 3);

    for (int c = 0; c < FA_NC; c++) {
        CP_WAIT0();
        __syncthreads();
        if (c + 1 < FA_NC) {
            fa_load_kv(sb, (c+1)&1, (c+1)*32, bh, tid);
            CP_COMMIT();
        }
        uint32_t stg = sb + FA_KVBASE + (c&1)*FA_STGB;

        float S[4][4];
        #pragma unroll
        for (int j = 0; j < 4; j++)
            #pragma unroll
            for (int q = 0; q < 4; q++) S[j][q] = 0.f;

        #pragma unroll
        for (int kt = 0; kt < 4; kt++) {
            #pragma unroll
            for (int g = 0; g < 2; g++) {
                uint32_t off = ((kRow + g*16)*72 + kt*16 + kCol)*2;
                uint32_t h0,h1,h2,h3, e0,e1,e2,e3;
                ldsm_x4(h0,h1,h2,h3, stg + 0*FA_MATB + off);
                ldsm_x4(e0,e1,e2,e3, stg + 1*FA_MATB + off);
                mma_bf16(S[2*g],   qh[kt], h0, h1);
                mma_bf16(S[2*g],   qh[kt], e0, e1);
                mma_bf16(S[2*g],   ql[kt], h0, h1);
                mma_bf16(S[2*g+1], qh[kt], h2, h3);
                mma_bf16(S[2*g+1], qh[kt], e2, e3);
                mma_bf16(S[2*g+1], ql[kt], h2, h3);
            }
        }

        if (c == FA_NC - 1) {
            #pragma unroll
            for (int j = 0; j < 4; j++) {
                int tb = (FA_NC-1)*32 + j*8 + (lane & 3)*2;
                if (tb     >= SEQ) { S[j][0] = -1e30f; S[j][2] = -1e30f; }
                if (tb + 1 >= SEQ) { S[j][1] = -1e30f; S[j][3] = -1e30f; }
            }
        }

        float mx0 = -1e30f, mx1 = -1e30f;
        #pragma unroll
        for (int j = 0; j < 4; j++) {
            mx0 = fmaxf(mx0, fmaxf(S[j][0], S[j][1]));
            mx1 = fmaxf(mx1, fmaxf(S[j][2], S[j][3]));
        }
        mx0 = fmaxf(mx0, __shfl_xor_sync(0xffffffffu, mx0, 1));
        mx0 = fmaxf(mx0, __shfl_xor_sync(0xffffffffu, mx0, 2));
        mx1 = fmaxf(mx1, __shfl_xor_sync(0xffffffffu, mx1, 1));
        mx1 = fmaxf(mx1, __shfl_xor_sync(0xffffffffu, mx1, 2));
        float mn0 = fmaxf(mr0, mx0), mn1 = fmaxf(mr1, mx1);
        float sc0 = expf(mr0 - mn0), sc1 = expf(mr1 - mn1);
        mr0 = mn0; mr1 = mn1;

        uint32_t ph[2][4], pl[2][4];
        float rs0 = 0.f, rs1 = 0.f;
        #pragma unroll
        for (int j = 0; j < 4; j++) {
            float p0 = expf(S[j][0] - mn0), p1 = expf(S[j][1] - mn0);
            float p2 = expf(S[j][2] - mn1), p3 = expf(S[j][3] - mn1);
            rs0 += p0 + p1; rs1 += p2 + p3;
            float h0 = __bfloat162float(__float2bfloat16(p0));
            float h1 = __bfloat162float(__float2bfloat16(p1));
            float h2 = __bfloat162float(__float2bfloat16(p2));
            float h3 = __bfloat162float(__float2bfloat16(p3));
            int kt2 = j >> 1, hb = (j & 1)*2;
            ph[kt2][hb]   = pack_bf2(h0, h1);
            ph[kt2][hb+1] = pack_bf2(h2, h3);
            pl[kt2][hb]   = pack_bf2(p0 - h0, p1 - h1);
            pl[kt2][hb+1] = pack_bf2(p2 - h2, p3 - h3);
        }
        rs0 += __shfl_xor_sync(0xffffffffu, rs0, 1);
        rs0 += __shfl_xor_sync(0xffffffffu, rs0, 2);
        rs1 += __shfl_xor_sync(0xffffffffu, rs1, 1);
        rs1 += __shfl_xor_sync(0xffffffffu, rs1, 2);
        l0 = l0*sc0 + rs0;
        l1 = l1*sc1 + rs1;

        #pragma unroll
        for (int j = 0; j < 8; j++) {
            o[j][0] *= sc0; o[j][1] *= sc0;
            o[j][2] *= sc1; o[j][3] *= sc1;
        }

        #pragma unroll
        for (int kt2 = 0; kt2 < 2; kt2++) {
            #pragma unroll
            for (int g = 0; g < 4; g++) {
                uint32_t off = ((kt2*16 + vRow)*72 + g*16 + vCol)*2;
                uint32_t h0,h1,h2,h3, e0,e1,e2,e3;
                ldsm_x4_t(h0,h1,h2,h3, stg + 2*FA_MATB + off);
                ldsm_x4_t(e0,e1,e2,e3, stg + 3*FA_MATB + off);
                mma_bf16(o[2*g],   ph[kt2], h0, h1);
                mma_bf16(o[2*g],   ph[kt2], e0, e1);
                mma_bf16(o[2*g],   pl[kt2], h0, h1);
                mma_bf16(o[2*g+1], ph[kt2], h2, h3);
                mma_bf16(o[2*g+1], ph[kt2], e2, e3);
                mma_bf16(o[2*g+1], pl[kt2], h2, h3);
            }
        }
    }

    float inv0 = 1.f/l0, inv1 = 1.f/l1;
    int r0 = mt*96 + w*16 + (lane >> 2);
    int r1 = r0 + 8;
    #pragma unroll
    for (int j = 0; j < 8; j++) {
        int d = hh*HD + j*8 + (lane & 3)*2;
        if (r0 < SEQ) {
            float v0 = o[j][0]*inv0, v1 = o[j][1]*inv0;
            float h0 = __bfloat162float(__float2bfloat16(v0));
            float h1 = __bfloat162float(__float2bfloat16(v1));
            size_t off = (size_t)(b*SEQ + r0)*DIM + d;
            *(uint32_t*)(g_xh + off) = pack_bf2(h0, h1);
            *(uint32_t*)(g_xl + off) = pack_bf2(v0 - h0, v1 - h1);
        }
        if (r1 < SEQ) {
            float v0 = o[j][2]*inv1, v1 = o[j][3]*inv1;
            float h0 = __bfloat162float(__float2bfloat16(v0));
            float h1 = __bfloat162float(__float2bfloat16(v1));
            size_t off = (size_t)(b*SEQ + r1)*DIM + d;
            *(uint32_t*)(g_xh + off) = pack_bf2(h0, h1);
            *(uint32_t*)(g_xl + off) = pack_bf2(v0 - h0, v1 - h1);
        }
    }
}

/* ---------------- launch ---------------- */
extern "C" void kernel_launch(void* const* d_in, const int* in_sizes, int n_in,
                              void* d_out, int out_size)
{
    const float* x   = (const float*)d_in[0];
    const float* gw1 = (const float*)d_in[1];
    const float* gb1 = (const float*)d_in[2];
    const float* gw2 = (const float*)d_in[3];
    const float* gb2 = (const float*)d_in[4];
    const float* Wm[4] = {(const float*)d_in[5],  (const float*)d_in[10],
                          (const float*)d_in[15], (const float*)d_in[20]};
    const float* Uu[4] = {(const float*)d_in[6],  (const float*)d_in[11],
                          (const float*)d_in[16], (const float*)d_in[21]};
    const float* Ss[4] = {(const float*)d_in[7],  (const float*)d_in[12],
                          (const float*)d_in[17], (const float*)d_in[22]};
    const float* Vv[4] = {(const float*)d_in[8],  (const float*)d_in[13],
                          (const float*)d_in[18], (const float*)d_in[23]};
    const float* bbv[4] = {(const float*)d_in[9],  (const float*)d_in[14],
                           (const float*)d_in[19], (const float*)d_in[24]};
    float* out = (float*)d_out;

    cudaFuncSetAttribute(mm_kernel, cudaFuncAttributeMaxDynamicSharedMemorySize, MM_SMEM);
    cudaFuncSetAttribute(fa_kernel, cudaFuncAttributeMaxDynamicSharedMemorySize, FA_SMEM);
    cudaFuncSetAttribute(xvmma_kernel, cudaFuncAttributeMaxDynamicSharedMemorySize, XV_SMEM);
    cudaFuncSetAttribute(xvmma_qkv_kernel, cudaFuncAttributeMaxDynamicSharedMemorySize, X3_SMEM);

    pool_kernel<<<dim3(BB, 8), 128>>>(x);
    gating_mlp_kernel<<<BB, GHID>>>(gw1, gb1, gw2, gb2);

    int nx4 = BSQ*DIM/4;
    int nw4 = DIM*DIM/4;
    convx_kernel<<<(nx4 + 255)/256, 256>>>(x, nx4);
    convw_kernel<<<dim3((nw4 + 255)/256, 4), 256>>>(Wm[0], Wm[1], Wm[2], Wm[3]);

    vuconv_kernel<<<dim3(BB, 36, 4), 256>>>(Vv[0], Vv[1], Vv[2], Vv[3],
                                            Ss[0], Ss[1], Ss[2], Ss[3],
                                            Uu[0], Uu[1], Uu[2], Uu[3]);

    xvmma_qkv_kernel<<<dim3(3, BB), 192, X3_SMEM>>>();

    dim3 gmm(8, 65, 3);
    mm_kernel<<<gmm, 256, MM_SMEM>>>(-1, bbv[0], bbv[1], bbv[2], nullptr);

    fa_kernel<<<dim3(3, BB*NH), 192, FA_SMEM>>>();

    xvmma_kernel<<<dim3(3, BB), 192, XV_SMEM>>>(3);
    mm_kernel<<<dim3(8, 65, 1), 256, MM_SMEM>>>(3, bbv[3], bbv[3], bbv[3], out);
}

// round 15
// speedup vs baseline: 1.0320x; 1.0003x over previous
#include <cuda_runtime.h>
#include <cuda_bf16.h>
#include <cstdint>
#include <math.h>

#define BB   32
#define SEQ  257
#define SEQP 320
#define DIM  1024
#define NH   16
#define HD   64
#define NEXP 8
#define RNK  16
#define GHID 256
#define BSQ  (BB*SEQ)          /* 8224 tokens */
#define QSCALE 0.125f

/* ---------------- scratch (device globals; no allocations) ---------------- */
static __device__ float g_pooled[BB*DIM];
static __device__ float g_gates[BB*2];
static __device__ int   g_idx  [BB*2];
static __device__ __align__(16) __nv_bfloat16 g_xh[(size_t)BSQ*DIM];
static __device__ __align__(16) __nv_bfloat16 g_xl[(size_t)BSQ*DIM];
static __device__ __align__(16) __nv_bfloat16 g_wh[(size_t)4*DIM*DIM];
static __device__ __align__(16) __nv_bfloat16 g_wl[(size_t)4*DIM*DIM];
static __device__ __align__(16) __nv_bfloat16 g_vbh[(size_t)4*BB*32*DIM];
static __device__ __align__(16) __nv_bfloat16 g_vbl[(size_t)4*BB*32*DIM];
static __device__ __align__(16) __nv_bfloat16 g_ubh[(size_t)4*BB*DIM*32];
static __device__ __align__(16) __nv_bfloat16 g_ubl[(size_t)4*BB*DIM*32];
static __device__ __align__(16) __nv_bfloat16 g_xvh[(size_t)4*BB*SEQP*32];
static __device__ __align__(16) __nv_bfloat16 g_xvl[(size_t)4*BB*SEQP*32];
static __device__ __align__(16) __nv_bfloat16 g_aqh[(size_t)BB*NH*SEQP*HD];
static __device__ __align__(16) __nv_bfloat16 g_aql[(size_t)BB*NH*SEQP*HD];
static __device__ __align__(16) __nv_bfloat16 g_akh[(size_t)BB*NH*SEQP*HD];
static __device__ __align__(16) __nv_bfloat16 g_akl[(size_t)BB*NH*SEQP*HD];
static __device__ __align__(16) __nv_bfloat16 g_avh[(size_t)BB*NH*SEQP*HD];
static __device__ __align__(16) __nv_bfloat16 g_avl[(size_t)BB*NH*SEQP*HD];

/* ---------------- small PTX helpers ---------------- */
__device__ __forceinline__ uint32_t smem_u32(const void* p) {
    uint32_t a;
    asm("{ .reg .u64 t; cvta.to.shared.u64 t, %1; cvt.u32.u64 %0, t; }" : "=r"(a) : "l"(p));
    return a;
}
__device__ __forceinline__ void cp16(uint32_t dst, const void* src, int srcBytes) {
    asm volatile("cp.async.cg.shared.global [%0], [%1], 16, %2;"
                 :: "r"(dst), "l"(src), "r"(srcBytes) : "memory");
}
#define CP_COMMIT() asm volatile("cp.async.commit_group;" ::: "memory")
#define CP_WAIT0()  asm volatile("cp.async.wait_group 0;" ::: "memory")

__device__ __forceinline__ void ldsm_x4(uint32_t& r0, uint32_t& r1, uint32_t& r2, uint32_t& r3,
                                        uint32_t addr) {
    asm volatile("ldmatrix.sync.aligned.m8n8.x4.shared.b16 {%0,%1,%2,%3}, [%4];"
                 : "=r"(r0), "=r"(r1), "=r"(r2), "=r"(r3) : "r"(addr));
}
__device__ __forceinline__ void ldsm_x4_t(uint32_t& r0, uint32_t& r1, uint32_t& r2, uint32_t& r3,
                                          uint32_t addr) {
    asm volatile("ldmatrix.sync.aligned.m8n8.x4.trans.shared.b16 {%0,%1,%2,%3}, [%4];"
                 : "=r"(r0), "=r"(r1), "=r"(r2), "=r"(r3) : "r"(addr));
}
__device__ __forceinline__ void mma_bf16(float* c, const uint32_t* a, uint32_t b0, uint32_t b1) {
    asm volatile("mma.sync.aligned.m16n8k16.row.col.f32.bf16.bf16.f32 "
                 "{%0,%1,%2,%3}, {%4,%5,%6,%7}, {%8,%9}, {%0,%1,%2,%3};"
                 : "+f"(c[0]), "+f"(c[1]), "+f"(c[2]), "+f"(c[3])
                 : "r"(a[0]), "r"(a[1]), "r"(a[2]), "r"(a[3]), "r"(b0), "r"(b1));
}
__device__ __forceinline__ uint32_t pack_bf2(float lo, float hi) {
    __nv_bfloat16 l = __float2bfloat16(lo), h = __float2bfloat16(hi);
    return ((uint32_t)__bfloat16_as_ushort(h) << 16) | (uint32_t)__bfloat16_as_ushort(l);
}

/* ---------------- pooling (parallel) + gating MLP ---------------- */
__global__ void pool_kernel(const float* __restrict__ x)
{
    int b = blockIdx.x;
    int d = blockIdx.y*128 + threadIdx.x;
    const float* xp = x + (size_t)b*SEQ*DIM + d;
    float s = 0.f;
    #pragma unroll 4
    for (int t = 0; t < SEQ; t++) s += xp[(size_t)t*DIM];
    g_pooled[b*DIM + d] = s * (1.0f/SEQ);
}

__global__ void gating_mlp_kernel(const float* __restrict__ gw1, const float* __restrict__ gb1,
                                  const float* __restrict__ gw2, const float* __restrict__ gb2)
{
    int b = blockIdx.x;
    __shared__ float h[GHID];
    __shared__ float logits[NEXP];
    int tid = threadIdx.x;
    const float* pooled = g_pooled + b*DIM;
    {
        float a = gb1[tid];
        const float* w = gw1 + (size_t)tid*DIM;
        #pragma unroll 4
        for (int d = 0; d < DIM; d++) a += pooled[d]*w[d];
        h[tid] = fmaxf(a, 0.f);
    }
    __syncthreads();
    if (tid < NEXP) {
        float a = gb2[tid];
        const float* w = gw2 + tid*GHID;
        for (int d = 0; d < GHID; d++) a += h[d]*w[d];
        logits[tid] = a;
    }
    __syncthreads();
    if (tid == 0) {
        int i0 = 0;
        for (int e = 1; e < NEXP; e++) if (logits[e] > logits[i0]) i0 = e;
        int i1 = -1;
        for (int e = 0; e < NEXP; e++) {
            if (e == i0) continue;
            if (i1 < 0 || logits[e] > logits[i1]) i1 = e;
        }
        float v0 = logits[i0], v1 = logits[i1];
        float e0 = expf(v0 - v0), e1 = expf(v1 - v0);
        float inv = 1.f/(e0 + e1);
        g_gates[b*2]   = e0*inv;
        g_gates[b*2+1] = e1*inv;
        g_idx[b*2]   = i0;
        g_idx[b*2+1] = i1;
    }
}

/* ---------------- fp32 -> (bf16 hi, bf16 lo) ---------------- */
__device__ __forceinline__ void split4(float4 v, ushort4& hh, ushort4& ll)
{
    __nv_bfloat16 t;
    t = __float2bfloat16(v.x); hh.x = __bfloat16_as_ushort(t);
    ll.x = __bfloat16_as_ushort(__float2bfloat16(v.x - __bfloat162float(t)));
    t = __float2bfloat16(v.y); hh.y = __bfloat16_as_ushort(t);
    ll.y = __bfloat16_as_ushort(__float2bfloat16(v.y - __bfloat162float(t)));
    t = __float2bfloat16(v.z); hh.z = __bfloat16_as_ushort(t);
    ll.z = __bfloat16_as_ushort(__float2bfloat16(v.z - __bfloat162float(t)));
    t = __float2bfloat16(v.w); hh.w = __bfloat16_as_ushort(t);
    ll.w = __bfloat16_as_ushort(__float2bfloat16(v.w - __bfloat162float(t)));
}

__global__ void convx_kernel(const float* __restrict__ s, int n4)
{
    int i = blockIdx.x*256 + threadIdx.x;
    if (i >= n4) return;
    ushort4 hh, ll;
    split4(((const float4*)s)[i], hh, ll);
    ((ushort4*)g_xh)[i] = hh;
    ((ushort4*)g_xl)[i] = ll;
}

__global__ void convw_kernel(const float* __restrict__ w0, const float* __restrict__ w1,
                             const float* __restrict__ w2, const float* __restrict__ w3)
{
    int p = blockIdx.y;
    const float* s = (p==0)?w0:(p==1)?w1:(p==2)?w2:w3;
    int i = blockIdx.x*256 + threadIdx.x;
    ushort4 hh, ll;
    split4(((const float4*)s)[i], hh, ll);
    size_t o = (size_t)p*(DIM*DIM/4) + i;
    ((ushort4*)g_wh)[o] = hh;
    ((ushort4*)g_wl)[o] = ll;
}

/* ---------------- vuconv: gather+scale V rows AND U cols (merged) --------- */
__global__ void vuconv_kernel(const float* __restrict__ V0, const float* __restrict__ V1,
                              const float* __restrict__ V2, const float* __restrict__ V3,
                              const float* __restrict__ S0, const float* __restrict__ S1,
                              const float* __restrict__ S2, const float* __restrict__ S3,
                              const float* __restrict__ U0, const float* __restrict__ U1,
                              const float* __restrict__ U2, const float* __restrict__ U3)
{
    int b = blockIdx.x, y = blockIdx.y, p = blockIdx.z;
    if (y < 32) {
        const float* Vm = (p==0)?V0:(p==1)?V1:(p==2)?V2:V3;
        const float* Sm = (p==0)?S0:(p==1)?S1:(p==2)?S2:S3;
        int j = y;
        int half = j >> 4, r = j & 15;
        int e = g_idx[b*2 + half];
        float sc = g_gates[b*2 + half] * Sm[e*RNK + r];
        float4 v = ((const float4*)(Vm + ((size_t)e*RNK + r)*DIM))[threadIdx.x];
        v.x *= sc; v.y *= sc; v.z *= sc; v.w *= sc;
        ushort4 hh, ll;
        split4(v, hh, ll);
        size_t o = ((size_t)p*BB*32 + (size_t)b*32 + j)*DIM/4 + threadIdx.x;
        ((ushort4*)g_vbh)[o] = hh;
        ((ushort4*)g_vbl)[o] = ll;
    } else {
        const float* U = (p==0)?U0:(p==1)?U1:(p==2)?U2:U3;
        int n = (y - 32)*256 + threadIdx.x;
        int i0 = g_idx[b*2], i1 = g_idx[b*2+1];
        const float* u0 = U + ((size_t)i0*DIM + n)*RNK;
        const float* u1 = U + ((size_t)i1*DIM + n)*RNK;
        __nv_bfloat16* H = g_ubh + ((size_t)p*BB*DIM + (size_t)b*DIM + n)*32;
        __nv_bfloat16* L = g_ubl + ((size_t)p*BB*DIM + (size_t)b*DIM + n)*32;
        #pragma unroll
        for (int r = 0; r < 16; r++) {
            float v0 = u0[r], v1 = u1[r];
            __nv_bfloat16 h0 = __float2bfloat16(v0);
            H[r]      = h0;
            L[r]      = __float2bfloat16(v0 - __bfloat162float(h0));
            __nv_bfloat16 h1 = __float2bfloat16(v1);
            H[16 + r] = h1;
            L[16 + r] = __float2bfloat16(v1 - __bfloat162float(h1));
        }
    }
}

/* ---------------- fused GEMM: Y = (X@W^T + bias + xv@Ub^T) * scale -------- */
#define MAT_BYTES (128*40*2)            /* 10240 */
#define STG_BYTES (4*MAT_BYTES)         /* 40960 */
#define MM_SMEM   (2*STG_BYTES)         /* 81920 */

__device__ __forceinline__ void mm_load_stage(uint32_t sb, int buf, int k0,
    const __nv_bfloat16* Ah, const __nv_bfloat16* Al,
    const __nv_bfloat16* Bh, const __nv_bfloat16* Bl,
    int m0, int n0, int tid)
{
    uint32_t base = sb + buf*STG_BYTES;
    const __nv_bfloat16* srcs[4] = {Ah, Al, Bh, Bl};
    #pragma unroll
    for (int i = 0; i < 8; i++) {
        int c = tid + 256*i;
        int mat = c >> 9;
        int cc  = c & 511;
        int row = cc >> 2;
        int col = (cc & 3) * 8;
        const __nv_bfloat16* p = srcs[mat];
        int grow = ((mat < 2) ? m0 : n0) + row;
        int ok = (mat >= 2) || (grow < BSQ);
        const void* src = p + ((size_t)(ok ? grow : 0))*DIM + k0 + col;
        uint32_t dst = base + mat*MAT_BYTES + (uint32_t)(row*40 + col)*2;
        cp16(dst, src, ok ? 16 : 0);
    }
}

__global__ void __launch_bounds__(256, 2) mm_kernel(int base_code,
    const float* __restrict__ bias0, const float* __restrict__ bias1,
    const float* __restrict__ bias2, float* __restrict__ Yext)
{
    extern __shared__ __align__(128) char smem[];
    int code = (base_code < 0) ? (int)blockIdx.z : base_code;
    const __nv_bfloat16* Ah = g_xh;
    const __nv_bfloat16* Al = g_xl;
    const __nv_bfloat16* Bh = g_wh + (size_t)code*DIM*DIM;
    const __nv_bfloat16* Bl = g_wl + (size_t)code*DIM*DIM;
    const float* bias = (code==0)?bias0:(code==1)?bias1:(code==2)?bias2:bias0;

    uint32_t sb = smem_u32(smem);
    int tid = threadIdx.x;
    int lane = tid & 31;
    int wid = tid >> 5;
    int warp_m = wid >> 2;
    int warp_n = wid & 3;
    int n0 = blockIdx.x*128, m0 = blockIdx.y*128;

    float acc[4][4][4];
    #pragma unroll
    for (int i = 0; i < 4; i++)
        #pragma unroll
        for (int j = 0; j < 4; j++)
            #pragma unroll
            for (int q = 0; q < 4; q++) acc[i][j][q] = 0.f;

    uint32_t aRow = (uint32_t)(warp_m*64 + (lane & 15));
    uint32_t aCol = (uint32_t)((lane >> 4) * 8);
    uint32_t bRowBase = (uint32_t)(warp_n*32 + (lane & 7) + ((lane >> 4) << 3));
    uint32_t bCol = (uint32_t)(((lane >> 3) & 1) * 8);

    mm_load_stage(sb, 0, 0, Ah, Al, Bh, Bl, m0, n0, tid);
    CP_COMMIT();

    const int NK = DIM/32;
    for (int s = 0; s < NK; s++) {
        CP_WAIT0();
        __syncthreads();
        if (s + 1 < NK) {
            mm_load_stage(sb, (s+1)&1, (s+1)*32, Ah, Al, Bh, Bl, m0, n0, tid);
            CP_COMMIT();
        }

        uint32_t stg = sb + (s&1)*STG_BYTES;
        #pragma unroll
        for (int kk = 0; kk < 32; kk += 16) {
            uint32_t ah[4][4], al[4][4], bh[8], bl[8];
            #pragma unroll
            for (int i = 0; i < 4; i++) {
                uint32_t off = ((aRow + i*16)*40 + kk + aCol)*2;
                ldsm_x4(ah[i][0], ah[i][1], ah[i][2], ah[i][3], stg + 0*MAT_BYTES + off);
                ldsm_x4(al[i][0], al[i][1], al[i][2], al[i][3], stg + 1*MAT_BYTES + off);
            }
            #pragma unroll
            for (int g = 0; g < 2; g++) {
                uint32_t off = ((bRowBase + g*16)*40 + kk + bCol)*2;
                ldsm_x4(bh[g*4+0], bh[g*4+1], bh[g*4+2], bh[g*4+3], stg + 2*MAT_BYTES + off);
                ldsm_x4(bl[g*4+0], bl[g*4+1], bl[g*4+2], bl[g*4+3], stg + 3*MAT_BYTES + off);
            }
            #pragma unroll
            for (int i = 0; i < 4; i++) {
                #pragma unroll
                for (int j = 0; j < 4; j++) {
                    mma_bf16(acc[i][j], ah[i], bh[j*2], bh[j*2+1]);
                    mma_bf16(acc[i][j], ah[i], bl[j*2], bl[j*2+1]);
                    mma_bf16(acc[i][j], al[i], bh[j*2], bh[j*2+1]);
                }
            }
        }
    }

    /* ---- fused rank-32 MoE correction: one pass per batch in this tile ---- */
    {
        int mlast = m0 + 127; if (mlast >= BSQ) mlast = BSQ - 1;
        int bb0 = m0 / SEQ, bb1 = mlast / SEQ;
        for (int bb = bb0; bb <= bb1; bb++) {
            uint32_t base = sb + ((bb - bb0) & 1)*STG_BYTES;
            __syncthreads();
            #pragma unroll
            for (int i2 = 0; i2 < 4; i2++) {
                int c = tid + 256*i2;
                int mat = c >> 9, cc = c & 511;
                int row = cc >> 2, col = (cc & 3)*8;
                int m = m0 + row;
                int ok = (m < BSQ) && (m / SEQ == bb);
                int t = m - bb*SEQ;
                const __nv_bfloat16* srcA = (mat ? g_xvl : g_xvh) +
                    (size_t)code*BB*SEQP*32 + ((size_t)bb*SEQP + (ok ? t : 0))*32 + col;
                cp16(base + mat*MAT_BYTES + (uint32_t)(row*40 + col)*2, srcA, ok ? 16 : 0);
            }
            #pragma unroll
            for (int i2 = 0; i2 < 4; i2++) {
                int c = tid + 256*i2;
                int mat = c >> 9, cc = c & 511;
                int row = cc >> 2, col = (cc & 3)*8;
                const __nv_bfloat16* srcB = (mat ? g_ubl : g_ubh) +
                    (size_t)code*BB*DIM*32 + ((size_t)bb*DIM + n0 + row)*32 + col;
                cp16(base + (2 + mat)*MAT_BYTES + (uint32_t)(row*40 + col)*2, srcB, 16);
            }
            CP_COMMIT();
            CP_WAIT0();
            __syncthreads();
            #pragma unroll
            for (int kk = 0; kk < 32; kk += 16) {
                uint32_t ah[4][4], al[4][4], bh[8], bl[8];
                #pragma unroll
                for (int i = 0; i < 4; i++) {
                    uint32_t off = ((aRow + i*16)*40 + kk + aCol)*2;
                    ldsm_x4(ah[i][0], ah[i][1], ah[i][2], ah[i][3], base + 0*MAT_BYTES + off);
                    ldsm_x4(al[i][0], al[i][1], al[i][2], al[i][3], base + 1*MAT_BYTES + off);
                }
                #pragma unroll
                for (int g = 0; g < 2; g++) {
                    uint32_t off = ((bRowBase + g*16)*40 + kk + bCol)*2;
                    ldsm_x4(bh[g*4+0], bh[g*4+1], bh[g*4+2], bh[g*4+3], base + 2*MAT_BYTES + off);
                    ldsm_x4(bl[g*4+0], bl[g*4+1], bl[g*4+2], bl[g*4+3], base + 3*MAT_BYTES + off);
                }
                #pragma unroll
                for (int i = 0; i < 4; i++) {
                    #pragma unroll
                    for (int j = 0; j < 4; j++) {
                        mma_bf16(acc[i][j], ah[i], bh[j*2], bh[j*2+1]);
                        mma_bf16(acc[i][j], ah[i], bl[j*2], bl[j*2+1]);
                        mma_bf16(acc[i][j], al[i], bh[j*2], bh[j*2+1]);
                    }
                }
            }
        }
    }

    /* ---- epilogue: row-major restructure, no per-element division -------- */
    float scale = (code == 0) ? QSCALE : 1.0f;
    __nv_bfloat16* Hd = (code==0)?g_aqh:(code==1)?g_akh:g_avh;
    __nv_bfloat16* Ld = (code==0)?g_aql:(code==1)?g_akl:g_avl;

    /* per-column constants (uniform over rows) */
    float bv0[4], bv1[4];
    int colv[4], hhv[4], d0v[4];
    #pragma unroll
    for (int j = 0; j < 4; j++) {
        int col = n0 + warp_n*32 + j*8 + (lane & 3)*2;
        colv[j] = col;
        bv0[j] = bias[col];
        bv1[j] = bias[col+1];
        hhv[j] = col >> 6;
        d0v[j] = col & 63;
    }

    int bbase = m0 / SEQ;                 /* uniform per CTA */
    int bnd = (bbase + 1)*SEQ;

    #pragma unroll
    for (int i = 0; i < 4; i++) {
        #pragma unroll
        for (int half = 0; half < 2; half++) {
            int m = m0 + warp_m*64 + i*16 + (lane >> 2) + half*8;
            if (m >= BSQ) continue;
            if (code == 3) {
                float* yrow = Yext + (size_t)m*DIM;
                #pragma unroll
                for (int j = 0; j < 4; j++) {
                    float v0 = (acc[i][j][half*2]   + bv0[j])*scale;
                    float v1 = (acc[i][j][half*2+1] + bv1[j])*scale;
                    *(float2*)(yrow + colv[j]) = make_float2(v0, v1);
                }
            } else {
                int b = (m >= bnd) ? bbase + 1 : bbase;
                int t = m - b*SEQ;
                size_t rowbase = ((size_t)(b*NH)*SEQP + t)*HD;
                #pragma unroll
                for (int j = 0; j < 4; j++) {
                    float v0 = (acc[i][j][half*2]   + bv0[j])*scale;
                    float v1 = (acc[i][j][half*2+1] + bv1[j])*scale;
                    float h0 = __bfloat162float(__float2bfloat16(v0));
                    float h1 = __bfloat162float(__float2bfloat16(v1));
                    size_t o = rowbase + (size_t)hhv[j]*SEQP*HD + d0v[j];
                    *(uint32_t*)(Hd + o) = pack_bf2(h0, h1);
                    *(uint32_t*)(Ld + o) = pack_bf2(v0 - h0, v1 - h1);
                }
            }
        }
    }
}

/* ---------------- xvmma_qkv: xv(p=0..2) = X @ [Vb0;Vb1;Vb2]^T ------------- */
#define X3_ABYT 13824
#define X3_BBYT 13824
#define X3_STGB (2*X3_ABYT + 2*X3_BBYT)
#define X3_SMEM (2*X3_STGB)

__device__ __forceinline__ void x3_load_stage(uint32_t sb, int buf, int k0,
                                              int b, int mt, int tid)
{
    uint32_t base = sb + buf*X3_STGB;
    #pragma unroll
    for (int i = 0; i < 16; i++) {
        int c = tid + 192*i;
        if (c >= 3072) break;
        int m4 = c / 768;
        int cc2 = c - m4*768;
        int row = cc2 >> 3, col8 = (cc2 & 7)*8;
        if (m4 < 2) {
            int t = mt*96 + row;
            int ok = t < SEQ;
            const __nv_bfloat16* src = (m4 ? g_xl : g_xh) +
                ((size_t)b*SEQ + (ok ? t : 0))*DIM + k0 + col8;
            cp16(base + m4*X3_ABYT + (uint32_t)(row*72 + col8)*2, src, ok ? 16 : 0);
        } else {
            int p = row >> 5, jr = row & 31;
            const __nv_bfloat16* src = ((m4 == 3) ? g_vbl : g_vbh) +
                (size_t)p*BB*32*DIM + ((size_t)b*32 + jr)*DIM + k0 + col8;
            cp16(base + 2*X3_ABYT + (m4 - 2)*X3_BBYT + (uint32_t)(row*72 + col8)*2, src, 16);
        }
    }
}

__global__ void __launch_bounds__(192, 1) xvmma_qkv_kernel()
{
    extern __shared__ __align__(16) char xsm[];
    uint32_t sb = smem_u32(xsm);
    int tid = threadIdx.x, lane = tid & 31, w = tid >> 5;
    int mt = blockIdx.x, b = blockIdx.y;

    float acc[12][4];
    #pragma unroll
    for (int j = 0; j < 12; j++)
        #pragma unroll
        for (int q = 0; q < 4; q++) acc[j][q] = 0.f;

    uint32_t aRow = (uint32_t)(w*16 + (lane & 15));
    uint32_t aCol = (uint32_t)((lane >> 4)*8);
    uint32_t bRow = (uint32_t)((lane & 7) + ((lane >> 4) << 3));
    uint32_t bCol = (uint32_t)(((lane >> 3) & 1)*8);

    x3_load_stage(sb, 0, 0, b, mt, tid);
    CP_COMMIT();

    for (int s = 0; s < 16; s++) {
        CP_WAIT0();
        __syncthreads();
        if (s + 1 < 16) {
            x3_load_stage(sb, (s+1)&1, (s+1)*64, b, mt, tid);
            CP_COMMIT();
        }
        uint32_t stg = sb + (s&1)*X3_STGB;
        #pragma unroll
        for (int kt = 0; kt < 4; kt++) {
            uint32_t ah[4], al[4];
            uint32_t off = (aRow*72 + kt*16 + aCol)*2;
            ldsm_x4(ah[0], ah[1], ah[2], ah[3], stg + off);
            ldsm_x4(al[0], al[1], al[2], al[3], stg + X3_ABYT + off);
            #pragma unroll
            for (int g = 0; g < 6; g++) {
                uint32_t bo = ((bRow + g*16)*72 + kt*16 + bCol)*2;
                uint32_t bh[4], bl[4];
                ldsm_x4(bh[0], bh[1], bh[2], bh[3], stg + 2*X3_ABYT + bo);
                ldsm_x4(bl[0], bl[1], bl[2], bl[3], stg + 2*X3_ABYT + X3_BBYT + bo);
                #pragma unroll
                for (int r = 0; r < 2; r++) {
                    int jj = g*2 + r;
                    mma_bf16(acc[jj], ah, bh[r*2], bh[r*2+1]);
                    mma_bf16(acc[jj], ah, bl[r*2], bl[r*2+1]);
                    mma_bf16(acc[jj], al, bh[r*2], bh[r*2+1]);
                }
            }
        }
    }

    int r0 = mt*96 + w*16 + (lane >> 2);
    int r1 = r0 + 8;
    #pragma unroll
    for (int j = 0; j < 12; j++) {
        int n = j*8 + (lane & 3)*2;
        int p = n >> 5, coln = n & 31;
        size_t xvoff = (size_t)p*BB*SEQP*32;
        if (r0 < SEQ) {
            float p0 = acc[j][0], p1 = acc[j][1];
            float h0 = __bfloat162float(__float2bfloat16(p0));
            float h1 = __bfloat162float(__float2bfloat16(p1));
            size_t o = xvoff + ((size_t)b*SEQP + r0)*32 + coln;
            *(uint32_t*)(g_xvh + o) = pack_bf2(h0, h1);
            *(uint32_t*)(g_xvl + o) = pack_bf2(p0 - h0, p1 - h1);
        }
        if (r1 < SEQ) {
            float p0 = acc[j][2], p1 = acc[j][3];
            float h0 = __bfloat162float(__float2bfloat16(p0));
            float h1 = __bfloat162float(__float2bfloat16(p1));
            size_t o = xvoff + ((size_t)b*SEQP + r1)*32 + coln;
            *(uint32_t*)(g_xvh + o) = pack_bf2(h0, h1);
            *(uint32_t*)(g_xvl + o) = pack_bf2(p0 - h0, p1 - h1);
        }
    }
}

/* ---------------- xvmma (single p = 3, ctx) -------------------- */
#define XV_ABYT 13824
#define XV_BBYT 4608
#define XV_STGB (2*XV_ABYT + 2*XV_BBYT)
#define XV_SMEM (2*XV_STGB)

__device__ __forceinline__ void xv_load_stage(uint32_t sb, int buf, int k0,
                                              int b, int mt, int tid, int p)
{
    uint32_t base = sb + buf*XV_STGB;
    size_t vboff = (size_t)p*BB*32*DIM;
    #pragma unroll
    for (int i = 0; i < 11; i++) {
        int c = tid + 192*i;
        if (c >= 2048) break;
        if (c < 1536) {
            int mat = (c >= 768);
            int cc = c - (mat ? 768 : 0);
            int row = cc >> 3, col8 = (cc & 7)*8;
            int t = mt*96 + row;
            int ok = t < SEQ;
            const __nv_bfloat16* src = (mat ? g_xl : g_xh) +
                ((size_t)b*SEQ + (ok ? t : 0))*DIM + k0 + col8;
            cp16(base + mat*XV_ABYT + (uint32_t)(row*72 + col8)*2, src, ok ? 16 : 0);
        } else {
            int c2 = c - 1536;
            int mat = c2 >> 8;
            int cc = c2 & 255;
            int row = cc >> 3, col8 = (cc & 7)*8;
            const __nv_bfloat16* src = (mat ? g_vbl : g_vbh) + vboff +
                ((size_t)b*32 + row)*DIM + k0 + col8;
            cp16(base + 2*XV_ABYT + mat*XV_BBYT + (uint32_t)(row*72 + col8)*2, src, 16);
        }
    }
}

__global__ void __launch_bounds__(192, 1) xvmma_kernel(int p)
{
    extern __shared__ __align__(16) char xsm[];
    uint32_t sb = smem_u32(xsm);
    int tid = threadIdx.x, lane = tid & 31, w = tid >> 5;
    int mt = blockIdx.x, b = blockIdx.y;

    float acc[4][4];
    #pragma unroll
    for (int j = 0; j < 4; j++)
        #pragma unroll
        for (int q = 0; q < 4; q++) acc[j][q] = 0.f;

    uint32_t aRow = (uint32_t)(w*16 + (lane & 15));
    uint32_t aCol = (uint32_t)((lane >> 4)*8);
    uint32_t bRow = (uint32_t)((lane & 7) + ((lane >> 4) << 3));
    uint32_t bCol = (uint32_t)(((lane >> 3) & 1)*8);

    xv_load_stage(sb, 0, 0, b, mt, tid, p);
    CP_COMMIT();

    for (int s = 0; s < 16; s++) {
        CP_WAIT0();
        __syncthreads();
        if (s + 1 < 16) {
            xv_load_stage(sb, (s+1)&1, (s+1)*64, b, mt, tid, p);
            CP_COMMIT();
        }
        uint32_t stg = sb + (s&1)*XV_STGB;
        #pragma unroll
        for (int kt = 0; kt < 4; kt++) {
            uint32_t ah[4], al[4], bh2[8], bl2[8];
            uint32_t off = (aRow*72 + kt*16 + aCol)*2;
            ldsm_x4(ah[0], ah[1], ah[2], ah[3], stg + off);
            ldsm_x4(al[0], al[1], al[2], al[3], stg + XV_ABYT + off);
            #pragma unroll
            for (int g = 0; g < 2; g++) {
                uint32_t bo = ((bRow + g*16)*72 + kt*16 + bCol)*2;
                ldsm_x4(bh2[g*4+0], bh2[g*4+1], bh2[g*4+2], bh2[g*4+3],
                        stg + 2*XV_ABYT + bo);
                ldsm_x4(bl2[g*4+0], bl2[g*4+1], bl2[g*4+2], bl2[g*4+3],
                        stg + 2*XV_ABYT + XV_BBYT + bo);
            }
            #pragma unroll
            for (int j = 0; j < 4; j++) {
                mma_bf16(acc[j], ah, bh2[j*2], bh2[j*2+1]);
                mma_bf16(acc[j], ah, bl2[j*2], bl2[j*2+1]);
                mma_bf16(acc[j], al, bh2[j*2], bh2[j*2+1]);
            }
        }
    }

    size_t xvoff = (size_t)p*BB*SEQP*32;
    int r0 = mt*96 + w*16 + (lane >> 2);
    int r1 = r0 + 8;
    #pragma unroll
    for (int j = 0; j < 4; j++) {
        int col = j*8 + (lane & 3)*2;
        if (r0 < SEQ) {
            float p0 = acc[j][0], p1 = acc[j][1];
            float h0 = __bfloat162float(__float2bfloat16(p0));
            float h1 = __bfloat162float(__float2bfloat16(p1));
            size_t o = xvoff + ((size_t)b*SEQP + r0)*32 + col;
            *(uint32_t*)(g_xvh + o) = pack_bf2(h0, h1);
            *(uint32_t*)(g_xvl + o) = pack_bf2(p0 - h0, p1 - h1);
        }
        if (r1 < SEQ) {
            float p0 = acc[j][2], p1 = acc[j][3];
            float h0 = __bfloat162float(__float2bfloat16(p0));
            float h1 = __bfloat162float(__float2bfloat16(p1));
            size_t o = xvoff + ((size_t)b*SEQP + r1)*32 + col;
            *(uint32_t*)(g_xvh + o) = pack_bf2(h0, h1);
            *(uint32_t*)(g_xvl + o) = pack_bf2(p0 - h0, p1 - h1);
        }
    }
}

/* ---------------- fused flash attention (KV chunk = 32, 9 chunks) --------- */
#define FA_QBYTES  13824
#define FA_MATB    4608
#define FA_STGB    (4*FA_MATB)
#define FA_KVBASE  (2*FA_QBYTES)
#define FA_SMEM    (FA_KVBASE + 2*FA_STGB)
#define FA_NC      9

__device__ __forceinline__ void fa_load_kv(uint32_t sb, int buf, int t0,
                                           int bh, int tid)
{
    uint32_t base = sb + FA_KVBASE + buf*FA_STGB;
    size_t goff = (size_t)bh*SEQP*HD + (size_t)t0*HD;
    const __nv_bfloat16* srcs[4] = {g_akh + goff, g_akl + goff, g_avh + goff, g_avl + goff};
    #pragma unroll
    for (int i = 0; i < 6; i++) {
        int c = tid + 192*i;
        if (c < 1024) {
            int mat = c >> 8, cc = c & 255;
            int row = cc >> 3, col8 = (cc & 7)*8;
            cp16(base + mat*FA_MATB + (uint32_t)(row*72 + col8)*2,
                 srcs[mat] + (size_t)row*HD + col8, 16);
        }
    }
}

__global__ void __launch_bounds__(192, 2) fa_kernel()
{
    extern __shared__ __align__(16) char fsm[];
    uint32_t sb = smem_u32(fsm);
    int tid = threadIdx.x, lane = tid & 31, w = tid >> 5;
    int mt = blockIdx.x, bh = blockIdx.y;
    int b = bh >> 4, hh = bh & 15;

    {
        const __nv_bfloat16* qs[2] = {g_aqh, g_aql};
        #pragma unroll
        for (int mat = 0; mat < 2; mat++) {
            const __nv_bfloat16* src = qs[mat] + ((size_t)bh*SEQP + mt*96)*HD;
            #pragma unroll
            for (int it = 0; it < 4; it++) {
                int c = tid + 192*it;
                int row = c >> 3, col8 = (c & 7)*8;
                uint4 v = *(const uint4*)(src + (size_t)row*HD + col8);
                *(uint4*)(fsm + mat*FA_QBYTES + (row*72 + col8)*2) = v;
            }
        }
    }
    fa_load_kv(sb, 0, 0, bh, tid);
    CP_COMMIT();
    __syncthreads();

    uint32_t qh[4][4], ql[4][4];
    {
        uint32_t aRow = (uint32_t)(w*16 + (lane & 15));
        uint32_t aCol = (uint32_t)((lane >> 4)*8);
        #pragma unroll
        for (int kt = 0; kt < 4; kt++) {
            uint32_t off = (aRow*72 + kt*16 + aCol)*2;
            ldsm_x4(qh[kt][0], qh[kt][1], qh[kt][2], qh[kt][3], sb + off);
            ldsm_x4(ql[kt][0], ql[kt][1], ql[kt][2], ql[kt][3], sb + FA_QBYTES + off);
        }
    }

    float o[8][4];
    #pragma unroll
    for (int j = 0; j < 8; j++)
        #pragma unroll
        for (int q = 0; q < 4; q++) o[j][q] = 0.f;
    float mr0 = -1e30f, mr1 = -1e30f, l0 = 0.f, l1 = 0.f;

    uint32_t kRow = (uint32_t)((lane & 7) + ((lane >> 4) << 3));
    uint32_t kCol = (uint32_t)(((lane >> 3) & 1)*8);
    uint32_t vRow = (uint32_t)(lane & 15);
    uint32_t vCol = (uint32_t)((lane >> 4) << 3);

    for (int c = 0; c < FA_NC; c++) {
        CP_WAIT0();
        __syncthreads();
        if (c + 1 < FA_NC) {
            fa_load_kv(sb, (c+1)&1, (c+1)*32, bh, tid);
            CP_COMMIT();
        }
        uint32_t stg = sb + FA_KVBASE + (c&1)*FA_STGB;

        float S[4][4];
        #pragma unroll
        for (int j = 0; j < 4; j++)
            #pragma unroll
            for (int q = 0; q < 4; q++) S[j][q] = 0.f;

        #pragma unroll
        for (int kt = 0; kt < 4; kt++) {
            #pragma unroll
            for (int g = 0; g < 2; g++) {
                uint32_t off = ((kRow + g*16)*72 + kt*16 + kCol)*2;
                uint32_t h0,h1,h2,h3, e0,e1,e2,e3;
                ldsm_x4(h0,h1,h2,h3, stg + 0*FA_MATB + off);
                ldsm_x4(e0,e1,e2,e3, stg + 1*FA_MATB + off);
                mma_bf16(S[2*g],   qh[kt], h0, h1);
                mma_bf16(S[2*g],   qh[kt], e0, e1);
                mma_bf16(S[2*g],   ql[kt], h0, h1);
                mma_bf16(S[2*g+1], qh[kt], h2, h3);
                mma_bf16(S[2*g+1], qh[kt], e2, e3);
                mma_bf16(S[2*g+1], ql[kt], h2, h3);
            }
        }

        if (c == FA_NC - 1) {
            #pragma unroll
            for (int j = 0; j < 4; j++) {
                int tb = (FA_NC-1)*32 + j*8 + (lane & 3)*2;
                if (tb     >= SEQ) { S[j][0] = -1e30f; S[j][2] = -1e30f; }
                if (tb + 1 >= SEQ) { S[j][1] = -1e30f; S[j][3] = -1e30f; }
            }
        }

        float mx0 = -1e30f, mx1 = -1e30f;
        #pragma unroll
        for (int j = 0; j < 4; j++) {
            mx0 = fmaxf(mx0, fmaxf(S[j][0], S[j][1]));
            mx1 = fmaxf(mx1, fmaxf(S[j][2], S[j][3]));
        }
        mx0 = fmaxf(mx0, __shfl_xor_sync(0xffffffffu, mx0, 1));
        mx0 = fmaxf(mx0, __shfl_xor_sync(0xffffffffu, mx0, 2));
        mx1 = fmaxf(mx1, __shfl_xor_sync(0xffffffffu, mx1, 1));
        mx1 = fmaxf(mx1, __shfl_xor_sync(0xffffffffu, mx1, 2));
        float mn0 = fmaxf(mr0, mx0), mn1 = fmaxf(mr1, mx1);
        float sc0 = expf(mr0 - mn0), sc1 = expf(mr1 - mn1);
        mr0 = mn0; mr1 = mn1;

        uint32_t ph[2][4], pl[2][4];
        float rs0 = 0.f, rs1 = 0.f;
        #pragma unroll
        for (int j = 0; j < 4; j++) {
            float p0 = expf(S[j][0] - mn0), p1 = expf(S[j][1] - mn0);
            float p2 = expf(S[j][2] - mn1), p3 = expf(S[j][3] - mn1);
            rs0 += p0 + p1; rs1 += p2 + p3;
            float h0 = __bfloat162float(__float2bfloat16(p0));
            float h1 = __bfloat162float(__float2bfloat16(p1));
            float h2 = __bfloat162float(__float2bfloat16(p2));
            float h3 = __bfloat162float(__float2bfloat16(p3));
            int kt2 = j >> 1, hb = (j & 1)*2;
            ph[kt2][hb]   = pack_bf2(h0, h1);
            ph[kt2][hb+1] = pack_bf2(h2, h3);
            pl[kt2][hb]   = pack_bf2(p0 - h0, p1 - h1);
            pl[kt2][hb+1] = pack_bf2(p2 - h2, p3 - h3);
        }
        rs0 += __shfl_xor_sync(0xffffffffu, rs0, 1);
        rs0 += __shfl_xor_sync(0xffffffffu, rs0, 2);
        rs1 += __shfl_xor_sync(0xffffffffu, rs1, 1);
        rs1 += __shfl_xor_sync(0xffffffffu, rs1, 2);
        l0 = l0*sc0 + rs0;
        l1 = l1*sc1 + rs1;

        #pragma unroll
        for (int j = 0; j < 8; j++) {
            o[j][0] *= sc0; o[j][1] *= sc0;
            o[j][2] *= sc1; o[j][3] *= sc1;
        }

        #pragma unroll
        for (int kt2 = 0; kt2 < 2; kt2++) {
            #pragma unroll
            for (int g = 0; g < 4; g++) {
                uint32_t off = ((kt2*16 + vRow)*72 + g*16 + vCol)*2;
                uint32_t h0,h1,h2,h3, e0,e1,e2,e3;
                ldsm_x4_t(h0,h1,h2,h3, stg + 2*FA_MATB + off);
                ldsm_x4_t(e0,e1,e2,e3, stg + 3*FA_MATB + off);
                mma_bf16(o[2*g],   ph[kt2], h0, h1);
                mma_bf16(o[2*g],   ph[kt2], e0, e1);
                mma_bf16(o[2*g],   pl[kt2], h0, h1);
                mma_bf16(o[2*g+1], ph[kt2], h2, h3);
                mma_bf16(o[2*g+1], ph[kt2], e2, e3);
                mma_bf16(o[2*g+1], pl[kt2], h2, h3);
            }
        }
    }

    float inv0 = 1.f/l0, inv1 = 1.f/l1;
    int r0 = mt*96 + w*16 + (lane >> 2);
    int r1 = r0 + 8;
    #pragma unroll
    for (int j = 0; j < 8; j++) {
        int d = hh*HD + j*8 + (lane & 3)*2;
        if (r0 < SEQ) {
            float v0 = o[j][0]*inv0, v1 = o[j][1]*inv0;
            float h0 = __bfloat162float(__float2bfloat16(v0));
            float h1 = __bfloat162float(__float2bfloat16(v1));
            size_t off = (size_t)(b*SEQ + r0)*DIM + d;
            *(uint32_t*)(g_xh + off) = pack_bf2(h0, h1);
            *(uint32_t*)(g_xl + off) = pack_bf2(v0 - h0, v1 - h1);
        }
        if (r1 < SEQ) {
            float v0 = o[j][2]*inv1, v1 = o[j][3]*inv1;
            float h0 = __bfloat162float(__float2bfloat16(v0));
            float h1 = __bfloat162float(__float2bfloat16(v1));
            size_t off = (size_t)(b*SEQ + r1)*DIM + d;
            *(uint32_t*)(g_xh + off) = pack_bf2(h0, h1);
            *(uint32_t*)(g_xl + off) = pack_bf2(v0 - h0, v1 - h1);
        }
    }
}

/* ---------------- launch ---------------- */
extern "C" void kernel_launch(void* const* d_in, const int* in_sizes, int n_in,
                              void* d_out, int out_size)
{
    const float* x   = (const float*)d_in[0];
    const float* gw1 = (const float*)d_in[1];
    const float* gb1 = (const float*)d_in[2];
    const float* gw2 = (const float*)d_in[3];
    const float* gb2 = (const float*)d_in[4];
    const float* Wm[4] = {(const float*)d_in[5],  (const float*)d_in[10],
                          (const float*)d_in[15], (const float*)d_in[20]};
    const float* Uu[4] = {(const float*)d_in[6],  (const float*)d_in[11],
                          (const float*)d_in[16], (const float*)d_in[21]};
    const float* Ss[4] = {(const float*)d_in[7],  (const float*)d_in[12],
                          (const float*)d_in[17], (const float*)d_in[22]};
    const float* Vv[4] = {(const float*)d_in[8],  (const float*)d_in[13],
                          (const float*)d_in[18], (const float*)d_in[23]};
    const float* bbv[4] = {(const float*)d_in[9],  (const float*)d_in[14],
                           (const float*)d_in[19], (const float*)d_in[24]};
    float* out = (float*)d_out;

    cudaFuncSetAttribute(mm_kernel, cudaFuncAttributeMaxDynamicSharedMemorySize, MM_SMEM);
    cudaFuncSetAttribute(fa_kernel, cudaFuncAttributeMaxDynamicSharedMemorySize, FA_SMEM);
    cudaFuncSetAttribute(xvmma_kernel, cudaFuncAttributeMaxDynamicSharedMemorySize, XV_SMEM);
    cudaFuncSetAttribute(xvmma_qkv_kernel, cudaFuncAttributeMaxDynamicSharedMemorySize, X3_SMEM);

    pool_kernel<<<dim3(BB, 8), 128>>>(x);
    gating_mlp_kernel<<<BB, GHID>>>(gw1, gb1, gw2, gb2);

    int nx4 = BSQ*DIM/4;
    int nw4 = DIM*DIM/4;
    convx_kernel<<<(nx4 + 255)/256, 256>>>(x, nx4);
    convw_kernel<<<dim3((nw4 + 255)/256, 4), 256>>>(Wm[0], Wm[1], Wm[2], Wm[3]);

    vuconv_kernel<<<dim3(BB, 36, 4), 256>>>(Vv[0], Vv[1], Vv[2], Vv[3],
                                            Ss[0], Ss[1], Ss[2], Ss[3],
                                            Uu[0], Uu[1], Uu[2], Uu[3]);

    xvmma_qkv_kernel<<<dim3(3, BB), 192, X3_SMEM>>>();

    dim3 gmm(8, 65, 3);
    mm_kernel<<<gmm, 256, MM_SMEM>>>(-1, bbv[0], bbv[1], bbv[2], nullptr);

    fa_kernel<<<dim3(3, BB*NH), 192, FA_SMEM>>>();

    xvmma_kernel<<<dim3(3, BB), 192, XV_SMEM>>>(3);
    mm_kernel<<<dim3(8, 65, 1), 256, MM_SMEM>>>(3, bbv[3], bbv[3], bbv[3], out);
}

// round 16
// speedup vs baseline: 1.0406x; 1.0083x over previous
#include <cuda_runtime.h>
#include <cuda_bf16.h>
#include <cstdint>
#include <math.h>

#define BB   32
#define SEQ  257
#define SEQP 320
#define DIM  1024
#define NH   16
#define HD   64
#define NEXP 8
#define RNK  16
#define GHID 256
#define BSQ  (BB*SEQ)          /* 8224 tokens */
#define QSCALE 0.125f

/* ---------------- scratch (device globals; no allocations) ---------------- */
static __device__ float g_pooled[BB*DIM];
static __device__ float g_gates[BB*2];
static __device__ int   g_idx  [BB*2];
static __device__ __align__(16) __nv_bfloat16 g_xh[(size_t)BSQ*DIM];
static __device__ __align__(16) __nv_bfloat16 g_xl[(size_t)BSQ*DIM];
static __device__ __align__(16) __nv_bfloat16 g_wh[(size_t)4*DIM*DIM];
static __device__ __align__(16) __nv_bfloat16 g_wl[(size_t)4*DIM*DIM];
static __device__ __align__(16) __nv_bfloat16 g_vbh[(size_t)4*BB*32*DIM];
static __device__ __align__(16) __nv_bfloat16 g_vbl[(size_t)4*BB*32*DIM];
static __device__ __align__(16) __nv_bfloat16 g_ubh[(size_t)4*BB*DIM*32];
static __device__ __align__(16) __nv_bfloat16 g_ubl[(size_t)4*BB*DIM*32];
static __device__ __align__(16) __nv_bfloat16 g_xvh[(size_t)4*BB*SEQP*32];
static __device__ __align__(16) __nv_bfloat16 g_xvl[(size_t)4*BB*SEQP*32];
static __device__ __align__(16) __nv_bfloat16 g_aqh[(size_t)BB*NH*SEQP*HD];
static __device__ __align__(16) __nv_bfloat16 g_aql[(size_t)BB*NH*SEQP*HD];
static __device__ __align__(16) __nv_bfloat16 g_akh[(size_t)BB*NH*SEQP*HD];
static __device__ __align__(16) __nv_bfloat16 g_akl[(size_t)BB*NH*SEQP*HD];
static __device__ __align__(16) __nv_bfloat16 g_avh[(size_t)BB*NH*SEQP*HD];
static __device__ __align__(16) __nv_bfloat16 g_avl[(size_t)BB*NH*SEQP*HD];

/* ---------------- small PTX helpers ---------------- */
__device__ __forceinline__ uint32_t smem_u32(const void* p) {
    uint32_t a;
    asm("{ .reg .u64 t; cvta.to.shared.u64 t, %1; cvt.u32.u64 %0, t; }" : "=r"(a) : "l"(p));
    return a;
}
__device__ __forceinline__ void cp16(uint32_t dst, const void* src, int srcBytes) {
    asm volatile("cp.async.cg.shared.global [%0], [%1], 16, %2;"
                 :: "r"(dst), "l"(src), "r"(srcBytes) : "memory");
}
#define CP_COMMIT() asm volatile("cp.async.commit_group;" ::: "memory")
#define CP_WAIT0()  asm volatile("cp.async.wait_group 0;" ::: "memory")

__device__ __forceinline__ void ldsm_x4(uint32_t& r0, uint32_t& r1, uint32_t& r2, uint32_t& r3,
                                        uint32_t addr) {
    asm volatile("ldmatrix.sync.aligned.m8n8.x4.shared.b16 {%0,%1,%2,%3}, [%4];"
                 : "=r"(r0), "=r"(r1), "=r"(r2), "=r"(r3) : "r"(addr));
}
__device__ __forceinline__ void ldsm_x4_t(uint32_t& r0, uint32_t& r1, uint32_t& r2, uint32_t& r3,
                                          uint32_t addr) {
    asm volatile("ldmatrix.sync.aligned.m8n8.x4.trans.shared.b16 {%0,%1,%2,%3}, [%4];"
                 : "=r"(r0), "=r"(r1), "=r"(r2), "=r"(r3) : "r"(addr));
}
__device__ __forceinline__ void mma_bf16(float* c, const uint32_t* a, uint32_t b0, uint32_t b1) {
    asm volatile("mma.sync.aligned.m16n8k16.row.col.f32.bf16.bf16.f32 "
                 "{%0,%1,%2,%3}, {%4,%5,%6,%7}, {%8,%9}, {%0,%1,%2,%3};"
                 : "+f"(c[0]), "+f"(c[1]), "+f"(c[2]), "+f"(c[3])
                 : "r"(a[0]), "r"(a[1]), "r"(a[2]), "r"(a[3]), "r"(b0), "r"(b1));
}
__device__ __forceinline__ uint32_t pack_bf2(float lo, float hi) {
    __nv_bfloat16 l = __float2bfloat16(lo), h = __float2bfloat16(hi);
    return ((uint32_t)__bfloat16_as_ushort(h) << 16) | (uint32_t)__bfloat16_as_ushort(l);
}

/* ---------------- pooling (parallel) + gating MLP ---------------- */
__global__ void pool_kernel(const float* __restrict__ x)
{
    int b = blockIdx.x;
    int d = blockIdx.y*128 + threadIdx.x;
    const float* xp = x + (size_t)b*SEQ*DIM + d;
    float s = 0.f;
    #pragma unroll 4
    for (int t = 0; t < SEQ; t++) s += xp[(size_t)t*DIM];
    g_pooled[b*DIM + d] = s * (1.0f/SEQ);
}

__global__ void gating_mlp_kernel(const float* __restrict__ gw1, const float* __restrict__ gb1,
                                  const float* __restrict__ gw2, const float* __restrict__ gb2)
{
    int b = blockIdx.x;
    __shared__ float h[GHID];
    __shared__ float logits[NEXP];
    int tid = threadIdx.x;
    const float* pooled = g_pooled + b*DIM;
    {
        float a = gb1[tid];
        const float* w = gw1 + (size_t)tid*DIM;
        #pragma unroll 4
        for (int d = 0; d < DIM; d++) a += pooled[d]*w[d];
        h[tid] = fmaxf(a, 0.f);
    }
    __syncthreads();
    if (tid < NEXP) {
        float a = gb2[tid];
        const float* w = gw2 + tid*GHID;
        for (int d = 0; d < GHID; d++) a += h[d]*w[d];
        logits[tid] = a;
    }
    __syncthreads();
    if (tid == 0) {
        int i0 = 0;
        for (int e = 1; e < NEXP; e++) if (logits[e] > logits[i0]) i0 = e;
        int i1 = -1;
        for (int e = 0; e < NEXP; e++) {
            if (e == i0) continue;
            if (i1 < 0 || logits[e] > logits[i1]) i1 = e;
        }
        float v0 = logits[i0], v1 = logits[i1];
        float e0 = expf(v0 - v0), e1 = expf(v1 - v0);
        float inv = 1.f/(e0 + e1);
        g_gates[b*2]   = e0*inv;
        g_gates[b*2+1] = e1*inv;
        g_idx[b*2]   = i0;
        g_idx[b*2+1] = i1;
    }
}

/* ---------------- fp32 -> (bf16 hi, bf16 lo) ---------------- */
__device__ __forceinline__ void split4(float4 v, ushort4& hh, ushort4& ll)
{
    __nv_bfloat16 t;
    t = __float2bfloat16(v.x); hh.x = __bfloat16_as_ushort(t);
    ll.x = __bfloat16_as_ushort(__float2bfloat16(v.x - __bfloat162float(t)));
    t = __float2bfloat16(v.y); hh.y = __bfloat16_as_ushort(t);
    ll.y = __bfloat16_as_ushort(__float2bfloat16(v.y - __bfloat162float(t)));
    t = __float2bfloat16(v.z); hh.z = __bfloat16_as_ushort(t);
    ll.z = __bfloat16_as_ushort(__float2bfloat16(v.z - __bfloat162float(t)));
    t = __float2bfloat16(v.w); hh.w = __bfloat16_as_ushort(t);
    ll.w = __bfloat16_as_ushort(__float2bfloat16(v.w - __bfloat162float(t)));
}

__global__ void convx_kernel(const float* __restrict__ s, int n4)
{
    int i = blockIdx.x*256 + threadIdx.x;
    if (i >= n4) return;
    ushort4 hh, ll;
    split4(((const float4*)s)[i], hh, ll);
    ((ushort4*)g_xh)[i] = hh;
    ((ushort4*)g_xl)[i] = ll;
}

__global__ void convw_kernel(const float* __restrict__ w0, const float* __restrict__ w1,
                             const float* __restrict__ w2, const float* __restrict__ w3)
{
    int p = blockIdx.y;
    const float* s = (p==0)?w0:(p==1)?w1:(p==2)?w2:w3;
    int i = blockIdx.x*256 + threadIdx.x;
    ushort4 hh, ll;
    split4(((const float4*)s)[i], hh, ll);
    size_t o = (size_t)p*(DIM*DIM/4) + i;
    ((ushort4*)g_wh)[o] = hh;
    ((ushort4*)g_wl)[o] = ll;
}

/* ---------------- vuconv: gather+scale V rows AND U cols (merged) --------- */
__global__ void vuconv_kernel(const float* __restrict__ V0, const float* __restrict__ V1,
                              const float* __restrict__ V2, const float* __restrict__ V3,
                              const float* __restrict__ S0, const float* __restrict__ S1,
                              const float* __restrict__ S2, const float* __restrict__ S3,
                              const float* __restrict__ U0, const float* __restrict__ U1,
                              const float* __restrict__ U2, const float* __restrict__ U3)
{
    int b = blockIdx.x, y = blockIdx.y, p = blockIdx.z;
    if (y < 32) {
        const float* Vm = (p==0)?V0:(p==1)?V1:(p==2)?V2:V3;
        const float* Sm = (p==0)?S0:(p==1)?S1:(p==2)?S2:S3;
        int j = y;
        int half = j >> 4, r = j & 15;
        int e = g_idx[b*2 + half];
        float sc = g_gates[b*2 + half] * Sm[e*RNK + r];
        float4 v = ((const float4*)(Vm + ((size_t)e*RNK + r)*DIM))[threadIdx.x];
        v.x *= sc; v.y *= sc; v.z *= sc; v.w *= sc;
        ushort4 hh, ll;
        split4(v, hh, ll);
        size_t o = ((size_t)p*BB*32 + (size_t)b*32 + j)*DIM/4 + threadIdx.x;
        ((ushort4*)g_vbh)[o] = hh;
        ((ushort4*)g_vbl)[o] = ll;
    } else {
        const float* U = (p==0)?U0:(p==1)?U1:(p==2)?U2:U3;
        int n = (y - 32)*256 + threadIdx.x;
        int i0 = g_idx[b*2], i1 = g_idx[b*2+1];
        const float* u0 = U + ((size_t)i0*DIM + n)*RNK;
        const float* u1 = U + ((size_t)i1*DIM + n)*RNK;
        __nv_bfloat16* H = g_ubh + ((size_t)p*BB*DIM + (size_t)b*DIM + n)*32;
        __nv_bfloat16* L = g_ubl + ((size_t)p*BB*DIM + (size_t)b*DIM + n)*32;
        #pragma unroll
        for (int r = 0; r < 16; r++) {
            float v0 = u0[r], v1 = u1[r];
            __nv_bfloat16 h0 = __float2bfloat16(v0);
            H[r]      = h0;
            L[r]      = __float2bfloat16(v0 - __bfloat162float(h0));
            __nv_bfloat16 h1 = __float2bfloat16(v1);
            H[16 + r] = h1;
            L[16 + r] = __float2bfloat16(v1 - __bfloat162float(h1));
        }
    }
}

/* ---------------- fused GEMM: Y = (X@W^T + bias + xv@Ub^T) * scale -------- */
#define MAT_BYTES (128*40*2)            /* 10240 */
#define STG_BYTES (4*MAT_BYTES)         /* 40960 */
#define MM_SMEM   (2*STG_BYTES)         /* 81920 */

__device__ __forceinline__ void mm_load_stage(uint32_t sb, int buf, int k0,
    const __nv_bfloat16* Ah, const __nv_bfloat16* Al,
    const __nv_bfloat16* Bh, const __nv_bfloat16* Bl,
    int m0, int n0, int tid)
{
    uint32_t base = sb + buf*STG_BYTES;
    const __nv_bfloat16* srcs[4] = {Ah, Al, Bh, Bl};
    #pragma unroll
    for (int i = 0; i < 8; i++) {
        int c = tid + 256*i;
        int mat = c >> 9;
        int cc  = c & 511;
        int row = cc >> 2;
        int col = (cc & 3) * 8;
        const __nv_bfloat16* p = srcs[mat];
        int grow = ((mat < 2) ? m0 : n0) + row;
        int ok = (mat >= 2) || (grow < BSQ);
        const void* src = p + ((size_t)(ok ? grow : 0))*DIM + k0 + col;
        uint32_t dst = base + mat*MAT_BYTES + (uint32_t)(row*40 + col)*2;
        cp16(dst, src, ok ? 16 : 0);
    }
}

__global__ void __launch_bounds__(256, 2) mm_kernel(int base_code,
    const float* __restrict__ bias0, const float* __restrict__ bias1,
    const float* __restrict__ bias2, float* __restrict__ Yext)
{
    extern __shared__ __align__(128) char smem[];
    int code = (base_code < 0) ? (int)blockIdx.z : base_code;
    const __nv_bfloat16* Ah = g_xh;
    const __nv_bfloat16* Al = g_xl;
    const __nv_bfloat16* Bh = g_wh + (size_t)code*DIM*DIM;
    const __nv_bfloat16* Bl = g_wl + (size_t)code*DIM*DIM;
    const float* bias = (code==0)?bias0:(code==1)?bias1:(code==2)?bias2:bias0;

    uint32_t sb = smem_u32(smem);
    int tid = threadIdx.x;
    int lane = tid & 31;
    int wid = tid >> 5;
    int warp_m = wid >> 2;
    int warp_n = wid & 3;
    int n0 = blockIdx.x*128, m0 = blockIdx.y*128;

    float acc[4][4][4];
    #pragma unroll
    for (int i = 0; i < 4; i++)
        #pragma unroll
        for (int j = 0; j < 4; j++)
            #pragma unroll
            for (int q = 0; q < 4; q++) acc[i][j][q] = 0.f;

    uint32_t aRow = (uint32_t)(warp_m*64 + (lane & 15));
    uint32_t aCol = (uint32_t)((lane >> 4) * 8);
    uint32_t bRowBase = (uint32_t)(warp_n*32 + (lane & 7) + ((lane >> 4) << 3));
    uint32_t bCol = (uint32_t)(((lane >> 3) & 1) * 8);

    mm_load_stage(sb, 0, 0, Ah, Al, Bh, Bl, m0, n0, tid);
    CP_COMMIT();

    const int NK = DIM/32;
    for (int s = 0; s < NK; s++) {
        CP_WAIT0();
        __syncthreads();
        if (s + 1 < NK) {
            mm_load_stage(sb, (s+1)&1, (s+1)*32, Ah, Al, Bh, Bl, m0, n0, tid);
            CP_COMMIT();
        }

        uint32_t stg = sb + (s&1)*STG_BYTES;
        #pragma unroll
        for (int kk = 0; kk < 32; kk += 16) {
            uint32_t ah[4][4], al[4][4], bh[8], bl[8];
            #pragma unroll
            for (int i = 0; i < 4; i++) {
                uint32_t off = ((aRow + i*16)*40 + kk + aCol)*2;
                ldsm_x4(ah[i][0], ah[i][1], ah[i][2], ah[i][3], stg + 0*MAT_BYTES + off);
                ldsm_x4(al[i][0], al[i][1], al[i][2], al[i][3], stg + 1*MAT_BYTES + off);
            }
            #pragma unroll
            for (int g = 0; g < 2; g++) {
                uint32_t off = ((bRowBase + g*16)*40 + kk + bCol)*2;
                ldsm_x4(bh[g*4+0], bh[g*4+1], bh[g*4+2], bh[g*4+3], stg + 2*MAT_BYTES + off);
                ldsm_x4(bl[g*4+0], bl[g*4+1], bl[g*4+2], bl[g*4+3], stg + 3*MAT_BYTES + off);
            }
            #pragma unroll
            for (int i = 0; i < 4; i++) {
                #pragma unroll
                for (int j = 0; j < 4; j++) {
                    mma_bf16(acc[i][j], ah[i], bh[j*2], bh[j*2+1]);
                    mma_bf16(acc[i][j], ah[i], bl[j*2], bl[j*2+1]);
                    mma_bf16(acc[i][j], al[i], bh[j*2], bh[j*2+1]);
                }
            }
        }
    }

    /* ---- fused rank-32 MoE correction: one pass per batch in this tile ---- */
    {
        int mlast = m0 + 127; if (mlast >= BSQ) mlast = BSQ - 1;
        int bb0 = m0 / SEQ, bb1 = mlast / SEQ;
        for (int bb = bb0; bb <= bb1; bb++) {
            uint32_t base = sb + ((bb - bb0) & 1)*STG_BYTES;
            __syncthreads();
            #pragma unroll
            for (int i2 = 0; i2 < 4; i2++) {
                int c = tid + 256*i2;
                int mat = c >> 9, cc = c & 511;
                int row = cc >> 2, col = (cc & 3)*8;
                int m = m0 + row;
                int ok = (m < BSQ) && (m / SEQ == bb);
                int t = m - bb*SEQ;
                const __nv_bfloat16* srcA = (mat ? g_xvl : g_xvh) +
                    (size_t)code*BB*SEQP*32 + ((size_t)bb*SEQP + (ok ? t : 0))*32 + col;
                cp16(base + mat*MAT_BYTES + (uint32_t)(row*40 + col)*2, srcA, ok ? 16 : 0);
            }
            #pragma unroll
            for (int i2 = 0; i2 < 4; i2++) {
                int c = tid + 256*i2;
                int mat = c >> 9, cc = c & 511;
                int row = cc >> 2, col = (cc & 3)*8;
                const __nv_bfloat16* srcB = (mat ? g_ubl : g_ubh) +
                    (size_t)code*BB*DIM*32 + ((size_t)bb*DIM + n0 + row)*32 + col;
                cp16(base + (2 + mat)*MAT_BYTES + (uint32_t)(row*40 + col)*2, srcB, 16);
            }
            CP_COMMIT();
            CP_WAIT0();
            __syncthreads();
            #pragma unroll
            for (int kk = 0; kk < 32; kk += 16) {
                uint32_t ah[4][4], al[4][4], bh[8], bl[8];
                #pragma unroll
                for (int i = 0; i < 4; i++) {
                    uint32_t off = ((aRow + i*16)*40 + kk + aCol)*2;
                    ldsm_x4(ah[i][0], ah[i][1], ah[i][2], ah[i][3], base + 0*MAT_BYTES + off);
                    ldsm_x4(al[i][0], al[i][1], al[i][2], al[i][3], base + 1*MAT_BYTES + off);
                }
                #pragma unroll
                for (int g = 0; g < 2; g++) {
                    uint32_t off = ((bRowBase + g*16)*40 + kk + bCol)*2;
                    ldsm_x4(bh[g*4+0], bh[g*4+1], bh[g*4+2], bh[g*4+3], base + 2*MAT_BYTES + off);
                    ldsm_x4(bl[g*4+0], bl[g*4+1], bl[g*4+2], bl[g*4+3], base + 3*MAT_BYTES + off);
                }
                #pragma unroll
                for (int i = 0; i < 4; i++) {
                    #pragma unroll
                    for (int j = 0; j < 4; j++) {
                        mma_bf16(acc[i][j], ah[i], bh[j*2], bh[j*2+1]);
                        mma_bf16(acc[i][j], ah[i], bl[j*2], bl[j*2+1]);
                        mma_bf16(acc[i][j], al[i], bh[j*2], bh[j*2+1]);
                    }
                }
            }
        }
    }

    /* ---- epilogue: row-major, no per-element division -------------------- */
    float scale = (code == 0) ? QSCALE : 1.0f;
    __nv_bfloat16* Hd = (code==0)?g_aqh:(code==1)?g_akh:g_avh;
    __nv_bfloat16* Ld = (code==0)?g_aql:(code==1)?g_akl:g_avl;

    float bv0[4], bv1[4];
    int colv[4], hhv[4], d0v[4];
    #pragma unroll
    for (int j = 0; j < 4; j++) {
        int col = n0 + warp_n*32 + j*8 + (lane & 3)*2;
        colv[j] = col;
        bv0[j] = bias[col];
        bv1[j] = bias[col+1];
        hhv[j] = col >> 6;
        d0v[j] = col & 63;
    }

    int bbase = m0 / SEQ;
    int bnd = (bbase + 1)*SEQ;

    #pragma unroll
    for (int i = 0; i < 4; i++) {
        #pragma unroll
        for (int half = 0; half < 2; half++) {
            int m = m0 + warp_m*64 + i*16 + (lane >> 2) + half*8;
            if (m >= BSQ) continue;
            if (code == 3) {
                float* yrow = Yext + (size_t)m*DIM;
                #pragma unroll
                for (int j = 0; j < 4; j++) {
                    float v0 = (acc[i][j][half*2]   + bv0[j])*scale;
                    float v1 = (acc[i][j][half*2+1] + bv1[j])*scale;
                    *(float2*)(yrow + colv[j]) = make_float2(v0, v1);
                }
            } else {
                int b = (m >= bnd) ? bbase + 1 : bbase;
                int t = m - b*SEQ;
                size_t rowbase = ((size_t)(b*NH)*SEQP + t)*HD;
                #pragma unroll
                for (int j = 0; j < 4; j++) {
                    float v0 = (acc[i][j][half*2]   + bv0[j])*scale;
                    float v1 = (acc[i][j][half*2+1] + bv1[j])*scale;
                    float h0 = __bfloat162float(__float2bfloat16(v0));
                    float h1 = __bfloat162float(__float2bfloat16(v1));
                    size_t o = rowbase + (size_t)hhv[j]*SEQP*HD + d0v[j];
                    *(uint32_t*)(Hd + o) = pack_bf2(h0, h1);
                    *(uint32_t*)(Ld + o) = pack_bf2(v0 - h0, v1 - h1);
                }
            }
        }
    }
}

/* ---------------- xvmma_qkv: xv(p=0..2) = X @ [Vb0;Vb1;Vb2]^T ------------- */
#define X3_ABYT 13824
#define X3_BBYT 13824
#define X3_STGB (2*X3_ABYT + 2*X3_BBYT)
#define X3_SMEM (2*X3_STGB)

__device__ __forceinline__ void x3_load_stage(uint32_t sb, int buf, int k0,
                                              int b, int mt, int tid)
{
    uint32_t base = sb + buf*X3_STGB;
    #pragma unroll
    for (int i = 0; i < 16; i++) {
        int c = tid + 192*i;
        if (c >= 3072) break;
        int m4 = c / 768;
        int cc2 = c - m4*768;
        int row = cc2 >> 3, col8 = (cc2 & 7)*8;
        if (m4 < 2) {
            int t = mt*96 + row;
            int ok = t < SEQ;
            const __nv_bfloat16* src = (m4 ? g_xl : g_xh) +
                ((size_t)b*SEQ + (ok ? t : 0))*DIM + k0 + col8;
            cp16(base + m4*X3_ABYT + (uint32_t)(row*72 + col8)*2, src, ok ? 16 : 0);
        } else {
            int p = row >> 5, jr = row & 31;
            const __nv_bfloat16* src = ((m4 == 3) ? g_vbl : g_vbh) +
                (size_t)p*BB*32*DIM + ((size_t)b*32 + jr)*DIM + k0 + col8;
            cp16(base + 2*X3_ABYT + (m4 - 2)*X3_BBYT + (uint32_t)(row*72 + col8)*2, src, 16);
        }
    }
}

__global__ void __launch_bounds__(192, 1) xvmma_qkv_kernel()
{
    extern __shared__ __align__(16) char xsm[];
    uint32_t sb = smem_u32(xsm);
    int tid = threadIdx.x, lane = tid & 31, w = tid >> 5;
    int mt = blockIdx.x, b = blockIdx.y;

    float acc[12][4];
    #pragma unroll
    for (int j = 0; j < 12; j++)
        #pragma unroll
        for (int q = 0; q < 4; q++) acc[j][q] = 0.f;

    uint32_t aRow = (uint32_t)(w*16 + (lane & 15));
    uint32_t aCol = (uint32_t)((lane >> 4)*8);
    uint32_t bRow = (uint32_t)((lane & 7) + ((lane >> 4) << 3));
    uint32_t bCol = (uint32_t)(((lane >> 3) & 1)*8);

    x3_load_stage(sb, 0, 0, b, mt, tid);
    CP_COMMIT();

    for (int s = 0; s < 16; s++) {
        CP_WAIT0();
        __syncthreads();
        if (s + 1 < 16) {
            x3_load_stage(sb, (s+1)&1, (s+1)*64, b, mt, tid);
            CP_COMMIT();
        }
        uint32_t stg = sb + (s&1)*X3_STGB;
        #pragma unroll
        for (int kt = 0; kt < 4; kt++) {
            uint32_t ah[4], al[4];
            uint32_t off = (aRow*72 + kt*16 + aCol)*2;
            ldsm_x4(ah[0], ah[1], ah[2], ah[3], stg + off);
            ldsm_x4(al[0], al[1], al[2], al[3], stg + X3_ABYT + off);
            #pragma unroll
            for (int g = 0; g < 6; g++) {
                uint32_t bo = ((bRow + g*16)*72 + kt*16 + bCol)*2;
                uint32_t bh[4], bl[4];
                ldsm_x4(bh[0], bh[1], bh[2], bh[3], stg + 2*X3_ABYT + bo);
                ldsm_x4(bl[0], bl[1], bl[2], bl[3], stg + 2*X3_ABYT + X3_BBYT + bo);
                #pragma unroll
                for (int r = 0; r < 2; r++) {
                    int jj = g*2 + r;
                    mma_bf16(acc[jj], ah, bh[r*2], bh[r*2+1]);
                    mma_bf16(acc[jj], ah, bl[r*2], bl[r*2+1]);
                    mma_bf16(acc[jj], al, bh[r*2], bh[r*2+1]);
                }
            }
        }
    }

    int r0 = mt*96 + w*16 + (lane >> 2);
    int r1 = r0 + 8;
    #pragma unroll
    for (int j = 0; j < 12; j++) {
        int n = j*8 + (lane & 3)*2;
        int p = n >> 5, coln = n & 31;
        size_t xvoff = (size_t)p*BB*SEQP*32;
        if (r0 < SEQ) {
            float p0 = acc[j][0], p1 = acc[j][1];
            float h0 = __bfloat162float(__float2bfloat16(p0));
            float h1 = __bfloat162float(__float2bfloat16(p1));
            size_t o = xvoff + ((size_t)b*SEQP + r0)*32 + coln;
            *(uint32_t*)(g_xvh + o) = pack_bf2(h0, h1);
            *(uint32_t*)(g_xvl + o) = pack_bf2(p0 - h0, p1 - h1);
        }
        if (r1 < SEQ) {
            float p0 = acc[j][2], p1 = acc[j][3];
            float h0 = __bfloat162float(__float2bfloat16(p0));
            float h1 = __bfloat162float(__float2bfloat16(p1));
            size_t o = xvoff + ((size_t)b*SEQP + r1)*32 + coln;
            *(uint32_t*)(g_xvh + o) = pack_bf2(h0, h1);
            *(uint32_t*)(g_xvl + o) = pack_bf2(p0 - h0, p1 - h1);
        }
    }
}

/* ---------------- xvmma (single p = 3, ctx) -------------------- */
#define XV_ABYT 13824
#define XV_BBYT 4608
#define XV_STGB (2*XV_ABYT + 2*XV_BBYT)
#define XV_SMEM (2*XV_STGB)

__device__ __forceinline__ void xv_load_stage(uint32_t sb, int buf, int k0,
                                              int b, int mt, int tid, int p)
{
    uint32_t base = sb + buf*XV_STGB;
    size_t vboff = (size_t)p*BB*32*DIM;
    #pragma unroll
    for (int i = 0; i < 11; i++) {
        int c = tid + 192*i;
        if (c >= 2048) break;
        if (c < 1536) {
            int mat = (c >= 768);
            int cc = c - (mat ? 768 : 0);
            int row = cc >> 3, col8 = (cc & 7)*8;
            int t = mt*96 + row;
            int ok = t < SEQ;
            const __nv_bfloat16* src = (mat ? g_xl : g_xh) +
                ((size_t)b*SEQ + (ok ? t : 0))*DIM + k0 + col8;
            cp16(base + mat*XV_ABYT + (uint32_t)(row*72 + col8)*2, src, ok ? 16 : 0);
        } else {
            int c2 = c - 1536;
            int mat = c2 >> 8;
            int cc = c2 & 255;
            int row = cc >> 3, col8 = (cc & 7)*8;
            const __nv_bfloat16* src = (mat ? g_vbl : g_vbh) + vboff +
                ((size_t)b*32 + row)*DIM + k0 + col8;
            cp16(base + 2*XV_ABYT + mat*XV_BBYT + (uint32_t)(row*72 + col8)*2, src, 16);
        }
    }
}

__global__ void __launch_bounds__(192, 1) xvmma_kernel(int p)
{
    extern __shared__ __align__(16) char xsm[];
    uint32_t sb = smem_u32(xsm);
    int tid = threadIdx.x, lane = tid & 31, w = tid >> 5;
    int mt = blockIdx.x, b = blockIdx.y;

    float acc[4][4];
    #pragma unroll
    for (int j = 0; j < 4; j++)
        #pragma unroll
        for (int q = 0; q < 4; q++) acc[j][q] = 0.f;

    uint32_t aRow = (uint32_t)(w*16 + (lane & 15));
    uint32_t aCol = (uint32_t)((lane >> 4)*8);
    uint32_t bRow = (uint32_t)((lane & 7) + ((lane >> 4) << 3));
    uint32_t bCol = (uint32_t)(((lane >> 3) & 1)*8);

    xv_load_stage(sb, 0, 0, b, mt, tid, p);
    CP_COMMIT();

    for (int s = 0; s < 16; s++) {
        CP_WAIT0();
        __syncthreads();
        if (s + 1 < 16) {
            xv_load_stage(sb, (s+1)&1, (s+1)*64, b, mt, tid, p);
            CP_COMMIT();
        }
        uint32_t stg = sb + (s&1)*XV_STGB;
        #pragma unroll
        for (int kt = 0; kt < 4; kt++) {
            uint32_t ah[4], al[4], bh2[8], bl2[8];
            uint32_t off = (aRow*72 + kt*16 + aCol)*2;
            ldsm_x4(ah[0], ah[1], ah[2], ah[3], stg + off);
            ldsm_x4(al[0], al[1], al[2], al[3], stg + XV_ABYT + off);
            #pragma unroll
            for (int g = 0; g < 2; g++) {
                uint32_t bo = ((bRow + g*16)*72 + kt*16 + bCol)*2;
                ldsm_x4(bh2[g*4+0], bh2[g*4+1], bh2[g*4+2], bh2[g*4+3],
                        stg + 2*XV_ABYT + bo);
                ldsm_x4(bl2[g*4+0], bl2[g*4+1], bl2[g*4+2], bl2[g*4+3],
                        stg + 2*XV_ABYT + XV_BBYT + bo);
            }
            #pragma unroll
            for (int j = 0; j < 4; j++) {
                mma_bf16(acc[j], ah, bh2[j*2], bh2[j*2+1]);
                mma_bf16(acc[j], ah, bl2[j*2], bl2[j*2+1]);
                mma_bf16(acc[j], al, bh2[j*2], bh2[j*2+1]);
            }
        }
    }

    size_t xvoff = (size_t)p*BB*SEQP*32;
    int r0 = mt*96 + w*16 + (lane >> 2);
    int r1 = r0 + 8;
    #pragma unroll
    for (int j = 0; j < 4; j++) {
        int col = j*8 + (lane & 3)*2;
        if (r0 < SEQ) {
            float p0 = acc[j][0], p1 = acc[j][1];
            float h0 = __bfloat162float(__float2bfloat16(p0));
            float h1 = __bfloat162float(__float2bfloat16(p1));
            size_t o = xvoff + ((size_t)b*SEQP + r0)*32 + col;
            *(uint32_t*)(g_xvh + o) = pack_bf2(h0, h1);
            *(uint32_t*)(g_xvl + o) = pack_bf2(p0 - h0, p1 - h1);
        }
        if (r1 < SEQ) {
            float p0 = acc[j][2], p1 = acc[j][3];
            float h0 = __bfloat162float(__float2bfloat16(p0));
            float h1 = __bfloat162float(__float2bfloat16(p1));
            size_t o = xvoff + ((size_t)b*SEQP + r1)*32 + col;
            *(uint32_t*)(g_xvh + o) = pack_bf2(h0, h1);
            *(uint32_t*)(g_xvl + o) = pack_bf2(p0 - h0, p1 - h1);
        }
    }
}

/* ---------------- fused flash attention (KV chunk = 32, 9 chunks) --------- */
/* Q fragments re-loaded from resident smem each chunk -> fewer live regs,
   enabling spill-free 3 CTAs/SM.                                            */
#define FA_QBYTES  13824
#define FA_MATB    4608
#define FA_STGB    (4*FA_MATB)
#define FA_KVBASE  (2*FA_QBYTES)
#define FA_SMEM    (FA_KVBASE + 2*FA_STGB)
#define FA_NC      9

__device__ __forceinline__ void fa_load_kv(uint32_t sb, int buf, int t0,
                                           int bh, int tid)
{
    uint32_t base = sb + FA_KVBASE + buf*FA_STGB;
    size_t goff = (size_t)bh*SEQP*HD + (size_t)t0*HD;
    const __nv_bfloat16* srcs[4] = {g_akh + goff, g_akl + goff, g_avh + goff, g_avl + goff};
    #pragma unroll
    for (int i = 0; i < 6; i++) {
        int c = tid + 192*i;
        if (c < 1024) {
            int mat = c >> 8, cc = c & 255;
            int row = cc >> 3, col8 = (cc & 7)*8;
            cp16(base + mat*FA_MATB + (uint32_t)(row*72 + col8)*2,
                 srcs[mat] + (size_t)row*HD + col8, 16);
        }
    }
}

__global__ void __launch_bounds__(192, 3) fa_kernel()
{
    extern __shared__ __align__(16) char fsm[];
    uint32_t sb = smem_u32(fsm);
    int tid = threadIdx.x, lane = tid & 31, w = tid >> 5;
    int mt = blockIdx.x, bh = blockIdx.y;
    int b = bh >> 4, hh = bh & 15;

    {
        const __nv_bfloat16* qs[2] = {g_aqh, g_aql};
        #pragma unroll
        for (int mat = 0; mat < 2; mat++) {
            const __nv_bfloat16* src = qs[mat] + ((size_t)bh*SEQP + mt*96)*HD;
            #pragma unroll
            for (int it = 0; it < 4; it++) {
                int c = tid + 192*it;
                int row = c >> 3, col8 = (c & 7)*8;
                uint4 v = *(const uint4*)(src + (size_t)row*HD + col8);
                *(uint4*)(fsm + mat*FA_QBYTES + (row*72 + col8)*2) = v;
            }
        }
    }
    fa_load_kv(sb, 0, 0, bh, tid);
    CP_COMMIT();
    __syncthreads();

    uint32_t qRowOff = (uint32_t)((w*16 + (lane & 15))*72 + (lane >> 4)*8)*2;

    float o[8][4];
    #pragma unroll
    for (int j = 0; j < 8; j++)
        #pragma unroll
        for (int q = 0; q < 4; q++) o[j][q] = 0.f;
    float mr0 = -1e30f, mr1 = -1e30f, l0 = 0.f, l1 = 0.f;

    uint32_t kRow = (uint32_t)((lane & 7) + ((lane >> 4) << 3));
    uint32_t kCol = (uint32_t)(((lane >> 3) & 1)*8);
    uint32_t vRow = (uint32_t)(lane & 15);
    uint32_t vCol = (uint32_t)((lane >> 4) << 3);

    for (int c = 0; c < FA_NC; c++) {
        CP_WAIT0();
        __syncthreads();
        if (c + 1 < FA_NC) {
            fa_load_kv(sb, (c+1)&1, (c+1)*32, bh, tid);
            CP_COMMIT();
        }
        uint32_t stg = sb + FA_KVBASE + (c&1)*FA_STGB;

        float S[4][4];
        #pragma unroll
        for (int j = 0; j < 4; j++)
            #pragma unroll
            for (int q = 0; q < 4; q++) S[j][q] = 0.f;

        #pragma unroll
        for (int kt = 0; kt < 4; kt++) {
            uint32_t qh4[4], ql4[4];
            uint32_t qoff = qRowOff + (uint32_t)(kt*16)*2;
            ldsm_x4(qh4[0], qh4[1], qh4[2], qh4[3], sb + qoff);
            ldsm_x4(ql4[0], ql4[1], ql4[2], ql4[3], sb + FA_QBYTES + qoff);
            #pragma unroll
            for (int g = 0; g < 2; g++) {
                uint32_t off = ((kRow + g*16)*72 + kt*16 + kCol)*2;
                uint32_t h0,h1,h2,h3, e0,e1,e2,e3;
                ldsm_x4(h0,h1,h2,h3, stg + 0*FA_MATB + off);
                ldsm_x4(e0,e1,e2,e3, stg + 1*FA_MATB + off);
                mma_bf16(S[2*g],   qh4, h0, h1);
                mma_bf16(S[2*g],   qh4, e0, e1);
                mma_bf16(S[2*g],   ql4, h0, h1);
                mma_bf16(S[2*g+1], qh4, h2, h3);
                mma_bf16(S[2*g+1], qh4, e2, e3);
                mma_bf16(S[2*g+1], ql4, h2, h3);
            }
        }

        if (c == FA_NC - 1) {
            #pragma unroll
            for (int j = 0; j < 4; j++) {
                int tb = (FA_NC-1)*32 + j*8 + (lane & 3)*2;
                if (tb     >= SEQ) { S[j][0] = -1e30f; S[j][2] = -1e30f; }
                if (tb + 1 >= SEQ) { S[j][1] = -1e30f; S[j][3] = -1e30f; }
            }
        }

        float mx0 = -1e30f, mx1 = -1e30f;
        #pragma unroll
        for (int j = 0; j < 4; j++) {
            mx0 = fmaxf(mx0, fmaxf(S[j][0], S[j][1]));
            mx1 = fmaxf(mx1, fmaxf(S[j][2], S[j][3]));
        }
        mx0 = fmaxf(mx0, __shfl_xor_sync(0xffffffffu, mx0, 1));
        mx0 = fmaxf(mx0, __shfl_xor_sync(0xffffffffu, mx0, 2));
        mx1 = fmaxf(mx1, __shfl_xor_sync(0xffffffffu, mx1, 1));
        mx1 = fmaxf(mx1, __shfl_xor_sync(0xffffffffu, mx1, 2));
        float mn0 = fmaxf(mr0, mx0), mn1 = fmaxf(mr1, mx1);
        float sc0 = __expf(mr0 - mn0), sc1 = __expf(mr1 - mn1);
        mr0 = mn0; mr1 = mn1;

        uint32_t ph[2][4], pl[2][4];
        float rs0 = 0.f, rs1 = 0.f;
        #pragma unroll
        for (int j = 0; j < 4; j++) {
            float p0 = __expf(S[j][0] - mn0), p1 = __expf(S[j][1] - mn0);
            float p2 = __expf(S[j][2] - mn1), p3 = __expf(S[j][3] - mn1);
            rs0 += p0 + p1; rs1 += p2 + p3;
            float h0 = __bfloat162float(__float2bfloat16(p0));
            float h1 = __bfloat162float(__float2bfloat16(p1));
            float h2 = __bfloat162float(__float2bfloat16(p2));
            float h3 = __bfloat162float(__float2bfloat16(p3));
            int kt2 = j >> 1, hb = (j & 1)*2;
            ph[kt2][hb]   = pack_bf2(h0, h1);
            ph[kt2][hb+1] = pack_bf2(h2, h3);
            pl[kt2][hb]   = pack_bf2(p0 - h0, p1 - h1);
            pl[kt2][hb+1] = pack_bf2(p2 - h2, p3 - h3);
        }
        rs0 += __shfl_xor_sync(0xffffffffu, rs0, 1);
        rs0 += __shfl_xor_sync(0xffffffffu, rs0, 2);
        rs1 += __shfl_xor_sync(0xffffffffu, rs1, 1);
        rs1 += __shfl_xor_sync(0xffffffffu, rs1, 2);
        l0 = l0*sc0 + rs0;
        l1 = l1*sc1 + rs1;

        #pragma unroll
        for (int j = 0; j < 8; j++) {
            o[j][0] *= sc0; o[j][1] *= sc0;
            o[j][2] *= sc1; o[j][3] *= sc1;
        }

        #pragma unroll
        for (int kt2 = 0; kt2 < 2; kt2++) {
            #pragma unroll
            for (int g = 0; g < 4; g++) {
                uint32_t off = ((kt2*16 + vRow)*72 + g*16 + vCol)*2;
                uint32_t h0,h1,h2,h3, e0,e1,e2,e3;
                ldsm_x4_t(h0,h1,h2,h3, stg + 2*FA_MATB + off);
                ldsm_x4_t(e0,e1,e2,e3, stg + 3*FA_MATB + off);
                mma_bf16(o[2*g],   ph[kt2], h0, h1);
                mma_bf16(o[2*g],   ph[kt2], e0, e1);
                mma_bf16(o[2*g],   pl[kt2], h0, h1);
                mma_bf16(o[2*g+1], ph[kt2], h2, h3);
                mma_bf16(o[2*g+1], ph[kt2], e2, e3);
                mma_bf16(o[2*g+1], pl[kt2], h2, h3);
            }
        }
    }

    float inv0 = 1.f/l0, inv1 = 1.f/l1;
    int r0 = mt*96 + w*16 + (lane >> 2);
    int r1 = r0 + 8;
    #pragma unroll
    for (int j = 0; j < 8; j++) {
        int d = hh*HD + j*8 + (lane & 3)*2;
        if (r0 < SEQ) {
            float v0 = o[j][0]*inv0, v1 = o[j][1]*inv0;
            float h0 = __bfloat162float(__float2bfloat16(v0));
            float h1 = __bfloat162float(__float2bfloat16(v1));
            size_t off = (size_t)(b*SEQ + r0)*DIM + d;
            *(uint32_t*)(g_xh + off) = pack_bf2(h0, h1);
            *(uint32_t*)(g_xl + off) = pack_bf2(v0 - h0, v1 - h1);
        }
        if (r1 < SEQ) {
            float v0 = o[j][2]*inv1, v1 = o[j][3]*inv1;
            float h0 = __bfloat162float(__float2bfloat16(v0));
            float h1 = __bfloat162float(__float2bfloat16(v1));
            size_t off = (size_t)(b*SEQ + r1)*DIM + d;
            *(uint32_t*)(g_xh + off) = pack_bf2(h0, h1);
            *(uint32_t*)(g_xl + off) = pack_bf2(v0 - h0, v1 - h1);
        }
    }
}

/* ---------------- launch ---------------- */
extern "C" void kernel_launch(void* const* d_in, const int* in_sizes, int n_in,
                              void* d_out, int out_size)
{
    const float* x   = (const float*)d_in[0];
    const float* gw1 = (const float*)d_in[1];
    const float* gb1 = (const float*)d_in[2];
    const float* gw2 = (const float*)d_in[3];
    const float* gb2 = (const float*)d_in[4];
    const float* Wm[4] = {(const float*)d_in[5],  (const float*)d_in[10],
                          (const float*)d_in[15], (const float*)d_in[20]};
    const float* Uu[4] = {(const float*)d_in[6],  (const float*)d_in[11],
                          (const float*)d_in[16], (const float*)d_in[21]};
    const float* Ss[4] = {(const float*)d_in[7],  (const float*)d_in[12],
                          (const float*)d_in[17], (const float*)d_in[22]};
    const float* Vv[4] = {(const float*)d_in[8],  (const float*)d_in[13],
                          (const float*)d_in[18], (const float*)d_in[23]};
    const float* bbv[4] = {(const float*)d_in[9],  (const float*)d_in[14],
                           (const float*)d_in[19], (const float*)d_in[24]};
    float* out = (float*)d_out;

    cudaFuncSetAttribute(mm_kernel, cudaFuncAttributeMaxDynamicSharedMemorySize, MM_SMEM);
    cudaFuncSetAttribute(fa_kernel, cudaFuncAttributeMaxDynamicSharedMemorySize, FA_SMEM);
    cudaFuncSetAttribute(xvmma_kernel, cudaFuncAttributeMaxDynamicSharedMemorySize, XV_SMEM);
    cudaFuncSetAttribute(xvmma_qkv_kernel, cudaFuncAttributeMaxDynamicSharedMemorySize, X3_SMEM);

    pool_kernel<<<dim3(BB, 8), 128>>>(x);
    gating_mlp_kernel<<<BB, GHID>>>(gw1, gb1, gw2, gb2);

    int nx4 = BSQ*DIM/4;
    int nw4 = DIM*DIM/4;
    convx_kernel<<<(nx4 + 255)/256, 256>>>(x, nx4);
    convw_kernel<<<dim3((nw4 + 255)/256, 4), 256>>>(Wm[0], Wm[1], Wm[2], Wm[3]);

    vuconv_kernel<<<dim3(BB, 36, 4), 256>>>(Vv[0], Vv[1], Vv[2], Vv[3],
                                            Ss[0], Ss[1], Ss[2], Ss[3],
                                            Uu[0], Uu[1], Uu[2], Uu[3]);

    xvmma_qkv_kernel<<<dim3(3, BB), 192, X3_SMEM>>>();

    dim3 gmm(8, 65, 3);
    mm_kernel<<<gmm, 256, MM_SMEM>>>(-1, bbv[0], bbv[1], bbv[2], nullptr);

    fa_kernel<<<dim3(3, BB*NH), 192, FA_SMEM>>>();

    xvmma_kernel<<<dim3(3, BB), 192, XV_SMEM>>>(3);
    mm_kernel<<<dim3(8, 65, 1), 256, MM_SMEM>>>(3, bbv[3], bbv[3], bbv[3], out);
}

// round 17
// speedup vs baseline: 1.0406x; 1.0000x over previous
#include <cuda_runtime.h>
#include <cuda_bf16.h>
#include <cstdint>
#include <math.h>

#define BB   32
#define SEQ  257
#define SEQP 320
#define DIM  1024
#define NH   16
#define HD   64
#define NEXP 8
#define RNK  16
#define GHID 256
#define BSQ  (BB*SEQ)          /* 8224 tokens */
#define QSCALE 0.125f

/* ---------------- scratch (device globals; no allocations) ---------------- */
static __device__ float g_pooled[BB*DIM];
static __device__ float g_gates[BB*2];
static __device__ int   g_idx  [BB*2];
static __device__ __align__(16) __nv_bfloat16 g_xh[(size_t)BSQ*DIM];
static __device__ __align__(16) __nv_bfloat16 g_xl[(size_t)BSQ*DIM];
static __device__ __align__(16) __nv_bfloat16 g_wh[(size_t)4*DIM*DIM];
static __device__ __align__(16) __nv_bfloat16 g_wl[(size_t)4*DIM*DIM];
static __device__ __align__(16) __nv_bfloat16 g_vbh[(size_t)4*BB*32*DIM];
static __device__ __align__(16) __nv_bfloat16 g_vbl[(size_t)4*BB*32*DIM];
static __device__ __align__(16) __nv_bfloat16 g_ubh[(size_t)4*BB*DIM*32];
static __device__ __align__(16) __nv_bfloat16 g_ubl[(size_t)4*BB*DIM*32];
static __device__ __align__(16) __nv_bfloat16 g_xvh[(size_t)4*BB*SEQP*32];
static __device__ __align__(16) __nv_bfloat16 g_xvl[(size_t)4*BB*SEQP*32];
static __device__ __align__(16) __nv_bfloat16 g_aqh[(size_t)BB*NH*SEQP*HD];
static __device__ __align__(16) __nv_bfloat16 g_aql[(size_t)BB*NH*SEQP*HD];
static __device__ __align__(16) __nv_bfloat16 g_akh[(size_t)BB*NH*SEQP*HD];
static __device__ __align__(16) __nv_bfloat16 g_akl[(size_t)BB*NH*SEQP*HD];
static __device__ __align__(16) __nv_bfloat16 g_avh[(size_t)BB*NH*SEQP*HD];
static __device__ __align__(16) __nv_bfloat16 g_avl[(size_t)BB*NH*SEQP*HD];

/* ---------------- small PTX helpers ---------------- */
__device__ __forceinline__ uint32_t smem_u32(const void* p) {
    uint32_t a;
    asm("{ .reg .u64 t; cvta.to.shared.u64 t, %1; cvt.u32.u64 %0, t; }" : "=r"(a) : "l"(p));
    return a;
}
__device__ __forceinline__ void cp16(uint32_t dst, const void* src, int srcBytes) {
    asm volatile("cp.async.cg.shared.global [%0], [%1], 16, %2;"
                 :: "r"(dst), "l"(src), "r"(srcBytes) : "memory");
}
#define CP_COMMIT() asm volatile("cp.async.commit_group;" ::: "memory")
#define CP_WAIT0()  asm volatile("cp.async.wait_group 0;" ::: "memory")

__device__ __forceinline__ void ldsm_x4(uint32_t& r0, uint32_t& r1, uint32_t& r2, uint32_t& r3,
                                        uint32_t addr) {
    asm volatile("ldmatrix.sync.aligned.m8n8.x4.shared.b16 {%0,%1,%2,%3}, [%4];"
                 : "=r"(r0), "=r"(r1), "=r"(r2), "=r"(r3) : "r"(addr));
}
__device__ __forceinline__ void ldsm_x4_t(uint32_t& r0, uint32_t& r1, uint32_t& r2, uint32_t& r3,
                                          uint32_t addr) {
    asm volatile("ldmatrix.sync.aligned.m8n8.x4.trans.shared.b16 {%0,%1,%2,%3}, [%4];"
                 : "=r"(r0), "=r"(r1), "=r"(r2), "=r"(r3) : "r"(addr));
}
__device__ __forceinline__ void mma_bf16(float* c, const uint32_t* a, uint32_t b0, uint32_t b1) {
    asm volatile("mma.sync.aligned.m16n8k16.row.col.f32.bf16.bf16.f32 "
                 "{%0,%1,%2,%3}, {%4,%5,%6,%7}, {%8,%9}, {%0,%1,%2,%3};"
                 : "+f"(c[0]), "+f"(c[1]), "+f"(c[2]), "+f"(c[3])
                 : "r"(a[0]), "r"(a[1]), "r"(a[2]), "r"(a[3]), "r"(b0), "r"(b1));
}
__device__ __forceinline__ uint32_t pack_bf2(float lo, float hi) {
    __nv_bfloat16 l = __float2bfloat16(lo), h = __float2bfloat16(hi);
    return ((uint32_t)__bfloat16_as_ushort(h) << 16) | (uint32_t)__bfloat16_as_ushort(l);
}

/* ---------------- pooling (parallel) + gating MLP ---------------- */
__global__ void pool_kernel(const float* __restrict__ x)
{
    int b = blockIdx.x;
    int d = blockIdx.y*128 + threadIdx.x;
    const float* xp = x + (size_t)b*SEQ*DIM + d;
    float s = 0.f;
    #pragma unroll 4
    for (int t = 0; t < SEQ; t++) s += xp[(size_t)t*DIM];
    g_pooled[b*DIM + d] = s * (1.0f/SEQ);
}

__global__ void gating_mlp_kernel(const float* __restrict__ gw1, const float* __restrict__ gb1,
                                  const float* __restrict__ gw2, const float* __restrict__ gb2)
{
    int b = blockIdx.x;
    __shared__ float h[GHID];
    __shared__ float logits[NEXP];
    int tid = threadIdx.x;
    const float* pooled = g_pooled + b*DIM;
    {
        float a = gb1[tid];
        const float* w = gw1 + (size_t)tid*DIM;
        #pragma unroll 4
        for (int d = 0; d < DIM; d++) a += pooled[d]*w[d];
        h[tid] = fmaxf(a, 0.f);
    }
    __syncthreads();
    if (tid < NEXP) {
        float a = gb2[tid];
        const float* w = gw2 + tid*GHID;
        for (int d = 0; d < GHID; d++) a += h[d]*w[d];
        logits[tid] = a;
    }
    __syncthreads();
    if (tid == 0) {
        int i0 = 0;
        for (int e = 1; e < NEXP; e++) if (logits[e] > logits[i0]) i0 = e;
        int i1 = -1;
        for (int e = 0; e < NEXP; e++) {
            if (e == i0) continue;
            if (i1 < 0 || logits[e] > logits[i1]) i1 = e;
        }
        float v0 = logits[i0], v1 = logits[i1];
        float e0 = expf(v0 - v0), e1 = expf(v1 - v0);
        float inv = 1.f/(e0 + e1);
        g_gates[b*2]   = e0*inv;
        g_gates[b*2+1] = e1*inv;
        g_idx[b*2]   = i0;
        g_idx[b*2+1] = i1;
    }
}

/* ---------------- fp32 -> (bf16 hi, bf16 lo) ---------------- */
__device__ __forceinline__ void split4(float4 v, ushort4& hh, ushort4& ll)
{
    __nv_bfloat16 t;
    t = __float2bfloat16(v.x); hh.x = __bfloat16_as_ushort(t);
    ll.x = __bfloat16_as_ushort(__float2bfloat16(v.x - __bfloat162float(t)));
    t = __float2bfloat16(v.y); hh.y = __bfloat16_as_ushort(t);
    ll.y = __bfloat16_as_ushort(__float2bfloat16(v.y - __bfloat162float(t)));
    t = __float2bfloat16(v.z); hh.z = __bfloat16_as_ushort(t);
    ll.z = __bfloat16_as_ushort(__float2bfloat16(v.z - __bfloat162float(t)));
    t = __float2bfloat16(v.w); hh.w = __bfloat16_as_ushort(t);
    ll.w = __bfloat16_as_ushort(__float2bfloat16(v.w - __bfloat162float(t)));
}

__global__ void convx_kernel(const float* __restrict__ s, int n4)
{
    int i = blockIdx.x*256 + threadIdx.x;
    if (i >= n4) return;
    ushort4 hh, ll;
    split4(((const float4*)s)[i], hh, ll);
    ((ushort4*)g_xh)[i] = hh;
    ((ushort4*)g_xl)[i] = ll;
}

/* 2 float4 per thread, grid.x halved */
__global__ void convw_kernel(const float* __restrict__ w0, const float* __restrict__ w1,
                             const float* __restrict__ w2, const float* __restrict__ w3)
{
    int p = blockIdx.y;
    const float* s = (p==0)?w0:(p==1)?w1:(p==2)?w2:w3;
    int i = (blockIdx.x*256 + threadIdx.x)*2;
    size_t o = (size_t)p*(DIM*DIM/4) + i;
    ushort4 hh, ll;
    split4(((const float4*)s)[i], hh, ll);
    ((ushort4*)g_wh)[o] = hh;
    ((ushort4*)g_wl)[o] = ll;
    split4(((const float4*)s)[i+1], hh, ll);
    ((ushort4*)g_wh)[o+1] = hh;
    ((ushort4*)g_wl)[o+1] = ll;
}

/* ---------------- vuconv: gather+scale V rows AND U cols (merged) --------- */
__global__ void vuconv_kernel(const float* __restrict__ V0, const float* __restrict__ V1,
                              const float* __restrict__ V2, const float* __restrict__ V3,
                              const float* __restrict__ S0, const float* __restrict__ S1,
                              const float* __restrict__ S2, const float* __restrict__ S3,
                              const float* __restrict__ U0, const float* __restrict__ U1,
                              const float* __restrict__ U2, const float* __restrict__ U3)
{
    int b = blockIdx.x, y = blockIdx.y, p = blockIdx.z;
    if (y < 32) {
        const float* Vm = (p==0)?V0:(p==1)?V1:(p==2)?V2:V3;
        const float* Sm = (p==0)?S0:(p==1)?S1:(p==2)?S2:S3;
        int j = y;
        int half = j >> 4, r = j & 15;
        int e = g_idx[b*2 + half];
        float sc = g_gates[b*2 + half] * Sm[e*RNK + r];
        float4 v = ((const float4*)(Vm + ((size_t)e*RNK + r)*DIM))[threadIdx.x];
        v.x *= sc; v.y *= sc; v.z *= sc; v.w *= sc;
        ushort4 hh, ll;
        split4(v, hh, ll);
        size_t o = ((size_t)p*BB*32 + (size_t)b*32 + j)*DIM/4 + threadIdx.x;
        ((ushort4*)g_vbh)[o] = hh;
        ((ushort4*)g_vbl)[o] = ll;
    } else {
        const float* U = (p==0)?U0:(p==1)?U1:(p==2)?U2:U3;
        int n = (y - 32)*256 + threadIdx.x;
        int i0 = g_idx[b*2], i1 = g_idx[b*2+1];
        const float* u0 = U + ((size_t)i0*DIM + n)*RNK;
        const float* u1 = U + ((size_t)i1*DIM + n)*RNK;
        /* stage 32 hi/lo bf16 in registers, emit 4+4 uint4 stores */
        ushort hv[32], lv[32];
        #pragma unroll
        for (int r = 0; r < 16; r++) {
            float v0 = u0[r], v1 = u1[r];
            __nv_bfloat16 h0 = __float2bfloat16(v0);
            hv[r]      = __bfloat16_as_ushort(h0);
            lv[r]      = __bfloat16_as_ushort(__float2bfloat16(v0 - __bfloat162float(h0)));
            __nv_bfloat16 h1 = __float2bfloat16(v1);
            hv[16 + r] = __bfloat16_as_ushort(h1);
            lv[16 + r] = __bfloat16_as_ushort(__float2bfloat16(v1 - __bfloat162float(h1)));
        }
        __nv_bfloat16* H = g_ubh + ((size_t)p*BB*DIM + (size_t)b*DIM + n)*32;
        __nv_bfloat16* L = g_ubl + ((size_t)p*BB*DIM + (size_t)b*DIM + n)*32;
        #pragma unroll
        for (int q = 0; q < 4; q++) {
            *(uint4*)(H + q*8) = *(uint4*)(hv + q*8);
            *(uint4*)(L + q*8) = *(uint4*)(lv + q*8);
        }
    }
}

/* ---------------- fused GEMM: Y = (X@W^T + bias + xv@Ub^T) * scale -------- */
#define MAT_BYTES (128*40*2)            /* 10240 */
#define STG_BYTES (4*MAT_BYTES)         /* 40960 */
#define MM_SMEM   (2*STG_BYTES)         /* 81920 */

__device__ __forceinline__ void mm_load_stage(uint32_t sb, int buf, int k0,
    const __nv_bfloat16* Ah, const __nv_bfloat16* Al,
    const __nv_bfloat16* Bh, const __nv_bfloat16* Bl,
    int m0, int n0, int tid)
{
    uint32_t base = sb + buf*STG_BYTES;
    const __nv_bfloat16* srcs[4] = {Ah, Al, Bh, Bl};
    #pragma unroll
    for (int i = 0; i < 8; i++) {
        int c = tid + 256*i;
        int mat = c >> 9;
        int cc  = c & 511;
        int row = cc >> 2;
        int col = (cc & 3) * 8;
        const __nv_bfloat16* p = srcs[mat];
        int grow = ((mat < 2) ? m0 : n0) + row;
        int ok = (mat >= 2) || (grow < BSQ);
        const void* src = p + ((size_t)(ok ? grow : 0))*DIM + k0 + col;
        uint32_t dst = base + mat*MAT_BYTES + (uint32_t)(row*40 + col)*2;
        cp16(dst, src, ok ? 16 : 0);
    }
}

__global__ void __launch_bounds__(256, 2) mm_kernel(int base_code,
    const float* __restrict__ bias0, const float* __restrict__ bias1,
    const float* __restrict__ bias2, float* __restrict__ Yext)
{
    extern __shared__ __align__(128) char smem[];
    int code = (base_code < 0) ? (int)blockIdx.z : base_code;
    const __nv_bfloat16* Ah = g_xh;
    const __nv_bfloat16* Al = g_xl;
    const __nv_bfloat16* Bh = g_wh + (size_t)code*DIM*DIM;
    const __nv_bfloat16* Bl = g_wl + (size_t)code*DIM*DIM;
    const float* bias = (code==0)?bias0:(code==1)?bias1:(code==2)?bias2:bias0;

    uint32_t sb = smem_u32(smem);
    int tid = threadIdx.x;
    int lane = tid & 31;
    int wid = tid >> 5;
    int warp_m = wid >> 2;
    int warp_n = wid & 3;
    int n0 = blockIdx.x*128, m0 = blockIdx.y*128;

    float acc[4][4][4];
    #pragma unroll
    for (int i = 0; i < 4; i++)
        #pragma unroll
        for (int j = 0; j < 4; j++)
            #pragma unroll
            for (int q = 0; q < 4; q++) acc[i][j][q] = 0.f;

    uint32_t aRow = (uint32_t)(warp_m*64 + (lane & 15));
    uint32_t aCol = (uint32_t)((lane >> 4) * 8);
    uint32_t bRowBase = (uint32_t)(warp_n*32 + (lane & 7) + ((lane >> 4) << 3));
    uint32_t bCol = (uint32_t)(((lane >> 3) & 1) * 8);

    mm_load_stage(sb, 0, 0, Ah, Al, Bh, Bl, m0, n0, tid);
    CP_COMMIT();

    const int NK = DIM/32;
    for (int s = 0; s < NK; s++) {
        CP_WAIT0();
        __syncthreads();
        if (s + 1 < NK) {
            mm_load_stage(sb, (s+1)&1, (s+1)*32, Ah, Al, Bh, Bl, m0, n0, tid);
            CP_COMMIT();
        }

        uint32_t stg = sb + (s&1)*STG_BYTES;
        #pragma unroll
        for (int kk = 0; kk < 32; kk += 16) {
            uint32_t ah[4][4], al[4][4], bh[8], bl[8];
            #pragma unroll
            for (int i = 0; i < 4; i++) {
                uint32_t off = ((aRow + i*16)*40 + kk + aCol)*2;
                ldsm_x4(ah[i][0], ah[i][1], ah[i][2], ah[i][3], stg + 0*MAT_BYTES + off);
                ldsm_x4(al[i][0], al[i][1], al[i][2], al[i][3], stg + 1*MAT_BYTES + off);
            }
            #pragma unroll
            for (int g = 0; g < 2; g++) {
                uint32_t off = ((bRowBase + g*16)*40 + kk + bCol)*2;
                ldsm_x4(bh[g*4+0], bh[g*4+1], bh[g*4+2], bh[g*4+3], stg + 2*MAT_BYTES + off);
                ldsm_x4(bl[g*4+0], bl[g*4+1], bl[g*4+2], bl[g*4+3], stg + 3*MAT_BYTES + off);
            }
            #pragma unroll
            for (int i = 0; i < 4; i++) {
                #pragma unroll
                for (int j = 0; j < 4; j++) {
                    mma_bf16(acc[i][j], ah[i], bh[j*2], bh[j*2+1]);
                    mma_bf16(acc[i][j], ah[i], bl[j*2], bl[j*2+1]);
                    mma_bf16(acc[i][j], al[i], bh[j*2], bh[j*2+1]);
                }
            }
        }
    }

    /* ---- fused rank-32 MoE correction: one pass per batch in this tile ---- */
    {
        int mlast = m0 + 127; if (mlast >= BSQ) mlast = BSQ - 1;
        int bb0 = m0 / SEQ, bb1 = mlast / SEQ;
        for (int bb = bb0; bb <= bb1; bb++) {
            uint32_t base = sb + ((bb - bb0) & 1)*STG_BYTES;
            __syncthreads();
            #pragma unroll
            for (int i2 = 0; i2 < 4; i2++) {
                int c = tid + 256*i2;
                int mat = c >> 9, cc = c & 511;
                int row = cc >> 2, col = (cc & 3)*8;
                int m = m0 + row;
                int ok = (m < BSQ) && (m / SEQ == bb);
                int t = m - bb*SEQ;
                const __nv_bfloat16* srcA = (mat ? g_xvl : g_xvh) +
                    (size_t)code*BB*SEQP*32 + ((size_t)bb*SEQP + (ok ? t : 0))*32 + col;
                cp16(base + mat*MAT_BYTES + (uint32_t)(row*40 + col)*2, srcA, ok ? 16 : 0);
            }
            #pragma unroll
            for (int i2 = 0; i2 < 4; i2++) {
                int c = tid + 256*i2;
                int mat = c >> 9, cc = c & 511;
                int row = cc >> 2, col = (cc & 3)*8;
                const __nv_bfloat16* srcB = (mat ? g_ubl : g_ubh) +
                    (size_t)code*BB*DIM*32 + ((size_t)bb*DIM + n0 + row)*32 + col;
                cp16(base + (2 + mat)*MAT_BYTES + (uint32_t)(row*40 + col)*2, srcB, 16);
            }
            CP_COMMIT();
            CP_WAIT0();
            __syncthreads();
            #pragma unroll
            for (int kk = 0; kk < 32; kk += 16) {
                uint32_t ah[4][4], al[4][4], bh[8], bl[8];
                #pragma unroll
                for (int i = 0; i < 4; i++) {
                    uint32_t off = ((aRow + i*16)*40 + kk + aCol)*2;
                    ldsm_x4(ah[i][0], ah[i][1], ah[i][2], ah[i][3], base + 0*MAT_BYTES + off);
                    ldsm_x4(al[i][0], al[i][1], al[i][2], al[i][3], base + 1*MAT_BYTES + off);
                }
                #pragma unroll
                for (int g = 0; g < 2; g++) {
                    uint32_t off = ((bRowBase + g*16)*40 + kk + bCol)*2;
                    ldsm_x4(bh[g*4+0], bh[g*4+1], bh[g*4+2], bh[g*4+3], base + 2*MAT_BYTES + off);
                    ldsm_x4(bl[g*4+0], bl[g*4+1], bl[g*4+2], bl[g*4+3], base + 3*MAT_BYTES + off);
                }
                #pragma unroll
                for (int i = 0; i < 4; i++) {
                    #pragma unroll
                    for (int j = 0; j < 4; j++) {
                        mma_bf16(acc[i][j], ah[i], bh[j*2], bh[j*2+1]);
                        mma_bf16(acc[i][j], ah[i], bl[j*2], bl[j*2+1]);
                        mma_bf16(acc[i][j], al[i], bh[j*2], bh[j*2+1]);
                    }
                }
            }
        }
    }

    /* ---- epilogue: row-major, no per-element division -------------------- */
    float scale = (code == 0) ? QSCALE : 1.0f;
    __nv_bfloat16* Hd = (code==0)?g_aqh:(code==1)?g_akh:g_avh;
    __nv_bfloat16* Ld = (code==0)?g_aql:(code==1)?g_akl:g_avl;

    float bv0[4], bv1[4];
    int colv[4], hhv[4], d0v[4];
    #pragma unroll
    for (int j = 0; j < 4; j++) {
        int col = n0 + warp_n*32 + j*8 + (lane & 3)*2;
        colv[j] = col;
        bv0[j] = bias[col];
        bv1[j] = bias[col+1];
        hhv[j] = col >> 6;
        d0v[j] = col & 63;
    }

    int bbase = m0 / SEQ;
    int bnd = (bbase + 1)*SEQ;

    #pragma unroll
    for (int i = 0; i < 4; i++) {
        #pragma unroll
        for (int half = 0; half < 2; half++) {
            int m = m0 + warp_m*64 + i*16 + (lane >> 2) + half*8;
            if (m >= BSQ) continue;
            if (code == 3) {
                float* yrow = Yext + (size_t)m*DIM;
                #pragma unroll
                for (int j = 0; j < 4; j++) {
                    float v0 = (acc[i][j][half*2]   + bv0[j])*scale;
                    float v1 = (acc[i][j][half*2+1] + bv1[j])*scale;
                    *(float2*)(yrow + colv[j]) = make_float2(v0, v1);
                }
            } else {
                int b = (m >= bnd) ? bbase + 1 : bbase;
                int t = m - b*SEQ;
                size_t rowbase = ((size_t)(b*NH)*SEQP + t)*HD;
                #pragma unroll
                for (int j = 0; j < 4; j++) {
                    float v0 = (acc[i][j][half*2]   + bv0[j])*scale;
                    float v1 = (acc[i][j][half*2+1] + bv1[j])*scale;
                    float h0 = __bfloat162float(__float2bfloat16(v0));
                    float h1 = __bfloat162float(__float2bfloat16(v1));
                    size_t o = rowbase + (size_t)hhv[j]*SEQP*HD + d0v[j];
                    *(uint32_t*)(Hd + o) = pack_bf2(h0, h1);
                    *(uint32_t*)(Ld + o) = pack_bf2(v0 - h0, v1 - h1);
                }
            }
        }
    }
}

/* ---------------- xvmma_qkv: xv(p=0..2) = X @ [Vb0;Vb1;Vb2]^T ------------- */
#define X3_ABYT 13824
#define X3_BBYT 13824
#define X3_STGB (2*X3_ABYT + 2*X3_BBYT)
#define X3_SMEM (2*X3_STGB)

__device__ __forceinline__ void x3_load_stage(uint32_t sb, int buf, int k0,
                                              int b, int mt, int tid)
{
    uint32_t base = sb + buf*X3_STGB;
    #pragma unroll
    for (int i = 0; i < 16; i++) {
        int c = tid + 192*i;
        if (c >= 3072) break;
        int m4 = c / 768;
        int cc2 = c - m4*768;
        int row = cc2 >> 3, col8 = (cc2 & 7)*8;
        if (m4 < 2) {
            int t = mt*96 + row;
            int ok = t < SEQ;
            const __nv_bfloat16* src = (m4 ? g_xl : g_xh) +
                ((size_t)b*SEQ + (ok ? t : 0))*DIM + k0 + col8;
            cp16(base + m4*X3_ABYT + (uint32_t)(row*72 + col8)*2, src, ok ? 16 : 0);
        } else {
            int p = row >> 5, jr = row & 31;
            const __nv_bfloat16* src = ((m4 == 3) ? g_vbl : g_vbh) +
                (size_t)p*BB*32*DIM + ((size_t)b*32 + jr)*DIM + k0 + col8;
            cp16(base + 2*X3_ABYT + (m4 - 2)*X3_BBYT + (uint32_t)(row*72 + col8)*2, src, 16);
        }
    }
}

__global__ void __launch_bounds__(192, 1) xvmma_qkv_kernel()
{
    extern __shared__ __align__(16) char xsm[];
    uint32_t sb = smem_u32(xsm);
    int tid = threadIdx.x, lane = tid & 31, w = tid >> 5;
    int mt = blockIdx.x, b = blockIdx.y;

    float acc[12][4];
    #pragma unroll
    for (int j = 0; j < 12; j++)
        #pragma unroll
        for (int q = 0; q < 4; q++) acc[j][q] = 0.f;

    uint32_t aRow = (uint32_t)(w*16 + (lane & 15));
    uint32_t aCol = (uint32_t)((lane >> 4)*8);
    uint32_t bRow = (uint32_t)((lane & 7) + ((lane >> 4) << 3));
    uint32_t bCol = (uint32_t)(((lane >> 3) & 1)*8);

    x3_load_stage(sb, 0, 0, b, mt, tid);
    CP_COMMIT();

    for (int s = 0; s < 16; s++) {
        CP_WAIT0();
        __syncthreads();
        if (s + 1 < 16) {
            x3_load_stage(sb, (s+1)&1, (s+1)*64, b, mt, tid);
            CP_COMMIT();
        }
        uint32_t stg = sb + (s&1)*X3_STGB;
        #pragma unroll
        for (int kt = 0; kt < 4; kt++) {
            uint32_t ah[4], al[4];
            uint32_t off = (aRow*72 + kt*16 + aCol)*2;
            ldsm_x4(ah[0], ah[1], ah[2], ah[3], stg + off);
            ldsm_x4(al[0], al[1], al[2], al[3], stg + X3_ABYT + off);
            #pragma unroll
            for (int g = 0; g < 6; g++) {
                uint32_t bo = ((bRow + g*16)*72 + kt*16 + bCol)*2;
                uint32_t bh[4], bl[4];
                ldsm_x4(bh[0], bh[1], bh[2], bh[3], stg + 2*X3_ABYT + bo);
                ldsm_x4(bl[0], bl[1], bl[2], bl[3], stg + 2*X3_ABYT + X3_BBYT + bo);
                #pragma unroll
                for (int r = 0; r < 2; r++) {
                    int jj = g*2 + r;
                    mma_bf16(acc[jj], ah, bh[r*2], bh[r*2+1]);
                    mma_bf16(acc[jj], ah, bl[r*2], bl[r*2+1]);
                    mma_bf16(acc[jj], al, bh[r*2], bh[r*2+1]);
                }
            }
        }
    }

    int r0 = mt*96 + w*16 + (lane >> 2);
    int r1 = r0 + 8;
    #pragma unroll
    for (int j = 0; j < 12; j++) {
        int n = j*8 + (lane & 3)*2;
        int p = n >> 5, coln = n & 31;
        size_t xvoff = (size_t)p*BB*SEQP*32;
        if (r0 < SEQ) {
            float p0 = acc[j][0], p1 = acc[j][1];
            float h0 = __bfloat162float(__float2bfloat16(p0));
            float h1 = __bfloat162float(__float2bfloat16(p1));
            size_t o = xvoff + ((size_t)b*SEQP + r0)*32 + coln;
            *(uint32_t*)(g_xvh + o) = pack_bf2(h0, h1);
            *(uint32_t*)(g_xvl + o) = pack_bf2(p0 - h0, p1 - h1);
        }
        if (r1 < SEQ) {
            float p0 = acc[j][2], p1 = acc[j][3];
            float h0 = __bfloat162float(__float2bfloat16(p0));
            float h1 = __bfloat162float(__float2bfloat16(p1));
            size_t o = xvoff + ((size_t)b*SEQP + r1)*32 + coln;
            *(uint32_t*)(g_xvh + o) = pack_bf2(h0, h1);
            *(uint32_t*)(g_xvl + o) = pack_bf2(p0 - h0, p1 - h1);
        }
    }
}

/* ---------------- xvmma (single p = 3, ctx) -------------------- */
#define XV_ABYT 13824
#define XV_BBYT 4608
#define XV_STGB (2*XV_ABYT + 2*XV_BBYT)
#define XV_SMEM (2*XV_STGB)

__device__ __forceinline__ void xv_load_stage(uint32_t sb, int buf, int k0,
                                              int b, int mt, int tid, int p)
{
    uint32_t base = sb + buf*XV_STGB;
    size_t vboff = (size_t)p*BB*32*DIM;
    #pragma unroll
    for (int i = 0; i < 11; i++) {
        int c = tid + 192*i;
        if (c >= 2048) break;
        if (c < 1536) {
            int mat = (c >= 768);
            int cc = c - (mat ? 768 : 0);
            int row = cc >> 3, col8 = (cc & 7)*8;
            int t = mt*96 + row;
            int ok = t < SEQ;
            const __nv_bfloat16* src = (mat ? g_xl : g_xh) +
                ((size_t)b*SEQ + (ok ? t : 0))*DIM + k0 + col8;
            cp16(base + mat*XV_ABYT + (uint32_t)(row*72 + col8)*2, src, ok ? 16 : 0);
        } else {
            int c2 = c - 1536;
            int mat = c2 >> 8;
            int cc = c2 & 255;
            int row = cc >> 3, col8 = (cc & 7)*8;
            const __nv_bfloat16* src = (mat ? g_vbl : g_vbh) + vboff +
                ((size_t)b*32 + row)*DIM + k0 + col8;
            cp16(base + 2*XV_ABYT + mat*XV_BBYT + (uint32_t)(row*72 + col8)*2, src, 16);
        }
    }
}

__global__ void __launch_bounds__(192, 1) xvmma_kernel(int p)
{
    extern __shared__ __align__(16) char xsm[];
    uint32_t sb = smem_u32(xsm);
    int tid = threadIdx.x, lane = tid & 31, w = tid >> 5;
    int mt = blockIdx.x, b = blockIdx.y;

    float acc[4][4];
    #pragma unroll
    for (int j = 0; j < 4; j++)
        #pragma unroll
        for (int q = 0; q < 4; q++) acc[j][q] = 0.f;

    uint32_t aRow = (uint32_t)(w*16 + (lane & 15));
    uint32_t aCol = (uint32_t)((lane >> 4)*8);
    uint32_t bRow = (uint32_t)((lane & 7) + ((lane >> 4) << 3));
    uint32_t bCol = (uint32_t)(((lane >> 3) & 1)*8);

    xv_load_stage(sb, 0, 0, b, mt, tid, p);
    CP_COMMIT();

    for (int s = 0; s < 16; s++) {
        CP_WAIT0();
        __syncthreads();
        if (s + 1 < 16) {
            xv_load_stage(sb, (s+1)&1, (s+1)*64, b, mt, tid, p);
            CP_COMMIT();
        }
        uint32_t stg = sb + (s&1)*XV_STGB;
        #pragma unroll
        for (int kt = 0; kt < 4; kt++) {
            uint32_t ah[4], al[4], bh2[8], bl2[8];
            uint32_t off = (aRow*72 + kt*16 + aCol)*2;
            ldsm_x4(ah[0], ah[1], ah[2], ah[3], stg + off);
            ldsm_x4(al[0], al[1], al[2], al[3], stg + XV_ABYT + off);
            #pragma unroll
            for (int g = 0; g < 2; g++) {
                uint32_t bo = ((bRow + g*16)*72 + kt*16 + bCol)*2;
                ldsm_x4(bh2[g*4+0], bh2[g*4+1], bh2[g*4+2], bh2[g*4+3],
                        stg + 2*XV_ABYT + bo);
                ldsm_x4(bl2[g*4+0], bl2[g*4+1], bl2[g*4+2], bl2[g*4+3],
                        stg + 2*XV_ABYT + XV_BBYT + bo);
            }
            #pragma unroll
            for (int j = 0; j < 4; j++) {
                mma_bf16(acc[j], ah, bh2[j*2], bh2[j*2+1]);
                mma_bf16(acc[j], ah, bl2[j*2], bl2[j*2+1]);
                mma_bf16(acc[j], al, bh2[j*2], bh2[j*2+1]);
            }
        }
    }

    size_t xvoff = (size_t)p*BB*SEQP*32;
    int r0 = mt*96 + w*16 + (lane >> 2);
    int r1 = r0 + 8;
    #pragma unroll
    for (int j = 0; j < 4; j++) {
        int col = j*8 + (lane & 3)*2;
        if (r0 < SEQ) {
            float p0 = acc[j][0], p1 = acc[j][1];
            float h0 = __bfloat162float(__float2bfloat16(p0));
            float h1 = __bfloat162float(__float2bfloat16(p1));
            size_t o = xvoff + ((size_t)b*SEQP + r0)*32 + col;
            *(uint32_t*)(g_xvh + o) = pack_bf2(h0, h1);
            *(uint32_t*)(g_xvl + o) = pack_bf2(p0 - h0, p1 - h1);
        }
        if (r1 < SEQ) {
            float p0 = acc[j][2], p1 = acc[j][3];
            float h0 = __bfloat162float(__float2bfloat16(p0));
            float h1 = __bfloat162float(__float2bfloat16(p1));
            size_t o = xvoff + ((size_t)b*SEQP + r1)*32 + col;
            *(uint32_t*)(g_xvh + o) = pack_bf2(h0, h1);
            *(uint32_t*)(g_xvl + o) = pack_bf2(p0 - h0, p1 - h1);
        }
    }
}

/* ---------------- fused flash attention (KV chunk = 32, 9 chunks) --------- */
#define FA_QBYTES  13824
#define FA_MATB    4608
#define FA_STGB    (4*FA_MATB)
#define FA_KVBASE  (2*FA_QBYTES)
#define FA_SMEM    (FA_KVBASE + 2*FA_STGB)
#define FA_NC      9

__device__ __forceinline__ void fa_load_kv(uint32_t sb, int buf, int t0,
                                           int bh, int tid)
{
    uint32_t base = sb + FA_KVBASE + buf*FA_STGB;
    size_t goff = (size_t)bh*SEQP*HD + (size_t)t0*HD;
    const __nv_bfloat16* srcs[4] = {g_akh + goff, g_akl + goff, g_avh + goff, g_avl + goff};
    #pragma unroll
    for (int i = 0; i < 6; i++) {
        int c = tid + 192*i;
        if (c < 1024) {
            int mat = c >> 8, cc = c & 255;
            int row = cc >> 3, col8 = (cc & 7)*8;
            cp16(base + mat*FA_MATB + (uint32_t)(row*72 + col8)*2,
                 srcs[mat] + (size_t)row*HD + col8, 16);
        }
    }
}

__global__ void __launch_bounds__(192, 3) fa_kernel()
{
    extern __shared__ __align__(16) char fsm[];
    uint32_t sb = smem_u32(fsm);
    int tid = threadIdx.x, lane = tid & 31, w = tid >> 5;
    int mt = blockIdx.x, bh = blockIdx.y;
    int b = bh >> 4, hh = bh & 15;

    {
        const __nv_bfloat16* qs[2] = {g_aqh, g_aql};
        #pragma unroll
        for (int mat = 0; mat < 2; mat++) {
            const __nv_bfloat16* src = qs[mat] + ((size_t)bh*SEQP + mt*96)*HD;
            #pragma unroll
            for (int it = 0; it < 4; it++) {
                int c = tid + 192*it;
                int row = c >> 3, col8 = (c & 7)*8;
                uint4 v = *(const uint4*)(src + (size_t)row*HD + col8);
                *(uint4*)(fsm + mat*FA_QBYTES + (row*72 + col8)*2) = v;
            }
        }
    }
    fa_load_kv(sb, 0, 0, bh, tid);
    CP_COMMIT();
    __syncthreads();

    uint32_t qRowOff = (uint32_t)((w*16 + (lane & 15))*72 + (lane >> 4)*8)*2;

    float o[8][4];
    #pragma unroll
    for (int j = 0; j < 8; j++)
        #pragma unroll
        for (int q = 0; q < 4; q++) o[j][q] = 0.f;
    float mr0 = -1e30f, mr1 = -1e30f, l0 = 0.f, l1 = 0.f;

    uint32_t kRow = (uint32_t)((lane & 7) + ((lane >> 4) << 3));
    uint32_t kCol = (uint32_t)(((lane >> 3) & 1)*8);
    uint32_t vRow = (uint32_t)(lane & 15);
    uint32_t vCol = (uint32_t)((lane >> 4) << 3);

    for (int c = 0; c < FA_NC; c++) {
        CP_WAIT0();
        __syncthreads();
        if (c + 1 < FA_NC) {
            fa_load_kv(sb, (c+1)&1, (c+1)*32, bh, tid);
            CP_COMMIT();
        }
        uint32_t stg = sb + FA_KVBASE + (c&1)*FA_STGB;

        float S[4][4];
        #pragma unroll
        for (int j = 0; j < 4; j++)
            #pragma unroll
            for (int q = 0; q < 4; q++) S[j][q] = 0.f;

        #pragma unroll
        for (int kt = 0; kt < 4; kt++) {
            uint32_t qh4[4], ql4[4];
            uint32_t qoff = qRowOff + (uint32_t)(kt*16)*2;
            ldsm_x4(qh4[0], qh4[1], qh4[2], qh4[3], sb + qoff);
            ldsm_x4(ql4[0], ql4[1], ql4[2], ql4[3], sb + FA_QBYTES + qoff);
            #pragma unroll
            for (int g = 0; g < 2; g++) {
                uint32_t off = ((kRow + g*16)*72 + kt*16 + kCol)*2;
                uint32_t h0,h1,h2,h3, e0,e1,e2,e3;
                ldsm_x4(h0,h1,h2,h3, stg + 0*FA_MATB + off);
                ldsm_x4(e0,e1,e2,e3, stg + 1*FA_MATB + off);
                mma_bf16(S[2*g],   qh4, h0, h1);
                mma_bf16(S[2*g],   qh4, e0, e1);
                mma_bf16(S[2*g],   ql4, h0, h1);
                mma_bf16(S[2*g+1], qh4, h2, h3);
                mma_bf16(S[2*g+1], qh4, e2, e3);
                mma_bf16(S[2*g+1], ql4, h2, h3);
            }
        }

        if (c == FA_NC - 1) {
            #pragma unroll
            for (int j = 0; j < 4; j++) {
                int tb = (FA_NC-1)*32 + j*8 + (lane & 3)*2;
                if (tb     >= SEQ) { S[j][0] = -1e30f; S[j][2] = -1e30f; }
                if (tb + 1 >= SEQ) { S[j][1] = -1e30f; S[j][3] = -1e30f; }
            }
        }

        float mx0 = -1e30f, mx1 = -1e30f;
        #pragma unroll
        for (int j = 0; j < 4; j++) {
            mx0 = fmaxf(mx0, fmaxf(S[j][0], S[j][1]));
            mx1 = fmaxf(mx1, fmaxf(S[j][2], S[j][3]));
        }
        mx0 = fmaxf(mx0, __shfl_xor_sync(0xffffffffu, mx0, 1));
        mx0 = fmaxf(mx0, __shfl_xor_sync(0xffffffffu, mx0, 2));
        mx1 = fmaxf(mx1, __shfl_xor_sync(0xffffffffu, mx1, 1));
        mx1 = fmaxf(mx1, __shfl_xor_sync(0xffffffffu, mx1, 2));
        float mn0 = fmaxf(mr0, mx0), mn1 = fmaxf(mr1, mx1);
        float sc0 = __expf(mr0 - mn0), sc1 = __expf(mr1 - mn1);
        mr0 = mn0; mr1 = mn1;

        uint32_t ph[2][4], pl[2][4];
        float rs0 = 0.f, rs1 = 0.f;
        #pragma unroll
        for (int j = 0; j < 4; j++) {
            float p0 = __expf(S[j][0] - mn0), p1 = __expf(S[j][1] - mn0);
            float p2 = __expf(S[j][2] - mn1), p3 = __expf(S[j][3] - mn1);
            rs0 += p0 + p1; rs1 += p2 + p3;
            float h0 = __bfloat162float(__float2bfloat16(p0));
            float h1 = __bfloat162float(__float2bfloat16(p1));
            float h2 = __bfloat162float(__float2bfloat16(p2));
            float h3 = __bfloat162float(__float2bfloat16(p3));
            int kt2 = j >> 1, hb = (j & 1)*2;
            ph[kt2][hb]   = pack_bf2(h0, h1);
            ph[kt2][hb+1] = pack_bf2(h2, h3);
            pl[kt2][hb]   = pack_bf2(p0 - h0, p1 - h1);
            pl[kt2][hb+1] = pack_bf2(p2 - h2, p3 - h3);
        }
        rs0 += __shfl_xor_sync(0xffffffffu, rs0, 1);
        rs0 += __shfl_xor_sync(0xffffffffu, rs0, 2);
        rs1 += __shfl_xor_sync(0xffffffffu, rs1, 1);
        rs1 += __shfl_xor_sync(0xffffffffu, rs1, 2);
        l0 = l0*sc0 + rs0;
        l1 = l1*sc1 + rs1;

        #pragma unroll
        for (int j = 0; j < 8; j++) {
            o[j][0] *= sc0; o[j][1] *= sc0;
            o[j][2] *= sc1; o[j][3] *= sc1;
        }

        #pragma unroll
        for (int kt2 = 0; kt2 < 2; kt2++) {
            #pragma unroll
            for (int g = 0; g < 4; g++) {
                uint32_t off = ((kt2*16 + vRow)*72 + g*16 + vCol)*2;
                uint32_t h0,h1,h2,h3, e0,e1,e2,e3;
                ldsm_x4_t(h0,h1,h2,h3, stg + 2*FA_MATB + off);
                ldsm_x4_t(e0,e1,e2,e3, stg + 3*FA_MATB + off);
                mma_bf16(o[2*g],   ph[kt2], h0, h1);
                mma_bf16(o[2*g],   ph[kt2], e0, e1);
                mma_bf16(o[2*g],   pl[kt2], h0, h1);
                mma_bf16(o[2*g+1], ph[kt2], h2, h3);
                mma_bf16(o[2*g+1], ph[kt2], e2, e3);
                mma_bf16(o[2*g+1], pl[kt2], h2, h3);
            }
        }
    }

    float inv0 = 1.f/l0, inv1 = 1.f/l1;
    int r0 = mt*96 + w*16 + (lane >> 2);
    int r1 = r0 + 8;
    #pragma unroll
    for (int j = 0; j < 8; j++) {
        int d = hh*HD + j*8 + (lane & 3)*2;
        if (r0 < SEQ) {
            float v0 = o[j][0]*inv0, v1 = o[j][1]*inv0;
            float h0 = __bfloat162float(__float2bfloat16(v0));
            float h1 = __bfloat162float(__float2bfloat16(v1));
            size_t off = (size_t)(b*SEQ + r0)*DIM + d;
            *(uint32_t*)(g_xh + off) = pack_bf2(h0, h1);
            *(uint32_t*)(g_xl + off) = pack_bf2(v0 - h0, v1 - h1);
        }
        if (r1 < SEQ) {
            float v0 = o[j][2]*inv1, v1 = o[j][3]*inv1;
            float h0 = __bfloat162float(__float2bfloat16(v0));
            float h1 = __bfloat162float(__float2bfloat16(v1));
            size_t off = (size_t)(b*SEQ + r1)*DIM + d;
            *(uint32_t*)(g_xh + off) = pack_bf2(h0, h1);
            *(uint32_t*)(g_xl + off) = pack_bf2(v0 - h0, v1 - h1);
        }
    }
}

/* ---------------- launch ---------------- */
extern "C" void kernel_launch(void* const* d_in, const int* in_sizes, int n_in,
                              void* d_out, int out_size)
{
    const float* x   = (const float*)d_in[0];
    const float* gw1 = (const float*)d_in[1];
    const float* gb1 = (const float*)d_in[2];
    const float* gw2 = (const float*)d_in[3];
    const float* gb2 = (const float*)d_in[4];
    const float* Wm[4] = {(const float*)d_in[5],  (const float*)d_in[10],
                          (const float*)d_in[15], (const float*)d_in[20]};
    const float* Uu[4] = {(const float*)d_in[6],  (const float*)d_in[11],
                          (const float*)d_in[16], (const float*)d_in[21]};
    const float* Ss[4] = {(const float*)d_in[7],  (const float*)d_in[12],
                          (const float*)d_in[17], (const float*)d_in[22]};
    const float* Vv[4] = {(const float*)d_in[8],  (const float*)d_in[13],
                          (const float*)d_in[18], (const float*)d_in[23]};
    const float* bbv[4] = {(const float*)d_in[9],  (const float*)d_in[14],
                           (const float*)d_in[19], (const float*)d_in[24]};
    float* out = (float*)d_out;

    cudaFuncSetAttribute(mm_kernel, cudaFuncAttributeMaxDynamicSharedMemorySize, MM_SMEM);
    cudaFuncSetAttribute(fa_kernel, cudaFuncAttributeMaxDynamicSharedMemorySize, FA_SMEM);
    cudaFuncSetAttribute(xvmma_kernel, cudaFuncAttributeMaxDynamicSharedMemorySize, XV_SMEM);
    cudaFuncSetAttribute(xvmma_qkv_kernel, cudaFuncAttributeMaxDynamicSharedMemorySize, X3_SMEM);

    pool_kernel<<<dim3(BB, 8), 128>>>(x);
    gating_mlp_kernel<<<BB, GHID>>>(gw1, gb1, gw2, gb2);

    int nx4 = BSQ*DIM/4;
    int nw4 = DIM*DIM/4;
    convx_kernel<<<(nx4 + 255)/256, 256>>>(x, nx4);
    convw_kernel<<<dim3(nw4/512, 4), 256>>>(Wm[0], Wm[1], Wm[2], Wm[3]);

    vuconv_kernel<<<dim3(BB, 36, 4), 256>>>(Vv[0], Vv[1], Vv[2], Vv[3],
                                            Ss[0], Ss[1], Ss[2], Ss[3],
                                            Uu[0], Uu[1], Uu[2], Uu[3]);

    xvmma_qkv_kernel<<<dim3(3, BB), 192, X3_SMEM>>>();

    dim3 gmm(8, 65, 3);
    mm_kernel<<<gmm, 256, MM_SMEM>>>(-1, bbv[0], bbv[1], bbv[2], nullptr);

    fa_kernel<<<dim3(3, BB*NH), 192, FA_SMEM>>>();

    xvmma_kernel<<<dim3(3, BB), 192, XV_SMEM>>>(3);
    mm_kernel<<<dim3(8, 65, 1), 256, MM_SMEM>>>(3, bbv[3], bbv[3], bbv[3], out);
}